// round 10
// baseline (speedup 1.0000x reference)
#include <cuda_runtime.h>
#include <cuda_fp16.h>
#include <math.h>
#include <stdint.h>

// ---------------- problem constants ----------------
#define NB 4
#define SS 1024
#define DD 1536
#define NH 12
#define HDIM 128
#define MAXC 256
#define SM1 1023
#define ROWS_DET (NB*SM1)        // 4092
#define CS_TOT (1023+511+255)    // 1789
#define XQ 6144                  // combined xling|qkv row width
#define QOFF 1536                // qkv column offset in combined buffer

#define WSCALE 64.0f
#define OSINV  0.015625f         // 1/64

// ---------------- fp32 scratch ----------------
__device__ float g_xq[(size_t)NB*SS*XQ];       // [.,0:1536)=xling, [.,1536:6144)=qkv
__device__ float g_bc[XQ];                     // combined bias
__device__ float g_norm[NB*SS];
__device__ float g_cs[NB*CS_TOT];
__device__ float g_base[NB*SM1];
__device__ float g_h2[(size_t)3*ROWS_DET*(DD/2)];
__device__ float g_final[NB*SM1];
__device__ int   g_seg[NB*SS];
__device__ int   g_qlo[NB*SS];
__device__ int   g_qhi[NB*SS];
__device__ int   g_segstart[NB*MAXC];
__device__ int   g_segcount[NB*MAXC];
__device__ float g_attnout[(size_t)NB*SS*DD];
__device__ float g_y[(size_t)NB*MAXC*DD];

// ---------------- fp16 2-way split scratch [rows][2K] (hi|lo) ----------------
__device__ __half g_x2[(size_t)NB*SS*2*DD];
__device__ __half g_wc2[(size_t)XQ*2*DD];      // combined [Wp | in_proj_w] split
__device__ __half g_dW1_2[(size_t)3*DD*2*(2*DD)];
__device__ __half g_h1_2[(size_t)3*ROWS_DET*2*DD];
__device__ __half g_dW2_2[(size_t)3*(DD/2)*2*DD];
__device__ __half g_ctx2[(size_t)NB*SS*2*DD];
__device__ __half g_outw2[(size_t)DD*2*DD];
__device__ __half g_chunk2[(size_t)NB*MAXC*2*DD];
__device__ __half g_pw1_2[(size_t)2*DD*2*DD];
__device__ __half g_hproc2[(size_t)NB*MAXC*2*2*DD];
__device__ __half g_pw2_2[(size_t)DD*2*2*DD];

// fast erf: Abramowitz-Stegun 7.1.26, |err| <= 1.5e-7 (absolute)
__device__ __forceinline__ float erf_fast(float x) {
    float ax = fabsf(x);
    float t = 1.0f / fmaf(0.3275911f, ax, 1.0f);
    float p = t*(0.254829592f + t*(-0.284496736f + t*(1.421413741f +
              t*(-1.453152027f + t*1.061405429f))));
    float r = 1.0f - p * __expf(-ax*ax);
    return copysignf(r, x);
}
__device__ __forceinline__ float gelu_fast(float v) {
    return 0.5f * v * (1.0f + erf_fast(v * 0.70710678118654752440f));
}
__device__ __forceinline__ uint32_t smem_u32(const void* p) {
    uint32_t a;
    asm("{ .reg .u64 t; cvta.to.shared.u64 t, %1; cvt.u32.u64 %0, t; }" : "=r"(a) : "l"(p));
    return a;
}

#define LDSM4(r0,r1,r2,r3,addr) \
    asm volatile("ldmatrix.sync.aligned.m8n8.x4.shared.b16 {%0,%1,%2,%3}, [%4];" \
        : "=r"(r0), "=r"(r1), "=r"(r2), "=r"(r3) : "r"(addr))

#define MMA16816(d, a, b0, b1) \
    asm volatile("mma.sync.aligned.m16n8k16.row.col.f32.f16.f16.f32 " \
        "{%0,%1,%2,%3},{%4,%5,%6,%7},{%8,%9},{%0,%1,%2,%3};" \
        : "+f"((d)[0]), "+f"((d)[1]), "+f"((d)[2]), "+f"((d)[3]) \
        : "r"((a)[0]), "r"((a)[1]), "r"((a)[2]), "r"((a)[3]), "r"(b0), "r"(b1))

#define CP_ASYNC16(dst, src, sz) \
    asm volatile("cp.async.ca.shared.global [%0], [%1], 16, %2;" :: "r"(dst), "l"(src), "r"(sz))
#define CP_COMMIT() asm volatile("cp.async.commit_group;" ::: "memory")
#define CP_WAIT2() asm volatile("cp.async.wait_group 2;" ::: "memory")

// ========== mma.sync fp16 split GEMM (4-stage, K-chunk 32, 2 CTAs/SM) ==========
// A[M][2K] (hi|lo), B[N][2K] (hi|lo).
// np = (n0 < splitN) ? npA : npB.
//   np=3: Ah.Bh + Ah.Bl + Al.Bh   (same product & k order as round 9 -> bit-identical)
//   np=2: Ah.Bh + Ah.Bl
// BIG=1: A is g_x2; rows are bigrams (b,s); chunk selects x_s / x_{s+1}.
#define RSTRIDE 80
#define MTILE (128*RSTRIDE)        // 10240 per matrix per stage
#define BUFSZ (2*MTILE)            // 20480
#define STAGES 4
#define TG_SMEM (STAGES*BUFSZ)     // 81920 -> 2 CTAs/SM

template<int ACT, int OMODE, int BIG>
__global__ void __launch_bounds__(256)
tgemm_k(const __half* __restrict__ A, const __half* __restrict__ B,
        const float* __restrict__ bias, float* __restrict__ C, __half* __restrict__ C2,
        int M, int K, int lda, int ldb, int ldc, int segoff, float oscale,
        int npA, int npB, int splitN,
        long long sAi, long long sAo, long long sBi, long long sBo,
        long long sCi, long long sCo, long long sbias, int innerN)
{
    const int segA_[3] = {0,0,1};
    const int segB_[3] = {0,1,0};
    extern __shared__ char smem[];
    uint32_t sb = smem_u32(smem);
    int tid = threadIdx.x;
    int z = blockIdx.z, zi = z % innerN, zo = z / innerN;
    if (!BIG) A += (size_t)(zi*sAi + zo*sAo);
    B += (size_t)(zi*sBi + zo*sBo);
    if (OMODE == 0) C  += (size_t)(zi*sCi + zo*sCo);
    else            C2 += (size_t)(zi*sCi + zo*sCo);
    int m0 = blockIdx.y * 128, n0 = blockIdx.x * 128;

    const int KPC = K >> 5;                  // 32-wide chunks per product
    const int NP = (n0 < splitN) ? npA : npB;
    const int NC = NP * KPC;

    // per-thread A/B load slots (row/col fixed across chunks): 2 slots, 16B each
    int arow_[2]; uint32_t asz_[2]; long long aoff_[2]; int ac_[2];
    int brow_[2]; int bc_[2];
    #pragma unroll
    for (int i = 0; i < 2; i++) {
        int f = tid + (i << 8);
        int row = f >> 2, c = f & 3;
        int gr = m0 + row;
        int grc = gr < M ? gr : (M - 1);
        arow_[i] = row; ac_[i] = c;
        asz_[i] = gr < M ? 16u : 0u;
        if (BIG) {
            int b = grc / SM1, s = grc % SM1;
            aoff_[i] = (long long)(b*SS + s) * (2*DD);
        } else {
            aoff_[i] = (long long)grc * lda;
        }
        brow_[i] = row; bc_[i] = c;
    }

    auto issue = [&](int kc, int buf) {
        int p = kc / KPC;
        int k0 = (kc - p * KPC) << 5;
        uint32_t sA = sb + buf * BUFSZ;
        uint32_t sB = sA + MTILE;
        if (BIG) {
            int side = (k0 >= DD) ? 1 : 0;
            long long cofs = (long long)side*(2*DD) + segA_[p]*DD + (k0 - side*DD);
            #pragma unroll
            for (int i = 0; i < 2; i++) {
                const void* src = A + aoff_[i] + cofs + ac_[i] * 8;
                CP_ASYNC16(sA + arow_[i] * RSTRIDE + ac_[i] * 16, src, asz_[i]);
            }
        } else {
            const __half* Ap = A + (size_t)segA_[p] * K + k0;
            #pragma unroll
            for (int i = 0; i < 2; i++) {
                const void* src = Ap + aoff_[i] + ac_[i] * 8;
                CP_ASYNC16(sA + arow_[i] * RSTRIDE + ac_[i] * 16, src, asz_[i]);
            }
        }
        const __half* Bp = B + (size_t)segB_[p] * K + k0;
        #pragma unroll
        for (int i = 0; i < 2; i++) {
            const void* src = Bp + (size_t)(n0 + brow_[i]) * ldb + bc_[i] * 8;
            CP_ASYNC16(sB + brow_[i] * RSTRIDE + bc_[i] * 16, src, 16u);
        }
    };

    int lane = tid & 31, w = tid >> 5;
    int wm = w & 1, wn = w >> 1;
    uint32_t a_row = ((lane >> 3) & 1) * 8 + (lane & 7);
    uint32_t a_cs  = lane >> 4;
    uint32_t b_row = (lane >> 4) * 8 + (lane & 7);
    uint32_t b_cs  = (lane >> 3) & 1;

    float acc[4][4][4];
    #pragma unroll
    for (int i = 0; i < 4; i++)
        #pragma unroll
        for (int j = 0; j < 4; j++)
            #pragma unroll
            for (int r = 0; r < 4; r++) acc[i][j][r] = 0.f;

    issue(0, 0); CP_COMMIT();
    issue(1, 1); CP_COMMIT();
    issue(2, 2); CP_COMMIT();

    for (int kc = 0; kc < NC; kc++) {
        CP_WAIT2();            // oldest committed group (kc) complete
        __syncthreads();       // all warps done reading buf (kc-1)&3
        if (kc + 3 < NC) issue(kc + 3, (kc + 3) & 3);
        CP_COMMIT();           // unconditional: exact wait_group accounting at tail

        uint32_t sA = sb + (kc & 3) * BUFSZ;
        uint32_t sB = sA + MTILE;
        #pragma unroll
        for (int ks = 0; ks < 2; ks++) {
            uint32_t av[4][4], bv[2][4];
            #pragma unroll
            for (int mt = 0; mt < 4; mt++) {
                uint32_t ad = sA + (wm*64 + mt*16 + a_row) * RSTRIDE + ((ks*2 + a_cs) << 4);
                LDSM4(av[mt][0], av[mt][1], av[mt][2], av[mt][3], ad);
            }
            #pragma unroll
            for (int bt = 0; bt < 2; bt++) {
                uint32_t bd = sB + (wn*32 + bt*16 + b_row) * RSTRIDE + ((ks*2 + b_cs) << 4);
                LDSM4(bv[bt][0], bv[bt][1], bv[bt][2], bv[bt][3], bd);
            }
            #pragma unroll
            for (int mt = 0; mt < 4; mt++)
                #pragma unroll
                for (int nt = 0; nt < 4; nt++) {
                    uint32_t b0 = bv[nt >> 1][(nt & 1) * 2];
                    uint32_t b1 = bv[nt >> 1][(nt & 1) * 2 + 1];
                    MMA16816(acc[mt][nt], av[mt], b0, b1);
                }
        }
    }

    // ---- epilogue ----
    if (bias) bias += (size_t)z * (size_t)sbias;
    #pragma unroll
    for (int mt = 0; mt < 4; mt++) {
        int r0 = m0 + wm*64 + mt*16 + (lane >> 2);
        #pragma unroll
        for (int nt = 0; nt < 4; nt++) {
            int col = n0 + wn*32 + nt*8 + (lane & 3)*2;
            float bb0 = 0.f, bb1 = 0.f;
            if (bias) { bb0 = bias[col]; bb1 = bias[col+1]; }
            #pragma unroll
            for (int half_ = 0; half_ < 2; half_++) {
                int r = r0 + half_*8;
                if (r >= M) continue;
                float v0 = acc[mt][nt][half_*2]   * oscale + bb0;
                float v1 = acc[mt][nt][half_*2+1] * oscale + bb1;
                if (ACT == 1) { v0 = gelu_fast(v0); v1 = gelu_fast(v1); }
                if (OMODE == 0) {
                    *(float2*)(C + (size_t)r*ldc + col) = make_float2(v0, v1);
                } else {
                    __half* d = C2 + (size_t)r*ldc + col;
                    __half h0 = __float2half_rn(v0);
                    __half h1 = __float2half_rn(v1);
                    __half l0 = __float2half_rn(v0 - __half2float(h0));
                    __half l1 = __float2half_rn(v1 - __half2float(h1));
                    *(__half2*)(d)          = __halves2half2(h0, h1);
                    *(__half2*)(d + segoff) = __halves2half2(l0, l1);
                }
            }
        }
    }
}

// ================= split / misc small kernels =================
__global__ void split2_k(const float* __restrict__ src, __half* __restrict__ dst,
                         long long total, int C, float scale) {
    long long idx = (long long)blockIdx.x * 256 + threadIdx.x;
    if (idx >= total) return;
    long long r = idx / C; int c = (int)(idx % C);
    float v = src[idx] * scale;
    __half h = __float2half_rn(v);
    __half l = __float2half_rn(v - __half2float(h));
    __half* d = dst + r * (2LL*C) + c;
    d[0] = h; d[C] = l;
}

__global__ void biascat_k(const float* __restrict__ bp, const float* __restrict__ ipb) {
    int i = blockIdx.x * 256 + threadIdx.x;
    if (i < DD)      g_bc[i] = bp[i];
    else if (i < XQ) g_bc[i] = ipb[i - DD];
}

__global__ void norm_k() {
    int r = blockIdx.x;
    const float* p = g_xq + (size_t)r * XQ;
    float ss = 0.f;
    for (int i = threadIdx.x; i < DD; i += 256) { float v = p[i]; ss += v*v; }
    __shared__ float sh[256];
    sh[threadIdx.x] = ss; __syncthreads();
    for (int o = 128; o > 0; o >>= 1) {
        if (threadIdx.x < o) sh[threadIdx.x] += sh[threadIdx.x + o];
        __syncthreads();
    }
    if (threadIdx.x == 0) g_norm[r] = fmaxf(sqrtf(sh[0]), 1e-8f);
}

__global__ void cos_k() {
    int b = blockIdx.y, t = blockIdx.x;
    int scale, i;
    if (t < 1023)      { scale = 1; i = t; }
    else if (t < 1534) { scale = 2; i = t - 1023; }
    else               { scale = 4; i = t - 1534; }
    int s0 = i * scale, s1 = s0 + scale;
    const float* a = g_xq + ((size_t)b*SS + s0) * XQ;
    const float* c = g_xq + ((size_t)b*SS + s1) * XQ;
    float d = 0.f;
    for (int j = threadIdx.x; j < DD; j += 256) d += a[j] * c[j];
    __shared__ float sh[256];
    sh[threadIdx.x] = d; __syncthreads();
    for (int o = 128; o > 0; o >>= 1) {
        if (threadIdx.x < o) sh[threadIdx.x] += sh[threadIdx.x + o];
        __syncthreads();
    }
    if (threadIdx.x == 0)
        g_cs[b*CS_TOT + t] = sh[0] / (g_norm[b*SS + s0] * g_norm[b*SS + s1]);
}

__global__ void base_k() {
    int idx = blockIdx.x * 256 + threadIdx.x;
    if (idx >= NB*SM1) return;
    int b = idx / SM1, j = idx % SM1;
    const int Ls[3]   = {1023, 511, 255};
    const int offs[3] = {0, 1023, 1534};
    float acc = 0.f;
    #pragma unroll
    for (int u = 0; u < 3; u++) {
        int L = Ls[u];
        float ratio = (float)((double)L / 1023.0);
        float src = ((float)j + 0.5f) * ratio - 0.5f;
        src = fminf(fmaxf(src, 0.0f), (float)(L - 1));
        int i0 = (int)floorf(src);
        int i1 = min(i0 + 1, L - 1);
        float w = src - (float)i0;
        const float* cs = g_cs + b*CS_TOT + offs[u];
        acc += cs[i0] * (1.0f - w) + cs[i1] * w;
    }
    g_base[idx] = 0.5f * (1.0f - acc / 3.0f);
}

__global__ void learned_final_k(const float* __restrict__ detW3,
                                const float* __restrict__ detb3) {
    int r = blockIdx.x;
    __shared__ float sh[256];
    __shared__ float sacc;
    if (threadIdx.x == 0) sacc = 0.f;
    for (int n = 0; n < 3; n++) {
        const float* h2p = g_h2 + ((size_t)n*ROWS_DET + r) * (DD/2);
        const float* w   = detW3 + n*(DD/2);
        float part = 0.f;
        for (int j = threadIdx.x; j < DD/2; j += 256) part += h2p[j] * w[j];
        __syncthreads();
        sh[threadIdx.x] = part; __syncthreads();
        for (int o = 128; o > 0; o >>= 1) {
            if (threadIdx.x < o) sh[threadIdx.x] += sh[threadIdx.x + o];
            __syncthreads();
        }
        if (threadIdx.x == 0) {
            float t = sh[0] + detb3[n];
            sacc += 1.0f / (1.0f + expf(-t));
        }
        __syncthreads();
    }
    if (threadIdx.x == 0)
        g_final[r] = 0.6f * g_base[r] + 0.4f * (sacc / 3.0f);
}

// parallel segmentation: integer scans (exact, order-independent)
__global__ void __launch_bounds__(SS)
seg_scan_k() {
    int b = blockIdx.x, t = threadIdx.x;
    __shared__ int sscan[SS];
    __shared__ int smax[SS];
    __shared__ int rmin[SS];
    float bv = (t == 0) ? 1.0f : g_final[b*SM1 + t - 1];
    int f = (t == 0) ? 1 : (bv > 0.5f ? 1 : 0);
    sscan[t] = f;
    smax[t]  = f ? t : -1;
    rmin[t]  = f ? t : SS;
    __syncthreads();
    for (int o = 1; o < SS; o <<= 1) {
        int vs = sscan[t];
        int vm = smax[t];
        int vr = rmin[t];
        int vs2 = (t >= o) ? sscan[t - o] : 0;
        int vm2 = (t >= o) ? smax[t - o]  : -1;
        int vr2 = (t + o < SS) ? rmin[t + o] : SS;
        __syncthreads();
        sscan[t] = vs + vs2;
        smax[t]  = max(vm, vm2);
        rmin[t]  = min(vr, vr2);
        __syncthreads();
    }
    int m = sscan[t] - 1;
    g_seg[b*SS + t] = m;
    g_qlo[b*SS + t] = smax[t];
    int hi = (t < SS - 1) ? rmin[t + 1] : SS;
    g_qhi[b*SS + t] = hi;
    if (t < MAXC) { g_segstart[b*MAXC + t] = 0; g_segcount[b*MAXC + t] = 0; }
    __syncthreads();
    if (f && m < MAXC) {
        g_segstart[b*MAXC + m] = t;
        g_segcount[b*MAXC + m] = hi - t;
    }
}

// fused segment attention: one warp per (b, s, h); fp32; writes fp16-split ctx
__global__ void __launch_bounds__(256)
seg_attn_k() {
    __shared__ float dots[8][SS];
    int w = threadIdx.x >> 5, lane = threadIdx.x & 31;
    int g = blockIdx.x * 8 + w;
    int h = g % NH;
    int s = (g / NH) & (SS - 1);
    int b = g / (NH * SS);
    int lo = g_qlo[b*SS + s], hi = g_qhi[b*SS + s];

    const float* qp = g_xq + ((size_t)(b*SS + s))*XQ + QOFF + h*HDIM + lane*4;
    float4 qv = *(const float4*)qp;
    const float scale = 0.088388347648318440550f;   // 1/sqrt(128)

    const float* kbase = g_xq + ((size_t)(b*SS))*XQ + QOFF + DD + h*HDIM + lane*4;
    float mx = -3.402823e38f;
    for (int k = lo; k < hi; k++) {
        float4 kv = *(const float4*)(kbase + (size_t)k*XQ);
        float d = qv.x*kv.x + qv.y*kv.y + qv.z*kv.z + qv.w*kv.w;
        #pragma unroll
        for (int o = 16; o > 0; o >>= 1) d += __shfl_xor_sync(0xffffffffu, d, o);
        d *= scale;
        if (lane == 0) dots[w][k - lo] = d;
        mx = fmaxf(mx, d);
    }
    __syncwarp();

    const float* vbase = g_xq + ((size_t)(b*SS))*XQ + QOFF + 2*DD + h*HDIM + lane*4;
    float4 acc = make_float4(0.f, 0.f, 0.f, 0.f);
    float sum = 0.f;
    for (int k = lo; k < hi; k++) {
        float e = expf(dots[w][k - lo] - mx);
        sum += e;
        float4 vv = *(const float4*)(vbase + (size_t)k*XQ);
        acc.x += e*vv.x; acc.y += e*vv.y; acc.z += e*vv.z; acc.w += e*vv.w;
    }
    float inv = 1.0f / sum;
    float c0 = acc.x*inv, c1 = acc.y*inv, c2 = acc.z*inv, c3 = acc.w*inv;

    __half* d = g_ctx2 + ((size_t)(b*SS + s))*(2*DD) + h*HDIM + lane*4;
    __half h0 = __float2half_rn(c0), h1 = __float2half_rn(c1);
    __half h2 = __float2half_rn(c2), h3 = __float2half_rn(c3);
    *(__half2*)(d)     = __halves2half2(h0, h1);
    *(__half2*)(d + 2) = __halves2half2(h2, h3);
    __half l0 = __float2half_rn(c0 - __half2float(h0));
    __half l1 = __float2half_rn(c1 - __half2float(h1));
    __half l2 = __float2half_rn(c2 - __half2float(h2));
    __half l3 = __float2half_rn(c3 - __half2float(h3));
    *(__half2*)(d + DD)     = __halves2half2(l0, l1);
    *(__half2*)(d + DD + 2) = __halves2half2(l2, l3);
}

// pooling + embeddings, writes 2-way fp16 split chunk directly
__global__ void chunk_k(const float* __restrict__ size_emb,
                        const float* __restrict__ pos_enc) {
    int m = blockIdx.x, b = blockIdx.y;
    int cnt = g_segcount[b*MAXC + m];
    int st  = g_segstart[b*MAXC + m];
    __half* drow = g_chunk2 + ((size_t)b*MAXC + m) * (2*DD);
    for (int d = threadIdx.x; d < DD; d += 256) {
        float v;
        if (cnt > 0) {
            float sum = 0.f;
            for (int s = st; s < st + cnt; s++)
                sum += g_attnout[((size_t)b*SS + s)*DD + d];
            int cl = min(cnt, 1023);
            v = sum / (float)cnt + size_emb[(size_t)cl*DD + d];
        } else v = 0.f;
        v += pos_enc[(size_t)m*DD + d];
        __half h = __float2half_rn(v);
        drow[d]      = h;
        drow[DD + d] = __float2half_rn(v - __half2float(h));
    }
}

__global__ void ln_k(const float* __restrict__ gamma,
                     const float* __restrict__ beta,
                     float* __restrict__ out) {
    int r = blockIdx.x;
    const float* y = g_y + (size_t)r*DD;
    __shared__ float sh[256];
    float s = 0.f;
    for (int d = threadIdx.x; d < DD; d += 256) s += y[d];
    sh[threadIdx.x] = s; __syncthreads();
    for (int o = 128; o > 0; o >>= 1) {
        if (threadIdx.x < o) sh[threadIdx.x] += sh[threadIdx.x+o];
        __syncthreads();
    }
    float mu = sh[0] / (float)DD; __syncthreads();
    float v2 = 0.f;
    for (int d = threadIdx.x; d < DD; d += 256) { float t = y[d]-mu; v2 += t*t; }
    sh[threadIdx.x] = v2; __syncthreads();
    for (int o = 128; o > 0; o >>= 1) {
        if (threadIdx.x < o) sh[threadIdx.x] += sh[threadIdx.x+o];
        __syncthreads();
    }
    float inv = 1.0f / sqrtf(sh[0] / (float)DD + 1e-5f);
    for (int d = threadIdx.x; d < DD; d += 256)
        out[(size_t)r*DD + d] = (y[d] - mu) * inv * gamma[d] + beta[d];
}

// ---------------- host launchers ----------------
struct GemmArgs {
    const __half *A, *B;
    const float* bias;
    float* C;
    __half* C2;
    int M, N, K, lda, ldb, ldc, segoff;
    float oscale;
    int npA, npB, splitN;
    long long sAi, sAo, sBi, sBo, sCi, sCo, sbias;
    int innerN, batch;
};

template<int ACT, int OMODE, int BIG>
static void tg_launch(const GemmArgs& a) {
    dim3 grid(a.N/128, (a.M + 127)/128, a.batch);
    tgemm_k<ACT,OMODE,BIG><<<grid,256,TG_SMEM>>>(a.A, a.B, a.bias, a.C, a.C2,
        a.M, a.K, a.lda, a.ldb, a.ldc, a.segoff, a.oscale,
        a.npA, a.npB, a.splitN,
        a.sAi, a.sAo, a.sBi, a.sBo, a.sCi, a.sCo, a.sbias, a.innerN);
}

static void split2(const float* src, __half* dst, long long rows, int cols, float scale) {
    long long total = rows * cols;
    split2_k<<<(unsigned)((total + 255)/256), 256>>>(src, dst, total, cols, scale);
}

#define NPALL 3, 3, (1<<30)

extern "C" void kernel_launch(void* const* d_in, const int* in_sizes, int n_in,
                              void* d_out, int out_size) {
    const float* x         = (const float*)d_in[0];
    const float* Wp        = (const float*)d_in[1];
    const float* bp        = (const float*)d_in[2];
    const float* detW1     = (const float*)d_in[3];
    const float* detb1     = (const float*)d_in[4];
    const float* detW2     = (const float*)d_in[5];
    const float* detb2     = (const float*)d_in[6];
    const float* detW3     = (const float*)d_in[7];
    const float* detb3     = (const float*)d_in[8];
    const float* in_proj_w = (const float*)d_in[9];
    const float* in_proj_b = (const float*)d_in[10];
    const float* out_w     = (const float*)d_in[11];
    const float* out_b     = (const float*)d_in[12];
    const float* size_emb  = (const float*)d_in[13];
    const float* pos_enc   = (const float*)d_in[14];
    const float* procW1    = (const float*)d_in[15];
    const float* procb1    = (const float*)d_in[16];
    const float* procW2    = (const float*)d_in[17];
    const float* procb2    = (const float*)d_in[18];
    const float* ln_g      = (const float*)d_in[19];
    const float* ln_b      = (const float*)d_in[20];
    float* outp = (float*)d_out;

    cudaFuncSetAttribute(tgemm_k<0,0,0>, cudaFuncAttributeMaxDynamicSharedMemorySize, TG_SMEM);
    cudaFuncSetAttribute(tgemm_k<1,0,0>, cudaFuncAttributeMaxDynamicSharedMemorySize, TG_SMEM);
    cudaFuncSetAttribute(tgemm_k<1,1,0>, cudaFuncAttributeMaxDynamicSharedMemorySize, TG_SMEM);
    cudaFuncSetAttribute(tgemm_k<1,1,1>, cudaFuncAttributeMaxDynamicSharedMemorySize, TG_SMEM);

    void *p;
    cudaGetSymbolAddress(&p, g_xq);      float* xq      = (float*)p;
    cudaGetSymbolAddress(&p, g_bc);      float* bc      = (float*)p;
    cudaGetSymbolAddress(&p, g_h2);      float* h2      = (float*)p;
    cudaGetSymbolAddress(&p, g_attnout); float* attnout = (float*)p;
    cudaGetSymbolAddress(&p, g_y);       float* yb      = (float*)p;
    cudaGetSymbolAddress(&p, g_x2);      __half* x2     = (__half*)p;
    cudaGetSymbolAddress(&p, g_wc2);     __half* wc2    = (__half*)p;
    cudaGetSymbolAddress(&p, g_dW1_2);   __half* dW1_2  = (__half*)p;
    cudaGetSymbolAddress(&p, g_h1_2);    __half* h1_2   = (__half*)p;
    cudaGetSymbolAddress(&p, g_dW2_2);   __half* dW2_2  = (__half*)p;
    cudaGetSymbolAddress(&p, g_ctx2);    __half* ctx2   = (__half*)p;
    cudaGetSymbolAddress(&p, g_outw2);   __half* outw2  = (__half*)p;
    cudaGetSymbolAddress(&p, g_chunk2);  __half* chunk2 = (__half*)p;
    cudaGetSymbolAddress(&p, g_pw1_2);   __half* pw1_2  = (__half*)p;
    cudaGetSymbolAddress(&p, g_hproc2);  __half* hproc2 = (__half*)p;
    cudaGetSymbolAddress(&p, g_pw2_2);   __half* pw2_2  = (__half*)p;

    // ===== input splits (weights scaled by 64 to keep fp16 lo plane normal) =====
    split2(x, x2, NB*SS, DD, 1.0f);
    split2(Wp, wc2, DD, DD, WSCALE);                            // rows 0..1535 of combined W
    split2(in_proj_w, wc2 + (size_t)DD*2*DD, 3*DD, DD, WSCALE); // rows 1536..6143
    split2(detW1, dW1_2, 3*DD, 2*DD, WSCALE);
    split2(detW2, dW2_2, 3*(DD/2), DD, WSCALE);
    split2(out_w, outw2, DD, DD, WSCALE);
    split2(procW1, pw1_2, 2*DD, DD, WSCALE);
    split2(procW2, pw2_2, DD, 2*DD, WSCALE);
    biascat_k<<<(XQ + 255)/256, 256>>>(bp, in_proj_b);

    // ===== merged xling|qkv GEMM: 3 products for n<1536 (boundary), 2 for qkv =====
    { GemmArgs a = { x2, wc2, bc, xq, nullptr, NB*SS, XQ, DD, 2*DD, 2*DD, XQ, 0,
                     OSINV, 3, 2, DD, 0,0,0,0,0,0,0, 1, 1 };
      tg_launch<0,0,0>(a); }

    // ===== boundary path =====
    norm_k<<<NB*SS, 256>>>();
    cos_k<<<dim3(CS_TOT, NB), 256>>>();
    base_k<<<(NB*SM1 + 255)/256, 256>>>();
    // h1 = gelu(bi @ detW1[n]^T + b) -> 2-way split directly; A gathered from x2 (BIG=1)
    { GemmArgs a = { x2, dW1_2, detb1, nullptr, h1_2, ROWS_DET, DD, 2*DD,
                     2*DD, 2*2*DD, 2*DD, DD, OSINV, NPALL,
                     0, 0, (long long)DD*2*2*DD, 0,
                     (long long)ROWS_DET*2*DD, 0, DD, 3, 3 };
      tg_launch<1,1,1>(a); }
    // h2 = gelu(h1 @ detW2[n]^T + b) fp32
    { GemmArgs a = { h1_2, dW2_2, detb2, h2, nullptr, ROWS_DET, DD/2, DD,
                     2*DD, 2*DD, DD/2, 0, OSINV, NPALL,
                     (long long)ROWS_DET*2*DD, 0, (long long)(DD/2)*2*DD, 0,
                     (long long)ROWS_DET*(DD/2), 0, DD/2, 3, 3 };
      tg_launch<1,0,0>(a); }
    learned_final_k<<<ROWS_DET, 256>>>(detW3, detb3);
    seg_scan_k<<<NB, SS>>>();

    // ===== continuous path =====
    // fused segment attention (fp32) -> ctx2 (fp16 split)
    seg_attn_k<<<NB*SS*NH/8, 256>>>();
    // attn_out = ctx @ out_w^T + out_b
    { GemmArgs a = { ctx2, outw2, out_b, attnout, nullptr, NB*SS, DD, DD,
                     2*DD, 2*DD, DD, 0, OSINV, NPALL, 0,0,0,0,0,0,0, 1, 1 };
      tg_launch<0,0,0>(a); }
    chunk_k<<<dim3(MAXC, NB), 256>>>(size_emb, pos_enc);
    // hproc = gelu(chunk @ procW1^T + b) -> 2-way split directly
    { GemmArgs a = { chunk2, pw1_2, procb1, nullptr, hproc2, NB*MAXC, 2*DD, DD,
                     2*DD, 2*DD, 2*2*DD, 2*DD, OSINV, NPALL, 0,0,0,0,0,0,0, 1, 1 };
      tg_launch<1,1,0>(a); }
    // y = hproc @ procW2^T + b
    { GemmArgs a = { hproc2, pw2_2, procb2, yb, nullptr, NB*MAXC, DD, 2*DD,
                     2*2*DD, 2*2*DD, DD, 0, OSINV, NPALL, 0,0,0,0,0,0,0, 1, 1 };
      tg_launch<0,0,0>(a); }
    ln_k<<<NB*MAXC, 256>>>(ln_g, ln_b, outp);
}

// round 11
// speedup vs baseline: 1.0558x; 1.0558x over previous
#include <cuda_runtime.h>
#include <cuda_fp16.h>
#include <math.h>
#include <stdint.h>

// ---------------- problem constants ----------------
#define NB 4
#define SS 1024
#define DD 1536
#define NH 12
#define HDIM 128
#define MAXC 256
#define SM1 1023
#define ROWS_DET (NB*SM1)        // 4092
#define CS_TOT (1023+511+255)    // 1789
#define XQ 6144                  // combined xling|qkv row width
#define QOFF 1536                // qkv column offset in combined buffer

#define WSCALE 64.0f
#define OSINV  0.015625f         // 1/64

// ---------------- fp32 scratch ----------------
__device__ float g_xq[(size_t)NB*SS*XQ];       // [.,0:1536)=xling, [.,1536:6144)=qkv
__device__ float g_bc[XQ];                     // combined bias
__device__ float g_norm[NB*SS];
__device__ float g_cs[NB*CS_TOT];
__device__ float g_base[NB*SM1];
__device__ float g_h2[(size_t)3*ROWS_DET*(DD/2)];
__device__ float g_final[NB*SM1];
__device__ int   g_seg[NB*SS];
__device__ int   g_qlo[NB*SS];
__device__ int   g_qhi[NB*SS];
__device__ int   g_segstart[NB*MAXC];
__device__ int   g_segcount[NB*MAXC];
__device__ float g_attnout[(size_t)NB*SS*DD];
__device__ float g_y[(size_t)NB*MAXC*DD];

// ---------------- fp16 2-way split scratch [rows][2K] (hi|lo) ----------------
__device__ __half g_x2[(size_t)NB*SS*2*DD];
__device__ __half g_wc2[(size_t)XQ*2*DD];      // combined [Wp | in_proj_w] split
__device__ __half g_dW1_2[(size_t)3*DD*2*(2*DD)];
__device__ __half g_h1_2[(size_t)3*ROWS_DET*2*DD];
__device__ __half g_dW2_2[(size_t)3*(DD/2)*2*DD];
__device__ __half g_ctx2[(size_t)NB*SS*2*DD];
__device__ __half g_outw2[(size_t)DD*2*DD];
__device__ __half g_chunk2[(size_t)NB*MAXC*2*DD];
__device__ __half g_pw1_2[(size_t)2*DD*2*DD];
__device__ __half g_hproc2[(size_t)NB*MAXC*2*2*DD];
__device__ __half g_pw2_2[(size_t)DD*2*2*DD];

// fast erf: Abramowitz-Stegun 7.1.26, |err| <= 1.5e-7 (absolute)
__device__ __forceinline__ float erf_fast(float x) {
    float ax = fabsf(x);
    float t = 1.0f / fmaf(0.3275911f, ax, 1.0f);
    float p = t*(0.254829592f + t*(-0.284496736f + t*(1.421413741f +
              t*(-1.453152027f + t*1.061405429f))));
    float r = 1.0f - p * __expf(-ax*ax);
    return copysignf(r, x);
}
__device__ __forceinline__ float gelu_fast(float v) {
    return 0.5f * v * (1.0f + erf_fast(v * 0.70710678118654752440f));
}
__device__ __forceinline__ uint32_t smem_u32(const void* p) {
    uint32_t a;
    asm("{ .reg .u64 t; cvta.to.shared.u64 t, %1; cvt.u32.u64 %0, t; }" : "=r"(a) : "l"(p));
    return a;
}

#define LDSM4(r0,r1,r2,r3,addr) \
    asm volatile("ldmatrix.sync.aligned.m8n8.x4.shared.b16 {%0,%1,%2,%3}, [%4];" \
        : "=r"(r0), "=r"(r1), "=r"(r2), "=r"(r3) : "r"(addr))

#define MMA16816(d, a, b0, b1) \
    asm volatile("mma.sync.aligned.m16n8k16.row.col.f32.f16.f16.f32 " \
        "{%0,%1,%2,%3},{%4,%5,%6,%7},{%8,%9},{%0,%1,%2,%3};" \
        : "+f"((d)[0]), "+f"((d)[1]), "+f"((d)[2]), "+f"((d)[3]) \
        : "r"((a)[0]), "r"((a)[1]), "r"((a)[2]), "r"((a)[3]), "r"(b0), "r"(b1))

#define CP_ASYNC16(dst, src, sz) \
    asm volatile("cp.async.ca.shared.global [%0], [%1], 16, %2;" :: "r"(dst), "l"(src), "r"(sz))
#define CP_COMMIT() asm volatile("cp.async.commit_group;" ::: "memory")
#define CP_WAIT1() asm volatile("cp.async.wait_group 1;" ::: "memory")
#define CP_WAIT0() asm volatile("cp.async.wait_group 0;" ::: "memory")

// ================= mma.sync fp16 split GEMM (2-stage, K64, 2 CTAs/SM) =================
// A[M][2K] (hi|lo), B[N][2K] (hi|lo).
// np = (n0 < splitN) ? npA : npB.
//   np=3: Ah.Bh + Ah.Bl + Al.Bh   (chunk order identical to round 9 -> bit-identical)
//   np=2: Ah.Bh + Ah.Bl           (weights full precision, data fp16-truncated)
// BIG=1: A is g_x2; rows are bigrams (b,s); chunk selects x_s / x_{s+1}.
#define RSTRIDE 144
#define ATILE (128*RSTRIDE)        // 18432
#define BUFSZ (2*ATILE)            // 36864
#define TG_SMEM (2*BUFSZ)          // 73728

template<int ACT, int OMODE, int BIG>
__global__ void __launch_bounds__(256)
tgemm_k(const __half* __restrict__ A, const __half* __restrict__ B,
        const float* __restrict__ bias, float* __restrict__ C, __half* __restrict__ C2,
        int M, int K, int lda, int ldb, int ldc, int segoff, float oscale,
        int npA, int npB, int splitN,
        long long sAi, long long sAo, long long sBi, long long sBo,
        long long sCi, long long sCo, long long sbias, int innerN)
{
    const int segA_[3] = {0,0,1};
    const int segB_[3] = {0,1,0};
    extern __shared__ char smem[];
    uint32_t sb = smem_u32(smem);
    int tid = threadIdx.x;
    int z = blockIdx.z, zi = z % innerN, zo = z / innerN;
    if (!BIG) A += (size_t)(zi*sAi + zo*sAo);
    B += (size_t)(zi*sBi + zo*sBo);
    if (OMODE == 0) C  += (size_t)(zi*sCi + zo*sCo);
    else            C2 += (size_t)(zi*sCi + zo*sCo);
    int m0 = blockIdx.y * 128, n0 = blockIdx.x * 128;

    const int KPC = K >> 6;
    const int NP = (n0 < splitN) ? npA : npB;
    const int NC = NP * KPC;

    // per-thread A-load slots (row/col fixed across chunks)
    int arow_[4]; uint32_t asz_[4]; long long aoff_[4]; int ac_[4];
    #pragma unroll
    for (int i = 0; i < 4; i++) {
        int f = tid + (i << 8);
        int row = f >> 3, c = f & 7;
        int gr = m0 + row;
        int grc = gr < M ? gr : (M - 1);
        arow_[i] = row; ac_[i] = c;
        asz_[i] = gr < M ? 16u : 0u;
        if (BIG) {
            int b = grc / SM1, s = grc % SM1;
            aoff_[i] = (long long)(b*SS + s) * (2*DD);
        } else {
            aoff_[i] = (long long)grc * lda;
        }
    }

    auto issue = [&](int kc, int buf) {
        int p = kc / KPC;
        int k0 = (kc - p * KPC) << 6;
        uint32_t sA = sb + buf * BUFSZ;
        uint32_t sB = sA + ATILE;
        if (BIG) {
            int side = (k0 >= DD) ? 1 : 0;
            long long cofs = (long long)side*(2*DD) + segA_[p]*DD + (k0 - side*DD);
            #pragma unroll
            for (int i = 0; i < 4; i++) {
                const void* src = A + aoff_[i] + cofs + ac_[i] * 8;
                CP_ASYNC16(sA + arow_[i] * RSTRIDE + ac_[i] * 16, src, asz_[i]);
            }
        } else {
            const __half* Ap = A + (size_t)segA_[p] * K + k0;
            #pragma unroll
            for (int i = 0; i < 4; i++) {
                const void* src = Ap + aoff_[i] + ac_[i] * 8;
                CP_ASYNC16(sA + arow_[i] * RSTRIDE + ac_[i] * 16, src, asz_[i]);
            }
        }
        const __half* Bp = B + (size_t)segB_[p] * K + k0;
        #pragma unroll
        for (int i = 0; i < 4; i++) {
            int f = tid + (i << 8);
            int row = f >> 3, c = f & 7;
            const void* src = Bp + (size_t)(n0 + row) * ldb + c * 8;
            CP_ASYNC16(sB + row * RSTRIDE + c * 16, src, 16u);
        }
    };

    int lane = tid & 31, w = tid >> 5;
    int wm = w & 1, wn = w >> 1;
    uint32_t a_row = ((lane >> 3) & 1) * 8 + (lane & 7);
    uint32_t a_cs  = lane >> 4;
    uint32_t b_row = (lane >> 4) * 8 + (lane & 7);
    uint32_t b_cs  = (lane >> 3) & 1;

    float acc[4][4][4];
    #pragma unroll
    for (int i = 0; i < 4; i++)
        #pragma unroll
        for (int j = 0; j < 4; j++)
            #pragma unroll
            for (int r = 0; r < 4; r++) acc[i][j][r] = 0.f;

    issue(0, 0);
    CP_COMMIT();

    for (int kc = 0; kc < NC; kc++) {
        int cur = kc & 1;
        if (kc + 1 < NC) { issue(kc + 1, cur ^ 1); CP_COMMIT(); CP_WAIT1(); }
        else             { CP_WAIT0(); }
        __syncthreads();

        uint32_t sA = sb + cur * BUFSZ;
        uint32_t sB = sA + ATILE;
        #pragma unroll
        for (int ks = 0; ks < 4; ks++) {
            uint32_t av[4][4], bv[2][4];
            #pragma unroll
            for (int mt = 0; mt < 4; mt++) {
                uint32_t ad = sA + (wm*64 + mt*16 + a_row) * RSTRIDE + ((ks*2 + a_cs) << 4);
                LDSM4(av[mt][0], av[mt][1], av[mt][2], av[mt][3], ad);
            }
            #pragma unroll
            for (int bt = 0; bt < 2; bt++) {
                uint32_t bd = sB + (wn*32 + bt*16 + b_row) * RSTRIDE + ((ks*2 + b_cs) << 4);
                LDSM4(bv[bt][0], bv[bt][1], bv[bt][2], bv[bt][3], bd);
            }
            #pragma unroll
            for (int mt = 0; mt < 4; mt++)
                #pragma unroll
                for (int nt = 0; nt < 4; nt++) {
                    uint32_t b0 = bv[nt >> 1][(nt & 1) * 2];
                    uint32_t b1 = bv[nt >> 1][(nt & 1) * 2 + 1];
                    MMA16816(acc[mt][nt], av[mt], b0, b1);
                }
        }
        __syncthreads();
    }

    // ---- epilogue ----
    if (bias) bias += (size_t)z * (size_t)sbias;
    #pragma unroll
    for (int mt = 0; mt < 4; mt++) {
        int r0 = m0 + wm*64 + mt*16 + (lane >> 2);
        #pragma unroll
        for (int nt = 0; nt < 4; nt++) {
            int col = n0 + wn*32 + nt*8 + (lane & 3)*2;
            float bb0 = 0.f, bb1 = 0.f;
            if (bias) { bb0 = bias[col]; bb1 = bias[col+1]; }
            #pragma unroll
            for (int half_ = 0; half_ < 2; half_++) {
                int r = r0 + half_*8;
                if (r >= M) continue;
                float v0 = acc[mt][nt][half_*2]   * oscale + bb0;
                float v1 = acc[mt][nt][half_*2+1] * oscale + bb1;
                if (ACT == 1) { v0 = gelu_fast(v0); v1 = gelu_fast(v1); }
                if (OMODE == 0) {
                    *(float2*)(C + (size_t)r*ldc + col) = make_float2(v0, v1);
                } else {
                    __half* d = C2 + (size_t)r*ldc + col;
                    __half h0 = __float2half_rn(v0);
                    __half h1 = __float2half_rn(v1);
                    __half l0 = __float2half_rn(v0 - __half2float(h0));
                    __half l1 = __float2half_rn(v1 - __half2float(h1));
                    *(__half2*)(d)          = __halves2half2(h0, h1);
                    *(__half2*)(d + segoff) = __halves2half2(l0, l1);
                }
            }
        }
    }
}

// ================= split / misc small kernels =================
__global__ void split2_k(const float* __restrict__ src, __half* __restrict__ dst,
                         long long total, int C, float scale) {
    long long idx = (long long)blockIdx.x * 256 + threadIdx.x;
    if (idx >= total) return;
    long long r = idx / C; int c = (int)(idx % C);
    float v = src[idx] * scale;
    __half h = __float2half_rn(v);
    __half l = __float2half_rn(v - __half2float(h));
    __half* d = dst + r * (2LL*C) + c;
    d[0] = h; d[C] = l;
}

__global__ void biascat_k(const float* __restrict__ bp, const float* __restrict__ ipb) {
    int i = blockIdx.x * 256 + threadIdx.x;
    if (i < DD)      g_bc[i] = bp[i];
    else if (i < XQ) g_bc[i] = ipb[i - DD];
}

__global__ void norm_k() {
    int r = blockIdx.x;
    const float* p = g_xq + (size_t)r * XQ;
    float ss = 0.f;
    for (int i = threadIdx.x; i < DD; i += 256) { float v = p[i]; ss += v*v; }
    __shared__ float sh[256];
    sh[threadIdx.x] = ss; __syncthreads();
    for (int o = 128; o > 0; o >>= 1) {
        if (threadIdx.x < o) sh[threadIdx.x] += sh[threadIdx.x + o];
        __syncthreads();
    }
    if (threadIdx.x == 0) g_norm[r] = fmaxf(sqrtf(sh[0]), 1e-8f);
}

__global__ void cos_k() {
    int b = blockIdx.y, t = blockIdx.x;
    int scale, i;
    if (t < 1023)      { scale = 1; i = t; }
    else if (t < 1534) { scale = 2; i = t - 1023; }
    else               { scale = 4; i = t - 1534; }
    int s0 = i * scale, s1 = s0 + scale;
    const float* a = g_xq + ((size_t)b*SS + s0) * XQ;
    const float* c = g_xq + ((size_t)b*SS + s1) * XQ;
    float d = 0.f;
    for (int j = threadIdx.x; j < DD; j += 256) d += a[j] * c[j];
    __shared__ float sh[256];
    sh[threadIdx.x] = d; __syncthreads();
    for (int o = 128; o > 0; o >>= 1) {
        if (threadIdx.x < o) sh[threadIdx.x] += sh[threadIdx.x + o];
        __syncthreads();
    }
    if (threadIdx.x == 0)
        g_cs[b*CS_TOT + t] = sh[0] / (g_norm[b*SS + s0] * g_norm[b*SS + s1]);
}

__global__ void base_k() {
    int idx = blockIdx.x * 256 + threadIdx.x;
    if (idx >= NB*SM1) return;
    int b = idx / SM1, j = idx % SM1;
    const int Ls[3]   = {1023, 511, 255};
    const int offs[3] = {0, 1023, 1534};
    float acc = 0.f;
    #pragma unroll
    for (int u = 0; u < 3; u++) {
        int L = Ls[u];
        float ratio = (float)((double)L / 1023.0);
        float src = ((float)j + 0.5f) * ratio - 0.5f;
        src = fminf(fmaxf(src, 0.0f), (float)(L - 1));
        int i0 = (int)floorf(src);
        int i1 = min(i0 + 1, L - 1);
        float w = src - (float)i0;
        const float* cs = g_cs + b*CS_TOT + offs[u];
        acc += cs[i0] * (1.0f - w) + cs[i1] * w;
    }
    g_base[idx] = 0.5f * (1.0f - acc / 3.0f);
}

__global__ void learned_final_k(const float* __restrict__ detW3,
                                const float* __restrict__ detb3) {
    int r = blockIdx.x;
    __shared__ float sh[256];
    __shared__ float sacc;
    if (threadIdx.x == 0) sacc = 0.f;
    for (int n = 0; n < 3; n++) {
        const float* h2p = g_h2 + ((size_t)n*ROWS_DET + r) * (DD/2);
        const float* w   = detW3 + n*(DD/2);
        float part = 0.f;
        for (int j = threadIdx.x; j < DD/2; j += 256) part += h2p[j] * w[j];
        __syncthreads();
        sh[threadIdx.x] = part; __syncthreads();
        for (int o = 128; o > 0; o >>= 1) {
            if (threadIdx.x < o) sh[threadIdx.x] += sh[threadIdx.x + o];
            __syncthreads();
        }
        if (threadIdx.x == 0) {
            float t = sh[0] + detb3[n];
            sacc += 1.0f / (1.0f + expf(-t));
        }
        __syncthreads();
    }
    if (threadIdx.x == 0)
        g_final[r] = 0.6f * g_base[r] + 0.4f * (sacc / 3.0f);
}

// parallel segmentation: integer scans (exact, order-independent)
__global__ void __launch_bounds__(SS)
seg_scan_k() {
    int b = blockIdx.x, t = threadIdx.x;
    __shared__ int sscan[SS];
    __shared__ int smax[SS];
    __shared__ int rmin[SS];
    float bv = (t == 0) ? 1.0f : g_final[b*SM1 + t - 1];
    int f = (t == 0) ? 1 : (bv > 0.5f ? 1 : 0);
    sscan[t] = f;
    smax[t]  = f ? t : -1;
    rmin[t]  = f ? t : SS;
    __syncthreads();
    for (int o = 1; o < SS; o <<= 1) {
        int vs = sscan[t];
        int vm = smax[t];
        int vr = rmin[t];
        int vs2 = (t >= o) ? sscan[t - o] : 0;
        int vm2 = (t >= o) ? smax[t - o]  : -1;
        int vr2 = (t + o < SS) ? rmin[t + o] : SS;
        __syncthreads();
        sscan[t] = vs + vs2;
        smax[t]  = max(vm, vm2);
        rmin[t]  = min(vr, vr2);
        __syncthreads();
    }
    int m = sscan[t] - 1;
    g_seg[b*SS + t] = m;
    g_qlo[b*SS + t] = smax[t];
    int hi = (t < SS - 1) ? rmin[t + 1] : SS;
    g_qhi[b*SS + t] = hi;
    if (t < MAXC) { g_segstart[b*MAXC + t] = 0; g_segcount[b*MAXC + t] = 0; }
    __syncthreads();
    if (f && m < MAXC) {
        g_segstart[b*MAXC + m] = t;
        g_segcount[b*MAXC + m] = hi - t;
    }
}

// fused segment attention: one warp per (b, s, h); fp32; writes fp16-split ctx
__global__ void __launch_bounds__(256)
seg_attn_k() {
    __shared__ float dots[8][SS];
    int w = threadIdx.x >> 5, lane = threadIdx.x & 31;
    int g = blockIdx.x * 8 + w;
    int h = g % NH;
    int s = (g / NH) & (SS - 1);
    int b = g / (NH * SS);
    int lo = g_qlo[b*SS + s], hi = g_qhi[b*SS + s];

    const float* qp = g_xq + ((size_t)(b*SS + s))*XQ + QOFF + h*HDIM + lane*4;
    float4 qv = *(const float4*)qp;
    const float scale = 0.088388347648318440550f;   // 1/sqrt(128)

    const float* kbase = g_xq + ((size_t)(b*SS))*XQ + QOFF + DD + h*HDIM + lane*4;
    float mx = -3.402823e38f;
    for (int k = lo; k < hi; k++) {
        float4 kv = *(const float4*)(kbase + (size_t)k*XQ);
        float d = qv.x*kv.x + qv.y*kv.y + qv.z*kv.z + qv.w*kv.w;
        #pragma unroll
        for (int o = 16; o > 0; o >>= 1) d += __shfl_xor_sync(0xffffffffu, d, o);
        d *= scale;
        if (lane == 0) dots[w][k - lo] = d;
        mx = fmaxf(mx, d);
    }
    __syncwarp();

    const float* vbase = g_xq + ((size_t)(b*SS))*XQ + QOFF + 2*DD + h*HDIM + lane*4;
    float4 acc = make_float4(0.f, 0.f, 0.f, 0.f);
    float sum = 0.f;
    for (int k = lo; k < hi; k++) {
        float e = expf(dots[w][k - lo] - mx);
        sum += e;
        float4 vv = *(const float4*)(vbase + (size_t)k*XQ);
        acc.x += e*vv.x; acc.y += e*vv.y; acc.z += e*vv.z; acc.w += e*vv.w;
    }
    float inv = 1.0f / sum;
    float c0 = acc.x*inv, c1 = acc.y*inv, c2 = acc.z*inv, c3 = acc.w*inv;

    __half* d = g_ctx2 + ((size_t)(b*SS + s))*(2*DD) + h*HDIM + lane*4;
    __half h0 = __float2half_rn(c0), h1 = __float2half_rn(c1);
    __half h2 = __float2half_rn(c2), h3 = __float2half_rn(c3);
    *(__half2*)(d)     = __halves2half2(h0, h1);
    *(__half2*)(d + 2) = __halves2half2(h2, h3);
    __half l0 = __float2half_rn(c0 - __half2float(h0));
    __half l1 = __float2half_rn(c1 - __half2float(h1));
    __half l2 = __float2half_rn(c2 - __half2float(h2));
    __half l3 = __float2half_rn(c3 - __half2float(h3));
    *(__half2*)(d + DD)     = __halves2half2(l0, l1);
    *(__half2*)(d + DD + 2) = __halves2half2(l2, l3);
}

// pooling + embeddings, writes 2-way fp16 split chunk directly
__global__ void chunk_k(const float* __restrict__ size_emb,
                        const float* __restrict__ pos_enc) {
    int m = blockIdx.x, b = blockIdx.y;
    int cnt = g_segcount[b*MAXC + m];
    int st  = g_segstart[b*MAXC + m];
    __half* drow = g_chunk2 + ((size_t)b*MAXC + m) * (2*DD);
    for (int d = threadIdx.x; d < DD; d += 256) {
        float v;
        if (cnt > 0) {
            float sum = 0.f;
            for (int s = st; s < st + cnt; s++)
                sum += g_attnout[((size_t)b*SS + s)*DD + d];
            int cl = min(cnt, 1023);
            v = sum / (float)cnt + size_emb[(size_t)cl*DD + d];
        } else v = 0.f;
        v += pos_enc[(size_t)m*DD + d];
        __half h = __float2half_rn(v);
        drow[d]      = h;
        drow[DD + d] = __float2half_rn(v - __half2float(h));
    }
}

__global__ void ln_k(const float* __restrict__ gamma,
                     const float* __restrict__ beta,
                     float* __restrict__ out) {
    int r = blockIdx.x;
    const float* y = g_y + (size_t)r*DD;
    __shared__ float sh[256];
    float s = 0.f;
    for (int d = threadIdx.x; d < DD; d += 256) s += y[d];
    sh[threadIdx.x] = s; __syncthreads();
    for (int o = 128; o > 0; o >>= 1) {
        if (threadIdx.x < o) sh[threadIdx.x] += sh[threadIdx.x+o];
        __syncthreads();
    }
    float mu = sh[0] / (float)DD; __syncthreads();
    float v2 = 0.f;
    for (int d = threadIdx.x; d < DD; d += 256) { float t = y[d]-mu; v2 += t*t; }
    sh[threadIdx.x] = v2; __syncthreads();
    for (int o = 128; o > 0; o >>= 1) {
        if (threadIdx.x < o) sh[threadIdx.x] += sh[threadIdx.x+o];
        __syncthreads();
    }
    float inv = 1.0f / sqrtf(sh[0] / (float)DD + 1e-5f);
    for (int d = threadIdx.x; d < DD; d += 256)
        out[(size_t)r*DD + d] = (y[d] - mu) * inv * gamma[d] + beta[d];
}

// ---------------- host launchers ----------------
struct GemmArgs {
    const __half *A, *B;
    const float* bias;
    float* C;
    __half* C2;
    int M, N, K, lda, ldb, ldc, segoff;
    float oscale;
    int npA, npB, splitN;
    long long sAi, sAo, sBi, sBo, sCi, sCo, sbias;
    int innerN, batch;
};

template<int ACT, int OMODE, int BIG>
static void tg_launch(const GemmArgs& a) {
    dim3 grid(a.N/128, (a.M + 127)/128, a.batch);
    tgemm_k<ACT,OMODE,BIG><<<grid,256,TG_SMEM>>>(a.A, a.B, a.bias, a.C, a.C2,
        a.M, a.K, a.lda, a.ldb, a.ldc, a.segoff, a.oscale,
        a.npA, a.npB, a.splitN,
        a.sAi, a.sAo, a.sBi, a.sBo, a.sCi, a.sCo, a.sbias, a.innerN);
}

static void split2(const float* src, __half* dst, long long rows, int cols, float scale) {
    long long total = rows * cols;
    split2_k<<<(unsigned)((total + 255)/256), 256>>>(src, dst, total, cols, scale);
}

#define NPALL 3, 3, (1<<30)

extern "C" void kernel_launch(void* const* d_in, const int* in_sizes, int n_in,
                              void* d_out, int out_size) {
    const float* x         = (const float*)d_in[0];
    const float* Wp        = (const float*)d_in[1];
    const float* bp        = (const float*)d_in[2];
    const float* detW1     = (const float*)d_in[3];
    const float* detb1     = (const float*)d_in[4];
    const float* detW2     = (const float*)d_in[5];
    const float* detb2     = (const float*)d_in[6];
    const float* detW3     = (const float*)d_in[7];
    const float* detb3     = (const float*)d_in[8];
    const float* in_proj_w = (const float*)d_in[9];
    const float* in_proj_b = (const float*)d_in[10];
    const float* out_w     = (const float*)d_in[11];
    const float* out_b     = (const float*)d_in[12];
    const float* size_emb  = (const float*)d_in[13];
    const float* pos_enc   = (const float*)d_in[14];
    const float* procW1    = (const float*)d_in[15];
    const float* procb1    = (const float*)d_in[16];
    const float* procW2    = (const float*)d_in[17];
    const float* procb2    = (const float*)d_in[18];
    const float* ln_g      = (const float*)d_in[19];
    const float* ln_b      = (const float*)d_in[20];
    float* outp = (float*)d_out;

    cudaFuncSetAttribute(tgemm_k<0,0,0>, cudaFuncAttributeMaxDynamicSharedMemorySize, TG_SMEM);
    cudaFuncSetAttribute(tgemm_k<1,0,0>, cudaFuncAttributeMaxDynamicSharedMemorySize, TG_SMEM);
    cudaFuncSetAttribute(tgemm_k<1,1,0>, cudaFuncAttributeMaxDynamicSharedMemorySize, TG_SMEM);
    cudaFuncSetAttribute(tgemm_k<1,1,1>, cudaFuncAttributeMaxDynamicSharedMemorySize, TG_SMEM);

    void *p;
    cudaGetSymbolAddress(&p, g_xq);      float* xq      = (float*)p;
    cudaGetSymbolAddress(&p, g_bc);      float* bc      = (float*)p;
    cudaGetSymbolAddress(&p, g_h2);      float* h2      = (float*)p;
    cudaGetSymbolAddress(&p, g_attnout); float* attnout = (float*)p;
    cudaGetSymbolAddress(&p, g_y);       float* yb      = (float*)p;
    cudaGetSymbolAddress(&p, g_x2);      __half* x2     = (__half*)p;
    cudaGetSymbolAddress(&p, g_wc2);     __half* wc2    = (__half*)p;
    cudaGetSymbolAddress(&p, g_dW1_2);   __half* dW1_2  = (__half*)p;
    cudaGetSymbolAddress(&p, g_h1_2);    __half* h1_2   = (__half*)p;
    cudaGetSymbolAddress(&p, g_dW2_2);   __half* dW2_2  = (__half*)p;
    cudaGetSymbolAddress(&p, g_ctx2);    __half* ctx2   = (__half*)p;
    cudaGetSymbolAddress(&p, g_outw2);   __half* outw2  = (__half*)p;
    cudaGetSymbolAddress(&p, g_chunk2);  __half* chunk2 = (__half*)p;
    cudaGetSymbolAddress(&p, g_pw1_2);   __half* pw1_2  = (__half*)p;
    cudaGetSymbolAddress(&p, g_hproc2);  __half* hproc2 = (__half*)p;
    cudaGetSymbolAddress(&p, g_pw2_2);   __half* pw2_2  = (__half*)p;

    // ===== input splits (weights scaled by 64 to keep fp16 lo plane normal) =====
    split2(x, x2, NB*SS, DD, 1.0f);
    split2(Wp, wc2, DD, DD, WSCALE);                            // rows 0..1535 of combined W
    split2(in_proj_w, wc2 + (size_t)DD*2*DD, 3*DD, DD, WSCALE); // rows 1536..6143
    split2(detW1, dW1_2, 3*DD, 2*DD, WSCALE);
    split2(detW2, dW2_2, 3*(DD/2), DD, WSCALE);
    split2(out_w, outw2, DD, DD, WSCALE);
    split2(procW1, pw1_2, 2*DD, DD, WSCALE);
    split2(procW2, pw2_2, DD, 2*DD, WSCALE);
    biascat_k<<<(XQ + 255)/256, 256>>>(bp, in_proj_b);

    // ===== merged xling|qkv GEMM: 3 products for n<1536 (boundary), 2 for qkv =====
    { GemmArgs a = { x2, wc2, bc, xq, nullptr, NB*SS, XQ, DD, 2*DD, 2*DD, XQ, 0,
                     OSINV, 3, 2, DD, 0,0,0,0,0,0,0, 1, 1 };
      tg_launch<0,0,0>(a); }

    // ===== boundary path =====
    norm_k<<<NB*SS, 256>>>();
    cos_k<<<dim3(CS_TOT, NB), 256>>>();
    base_k<<<(NB*SM1 + 255)/256, 256>>>();
    // h1 = gelu(bi @ detW1[n]^T + b) -> 2-way split directly; A gathered from x2 (BIG=1)
    { GemmArgs a = { x2, dW1_2, detb1, nullptr, h1_2, ROWS_DET, DD, 2*DD,
                     2*DD, 2*2*DD, 2*DD, DD, OSINV, NPALL,
                     0, 0, (long long)DD*2*2*DD, 0,
                     (long long)ROWS_DET*2*DD, 0, DD, 3, 3 };
      tg_launch<1,1,1>(a); }
    // h2 = gelu(h1 @ detW2[n]^T + b) fp32
    { GemmArgs a = { h1_2, dW2_2, detb2, h2, nullptr, ROWS_DET, DD/2, DD,
                     2*DD, 2*DD, DD/2, 0, OSINV, NPALL,
                     (long long)ROWS_DET*2*DD, 0, (long long)(DD/2)*2*DD, 0,
                     (long long)ROWS_DET*(DD/2), 0, DD/2, 3, 3 };
      tg_launch<1,0,0>(a); }
    learned_final_k<<<ROWS_DET, 256>>>(detW3, detb3);
    seg_scan_k<<<NB, SS>>>();

    // ===== continuous path =====
    // fused segment attention (fp32) -> ctx2 (fp16 split)
    seg_attn_k<<<NB*SS*NH/8, 256>>>();
    // attn_out = ctx @ out_w^T + out_b
    { GemmArgs a = { ctx2, outw2, out_b, attnout, nullptr, NB*SS, DD, DD,
                     2*DD, 2*DD, DD, 0, OSINV, NPALL, 0,0,0,0,0,0,0, 1, 1 };
      tg_launch<0,0,0>(a); }
    chunk_k<<<dim3(MAXC, NB), 256>>>(size_emb, pos_enc);
    // hproc = gelu(chunk @ procW1^T + b) -> 2-way split directly
    { GemmArgs a = { chunk2, pw1_2, procb1, nullptr, hproc2, NB*MAXC, 2*DD, DD,
                     2*DD, 2*DD, 2*2*DD, 2*DD, OSINV, NPALL, 0,0,0,0,0,0,0, 1, 1 };
      tg_launch<1,1,0>(a); }
    // y = hproc @ procW2^T + b
    { GemmArgs a = { hproc2, pw2_2, procb2, yb, nullptr, NB*MAXC, DD, 2*DD,
                     2*2*DD, 2*2*DD, DD, 0, OSINV, NPALL, 0,0,0,0,0,0,0, 1, 1 };
      tg_launch<0,0,0>(a); }
    ln_k<<<NB*MAXC, 256>>>(ln_g, ln_b, outp);
}

// round 12
// speedup vs baseline: 1.1074x; 1.0489x over previous
#include <cuda_runtime.h>
#include <cuda_fp16.h>
#include <math.h>
#include <stdint.h>

// ---------------- problem constants ----------------
#define NB 4
#define SS 1024
#define DD 1536
#define NH 12
#define HDIM 128
#define MAXC 256
#define SM1 1023
#define ROWS_DET (NB*SM1)        // 4092
#define CS_TOT (1023+511+255)    // 1789
#define XQ 6144                  // combined xling|qkv row width
#define QOFF 1536                // qkv column offset in combined buffer

#define WSCALE 64.0f
#define OSINV  0.015625f         // 1/64

// ---------------- fp32 scratch ----------------
__device__ float g_xq[(size_t)NB*SS*XQ];       // [.,0:1536)=xling, [.,1536:6144)=qkv
__device__ float g_bc[XQ];                     // combined bias
__device__ float g_norm[NB*SS];
__device__ float g_cs[NB*CS_TOT];
__device__ float g_base[NB*SM1];
__device__ float g_h2[(size_t)3*ROWS_DET*(DD/2)];
__device__ float g_final[NB*SM1];
__device__ int   g_seg[NB*SS];
__device__ int   g_qlo[NB*SS];
__device__ int   g_qhi[NB*SS];
__device__ int   g_segstart[NB*MAXC];
__device__ int   g_segcount[NB*MAXC];
__device__ float g_attnout[(size_t)NB*SS*DD];
__device__ float g_y[(size_t)NB*MAXC*DD];

// ---------------- fp16 2-way split scratch [rows][2K] (hi|lo) ----------------
__device__ __half g_x2[(size_t)NB*SS*2*DD];
__device__ __half g_wc2[(size_t)XQ*2*DD];      // combined [Wp | in_proj_w] split
__device__ __half g_dW1_2[(size_t)3*DD*2*(2*DD)];
__device__ __half g_h1_2[(size_t)3*ROWS_DET*2*DD];
__device__ __half g_dW2_2[(size_t)3*(DD/2)*2*DD];
__device__ __half g_ctx2[(size_t)NB*SS*2*DD];
__device__ __half g_outw2[(size_t)DD*2*DD];
__device__ __half g_chunk2[(size_t)NB*MAXC*2*DD];
__device__ __half g_pw1_2[(size_t)2*DD*2*DD];
__device__ __half g_hproc2[(size_t)NB*MAXC*2*2*DD];
__device__ __half g_pw2_2[(size_t)DD*2*2*DD];

__device__ __forceinline__ float gelu_exact(float v) {
    return 0.5f * v * (1.0f + erff(v * 0.70710678118654752440f));
}
__device__ __forceinline__ uint32_t smem_u32(const void* p) {
    uint32_t a;
    asm("{ .reg .u64 t; cvta.to.shared.u64 t, %1; cvt.u32.u64 %0, t; }" : "=r"(a) : "l"(p));
    return a;
}

#define LDSM4(r0,r1,r2,r3,addr) \
    asm volatile("ldmatrix.sync.aligned.m8n8.x4.shared.b16 {%0,%1,%2,%3}, [%4];" \
        : "=r"(r0), "=r"(r1), "=r"(r2), "=r"(r3) : "r"(addr))

#define MMA16816(d, a, b0, b1) \
    asm volatile("mma.sync.aligned.m16n8k16.row.col.f32.f16.f16.f32 " \
        "{%0,%1,%2,%3},{%4,%5,%6,%7},{%8,%9},{%0,%1,%2,%3};" \
        : "+f"((d)[0]), "+f"((d)[1]), "+f"((d)[2]), "+f"((d)[3]) \
        : "r"((a)[0]), "r"((a)[1]), "r"((a)[2]), "r"((a)[3]), "r"(b0), "r"(b1))

#define CP_ASYNC16(dst, src, sz) \
    asm volatile("cp.async.ca.shared.global [%0], [%1], 16, %2;" :: "r"(dst), "l"(src), "r"(sz))
#define CP_COMMIT() asm volatile("cp.async.commit_group;" ::: "memory")
#define CP_WAIT1() asm volatile("cp.async.wait_group 1;" ::: "memory")
#define CP_WAIT0() asm volatile("cp.async.wait_group 0;" ::: "memory")

// ================= mma.sync fp16 split GEMM (2-stage, K64, 2 CTAs/SM) =================
// A[M][2K] (hi|lo), B[N][2K] (hi|lo).
// np = (n0 < splitN) ? npA : npB.
//   np=3: Ah.Bh + Ah.Bl + Al.Bh
//   np=2: Ah.Bh + Ah.Bl           (weights full precision, data fp16-truncated)
// BIG=1: A is g_x2; rows are bigrams (b,s); chunk selects x_s / x_{s+1}.
#define RSTRIDE 144
#define ATILE (128*RSTRIDE)        // 18432
#define BUFSZ (2*ATILE)            // 36864
#define TG_SMEM (2*BUFSZ)          // 73728

template<int ACT, int OMODE, int BIG>
__global__ void __launch_bounds__(256)
tgemm_k(const __half* __restrict__ A, const __half* __restrict__ B,
        const float* __restrict__ bias, float* __restrict__ C, __half* __restrict__ C2,
        int M, int K, int lda, int ldb, int ldc, int segoff, float oscale,
        int npA, int npB, int splitN,
        long long sAi, long long sAo, long long sBi, long long sBo,
        long long sCi, long long sCo, long long sbias, int innerN)
{
    const int segA_[3] = {0,0,1};
    const int segB_[3] = {0,1,0};
    extern __shared__ char smem[];
    uint32_t sb = smem_u32(smem);
    int tid = threadIdx.x;
    int z = blockIdx.z, zi = z % innerN, zo = z / innerN;
    if (!BIG) A += (size_t)(zi*sAi + zo*sAo);
    B += (size_t)(zi*sBi + zo*sBo);
    if (OMODE == 0) C  += (size_t)(zi*sCi + zo*sCo);
    else            C2 += (size_t)(zi*sCi + zo*sCo);
    int m0 = blockIdx.y * 128, n0 = blockIdx.x * 128;

    const int KPC = K >> 6;
    const int NP = (n0 < splitN) ? npA : npB;
    const int NC = NP * KPC;

    // per-thread A-load slots (row/col fixed across chunks)
    int arow_[4]; uint32_t asz_[4]; long long aoff_[4]; int ac_[4];
    #pragma unroll
    for (int i = 0; i < 4; i++) {
        int f = tid + (i << 8);
        int row = f >> 3, c = f & 7;
        int gr = m0 + row;
        int grc = gr < M ? gr : (M - 1);
        arow_[i] = row; ac_[i] = c;
        asz_[i] = gr < M ? 16u : 0u;
        if (BIG) {
            int b = grc / SM1, s = grc % SM1;
            aoff_[i] = (long long)(b*SS + s) * (2*DD);
        } else {
            aoff_[i] = (long long)grc * lda;
        }
    }

    auto issue = [&](int kc, int buf) {
        int p = kc / KPC;
        int k0 = (kc - p * KPC) << 6;
        uint32_t sA = sb + buf * BUFSZ;
        uint32_t sB = sA + ATILE;
        if (BIG) {
            int side = (k0 >= DD) ? 1 : 0;
            long long cofs = (long long)side*(2*DD) + segA_[p]*DD + (k0 - side*DD);
            #pragma unroll
            for (int i = 0; i < 4; i++) {
                const void* src = A + aoff_[i] + cofs + ac_[i] * 8;
                CP_ASYNC16(sA + arow_[i] * RSTRIDE + ac_[i] * 16, src, asz_[i]);
            }
        } else {
            const __half* Ap = A + (size_t)segA_[p] * K + k0;
            #pragma unroll
            for (int i = 0; i < 4; i++) {
                const void* src = Ap + aoff_[i] + ac_[i] * 8;
                CP_ASYNC16(sA + arow_[i] * RSTRIDE + ac_[i] * 16, src, asz_[i]);
            }
        }
        const __half* Bp = B + (size_t)segB_[p] * K + k0;
        #pragma unroll
        for (int i = 0; i < 4; i++) {
            int f = tid + (i << 8);
            int row = f >> 3, c = f & 7;
            const void* src = Bp + (size_t)(n0 + row) * ldb + c * 8;
            CP_ASYNC16(sB + row * RSTRIDE + c * 16, src, 16u);
        }
    };

    int lane = tid & 31, w = tid >> 5;
    int wm = w & 1, wn = w >> 1;
    uint32_t a_row = ((lane >> 3) & 1) * 8 + (lane & 7);
    uint32_t a_cs  = lane >> 4;
    uint32_t b_row = (lane >> 4) * 8 + (lane & 7);
    uint32_t b_cs  = (lane >> 3) & 1;

    float acc[4][4][4];
    #pragma unroll
    for (int i = 0; i < 4; i++)
        #pragma unroll
        for (int j = 0; j < 4; j++)
            #pragma unroll
            for (int r = 0; r < 4; r++) acc[i][j][r] = 0.f;

    issue(0, 0);
    CP_COMMIT();

    for (int kc = 0; kc < NC; kc++) {
        int cur = kc & 1;
        if (kc + 1 < NC) { issue(kc + 1, cur ^ 1); CP_COMMIT(); CP_WAIT1(); }
        else             { CP_WAIT0(); }
        __syncthreads();

        uint32_t sA = sb + cur * BUFSZ;
        uint32_t sB = sA + ATILE;
        #pragma unroll
        for (int ks = 0; ks < 4; ks++) {
            uint32_t av[4][4], bv[2][4];
            #pragma unroll
            for (int mt = 0; mt < 4; mt++) {
                uint32_t ad = sA + (wm*64 + mt*16 + a_row) * RSTRIDE + ((ks*2 + a_cs) << 4);
                LDSM4(av[mt][0], av[mt][1], av[mt][2], av[mt][3], ad);
            }
            #pragma unroll
            for (int bt = 0; bt < 2; bt++) {
                uint32_t bd = sB + (wn*32 + bt*16 + b_row) * RSTRIDE + ((ks*2 + b_cs) << 4);
                LDSM4(bv[bt][0], bv[bt][1], bv[bt][2], bv[bt][3], bd);
            }
            #pragma unroll
            for (int mt = 0; mt < 4; mt++)
                #pragma unroll
                for (int nt = 0; nt < 4; nt++) {
                    uint32_t b0 = bv[nt >> 1][(nt & 1) * 2];
                    uint32_t b1 = bv[nt >> 1][(nt & 1) * 2 + 1];
                    MMA16816(acc[mt][nt], av[mt], b0, b1);
                }
        }
        __syncthreads();
    }

    // ---- epilogue ----
    if (bias) bias += (size_t)z * (size_t)sbias;
    #pragma unroll
    for (int mt = 0; mt < 4; mt++) {
        int r0 = m0 + wm*64 + mt*16 + (lane >> 2);
        #pragma unroll
        for (int nt = 0; nt < 4; nt++) {
            int col = n0 + wn*32 + nt*8 + (lane & 3)*2;
            float bb0 = 0.f, bb1 = 0.f;
            if (bias) { bb0 = bias[col]; bb1 = bias[col+1]; }
            #pragma unroll
            for (int half_ = 0; half_ < 2; half_++) {
                int r = r0 + half_*8;
                if (r >= M) continue;
                float v0 = acc[mt][nt][half_*2]   * oscale + bb0;
                float v1 = acc[mt][nt][half_*2+1] * oscale + bb1;
                if (ACT == 1) { v0 = gelu_exact(v0); v1 = gelu_exact(v1); }
                if (OMODE == 0) {
                    *(float2*)(C + (size_t)r*ldc + col) = make_float2(v0, v1);
                } else {
                    __half* d = C2 + (size_t)r*ldc + col;
                    __half h0 = __float2half_rn(v0);
                    __half h1 = __float2half_rn(v1);
                    __half l0 = __float2half_rn(v0 - __half2float(h0));
                    __half l1 = __float2half_rn(v1 - __half2float(h1));
                    *(__half2*)(d)          = __halves2half2(h0, h1);
                    *(__half2*)(d + segoff) = __halves2half2(l0, l1);
                }
            }
        }
    }
}

// ================= vectorized split kernel (4 cols/thread, bit-identical math) =================
__global__ void split2v_k(const float* __restrict__ src, __half* __restrict__ dst,
                          long long total4, int C4, int C, float scale) {
    long long idx4 = (long long)blockIdx.x * 256 + threadIdx.x;
    if (idx4 >= total4) return;
    long long r = idx4 / C4;
    int c = (int)(idx4 - r * C4) * 4;
    float4 v = *(const float4*)(src + r * C + c);
    v.x *= scale; v.y *= scale; v.z *= scale; v.w *= scale;
    __half h0 = __float2half_rn(v.x), h1 = __float2half_rn(v.y);
    __half h2 = __float2half_rn(v.z), h3 = __float2half_rn(v.w);
    __half l0 = __float2half_rn(v.x - __half2float(h0));
    __half l1 = __float2half_rn(v.y - __half2float(h1));
    __half l2 = __float2half_rn(v.z - __half2float(h2));
    __half l3 = __float2half_rn(v.w - __half2float(h3));
    __half* d = dst + r * (2LL*C) + c;
    *(__half2*)(d)         = __halves2half2(h0, h1);
    *(__half2*)(d + 2)     = __halves2half2(h2, h3);
    *(__half2*)(d + C)     = __halves2half2(l0, l1);
    *(__half2*)(d + C + 2) = __halves2half2(l2, l3);
}

__global__ void biascat_k(const float* __restrict__ bp, const float* __restrict__ ipb) {
    int i = blockIdx.x * 256 + threadIdx.x;
    if (i < DD)      g_bc[i] = bp[i];
    else if (i < XQ) g_bc[i] = ipb[i - DD];
}

// ---------------- small kernels ----------------
__global__ void norm_k() {
    int r = blockIdx.x;
    const float* p = g_xq + (size_t)r * XQ;
    float ss = 0.f;
    for (int i = threadIdx.x; i < DD; i += 256) { float v = p[i]; ss += v*v; }
    __shared__ float sh[256];
    sh[threadIdx.x] = ss; __syncthreads();
    for (int o = 128; o > 0; o >>= 1) {
        if (threadIdx.x < o) sh[threadIdx.x] += sh[threadIdx.x + o];
        __syncthreads();
    }
    if (threadIdx.x == 0) g_norm[r] = fmaxf(sqrtf(sh[0]), 1e-8f);
}

__global__ void cos_k() {
    int b = blockIdx.y, t = blockIdx.x;
    int scale, i;
    if (t < 1023)      { scale = 1; i = t; }
    else if (t < 1534) { scale = 2; i = t - 1023; }
    else               { scale = 4; i = t - 1534; }
    int s0 = i * scale, s1 = s0 + scale;
    const float* a = g_xq + ((size_t)b*SS + s0) * XQ;
    const float* c = g_xq + ((size_t)b*SS + s1) * XQ;
    float d = 0.f;
    for (int j = threadIdx.x; j < DD; j += 256) d += a[j] * c[j];
    __shared__ float sh[256];
    sh[threadIdx.x] = d; __syncthreads();
    for (int o = 128; o > 0; o >>= 1) {
        if (threadIdx.x < o) sh[threadIdx.x] += sh[threadIdx.x + o];
        __syncthreads();
    }
    if (threadIdx.x == 0)
        g_cs[b*CS_TOT + t] = sh[0] / (g_norm[b*SS + s0] * g_norm[b*SS + s1]);
}

__global__ void base_k() {
    int idx = blockIdx.x * 256 + threadIdx.x;
    if (idx >= NB*SM1) return;
    int b = idx / SM1, j = idx % SM1;
    const int Ls[3]   = {1023, 511, 255};
    const int offs[3] = {0, 1023, 1534};
    float acc = 0.f;
    #pragma unroll
    for (int u = 0; u < 3; u++) {
        int L = Ls[u];
        float ratio = (float)((double)L / 1023.0);
        float src = ((float)j + 0.5f) * ratio - 0.5f;
        src = fminf(fmaxf(src, 0.0f), (float)(L - 1));
        int i0 = (int)floorf(src);
        int i1 = min(i0 + 1, L - 1);
        float w = src - (float)i0;
        const float* cs = g_cs + b*CS_TOT + offs[u];
        acc += cs[i0] * (1.0f - w) + cs[i1] * w;
    }
    g_base[idx] = 0.5f * (1.0f - acc / 3.0f);
}

__global__ void learned_final_k(const float* __restrict__ detW3,
                                const float* __restrict__ detb3) {
    int r = blockIdx.x;
    __shared__ float sh[256];
    __shared__ float sacc;
    if (threadIdx.x == 0) sacc = 0.f;
    for (int n = 0; n < 3; n++) {
        const float* h2p = g_h2 + ((size_t)n*ROWS_DET + r) * (DD/2);
        const float* w   = detW3 + n*(DD/2);
        float part = 0.f;
        for (int j = threadIdx.x; j < DD/2; j += 256) part += h2p[j] * w[j];
        __syncthreads();
        sh[threadIdx.x] = part; __syncthreads();
        for (int o = 128; o > 0; o >>= 1) {
            if (threadIdx.x < o) sh[threadIdx.x] += sh[threadIdx.x + o];
            __syncthreads();
        }
        if (threadIdx.x == 0) {
            float t = sh[0] + detb3[n];
            sacc += 1.0f / (1.0f + expf(-t));
        }
        __syncthreads();
    }
    if (threadIdx.x == 0)
        g_final[r] = 0.6f * g_base[r] + 0.4f * (sacc / 3.0f);
}

// parallel segmentation: integer scans (exact, order-independent)
__global__ void __launch_bounds__(SS)
seg_scan_k() {
    int b = blockIdx.x, t = threadIdx.x;
    __shared__ int sscan[SS];
    __shared__ int smax[SS];
    __shared__ int rmin[SS];
    float bv = (t == 0) ? 1.0f : g_final[b*SM1 + t - 1];
    int f = (t == 0) ? 1 : (bv > 0.5f ? 1 : 0);
    sscan[t] = f;
    smax[t]  = f ? t : -1;
    rmin[t]  = f ? t : SS;
    __syncthreads();
    for (int o = 1; o < SS; o <<= 1) {
        int vs = sscan[t];
        int vm = smax[t];
        int vr = rmin[t];
        int vs2 = (t >= o) ? sscan[t - o] : 0;
        int vm2 = (t >= o) ? smax[t - o]  : -1;
        int vr2 = (t + o < SS) ? rmin[t + o] : SS;
        __syncthreads();
        sscan[t] = vs + vs2;
        smax[t]  = max(vm, vm2);
        rmin[t]  = min(vr, vr2);
        __syncthreads();
    }
    int m = sscan[t] - 1;
    g_seg[b*SS + t] = m;
    g_qlo[b*SS + t] = smax[t];
    int hi = (t < SS - 1) ? rmin[t + 1] : SS;
    g_qhi[b*SS + t] = hi;
    if (t < MAXC) { g_segstart[b*MAXC + t] = 0; g_segcount[b*MAXC + t] = 0; }
    __syncthreads();
    if (f && m < MAXC) {
        g_segstart[b*MAXC + m] = t;
        g_segcount[b*MAXC + m] = hi - t;
    }
}

// fused segment attention: one warp per (b, s, h); fp32; writes fp16-split ctx
__global__ void __launch_bounds__(256)
seg_attn_k() {
    __shared__ float dots[8][SS];
    int w = threadIdx.x >> 5, lane = threadIdx.x & 31;
    int g = blockIdx.x * 8 + w;
    int h = g % NH;
    int s = (g / NH) & (SS - 1);
    int b = g / (NH * SS);
    int lo = g_qlo[b*SS + s], hi = g_qhi[b*SS + s];

    const float* qp = g_xq + ((size_t)(b*SS + s))*XQ + QOFF + h*HDIM + lane*4;
    float4 qv = *(const float4*)qp;
    const float scale = 0.088388347648318440550f;   // 1/sqrt(128)

    const float* kbase = g_xq + ((size_t)(b*SS))*XQ + QOFF + DD + h*HDIM + lane*4;
    float mx = -3.402823e38f;
    for (int k = lo; k < hi; k++) {
        float4 kv = *(const float4*)(kbase + (size_t)k*XQ);
        float d = qv.x*kv.x + qv.y*kv.y + qv.z*kv.z + qv.w*kv.w;
        #pragma unroll
        for (int o = 16; o > 0; o >>= 1) d += __shfl_xor_sync(0xffffffffu, d, o);
        d *= scale;
        if (lane == 0) dots[w][k - lo] = d;
        mx = fmaxf(mx, d);
    }
    __syncwarp();

    const float* vbase = g_xq + ((size_t)(b*SS))*XQ + QOFF + 2*DD + h*HDIM + lane*4;
    float4 acc = make_float4(0.f, 0.f, 0.f, 0.f);
    float sum = 0.f;
    for (int k = lo; k < hi; k++) {
        float e = expf(dots[w][k - lo] - mx);
        sum += e;
        float4 vv = *(const float4*)(vbase + (size_t)k*XQ);
        acc.x += e*vv.x; acc.y += e*vv.y; acc.z += e*vv.z; acc.w += e*vv.w;
    }
    float inv = 1.0f / sum;
    float c0 = acc.x*inv, c1 = acc.y*inv, c2 = acc.z*inv, c3 = acc.w*inv;

    __half* d = g_ctx2 + ((size_t)(b*SS + s))*(2*DD) + h*HDIM + lane*4;
    __half h0 = __float2half_rn(c0), h1 = __float2half_rn(c1);
    __half h2 = __float2half_rn(c2), h3 = __float2half_rn(c3);
    *(__half2*)(d)     = __halves2half2(h0, h1);
    *(__half2*)(d + 2) = __halves2half2(h2, h3);
    __half l0 = __float2half_rn(c0 - __half2float(h0));
    __half l1 = __float2half_rn(c1 - __half2float(h1));
    __half l2 = __float2half_rn(c2 - __half2float(h2));
    __half l3 = __float2half_rn(c3 - __half2float(h3));
    *(__half2*)(d + DD)     = __halves2half2(l0, l1);
    *(__half2*)(d + DD + 2) = __halves2half2(l2, l3);
}

// pooling + embeddings, writes 2-way fp16 split chunk directly
__global__ void chunk_k(const float* __restrict__ size_emb,
                        const float* __restrict__ pos_enc) {
    int m = blockIdx.x, b = blockIdx.y;
    int cnt = g_segcount[b*MAXC + m];
    int st  = g_segstart[b*MAXC + m];
    __half* drow = g_chunk2 + ((size_t)b*MAXC + m) * (2*DD);
    for (int d = threadIdx.x; d < DD; d += 256) {
        float v;
        if (cnt > 0) {
            float sum = 0.f;
            for (int s = st; s < st + cnt; s++)
                sum += g_attnout[((size_t)b*SS + s)*DD + d];
            int cl = min(cnt, 1023);
            v = sum / (float)cnt + size_emb[(size_t)cl*DD + d];
        } else v = 0.f;
        v += pos_enc[(size_t)m*DD + d];
        __half h = __float2half_rn(v);
        drow[d]      = h;
        drow[DD + d] = __float2half_rn(v - __half2float(h));
    }
}

__global__ void ln_k(const float* __restrict__ gamma,
                     const float* __restrict__ beta,
                     float* __restrict__ out) {
    int r = blockIdx.x;
    const float* y = g_y + (size_t)r*DD;
    __shared__ float sh[256];
    float s = 0.f;
    for (int d = threadIdx.x; d < DD; d += 256) s += y[d];
    sh[threadIdx.x] = s; __syncthreads();
    for (int o = 128; o > 0; o >>= 1) {
        if (threadIdx.x < o) sh[threadIdx.x] += sh[threadIdx.x+o];
        __syncthreads();
    }
    float mu = sh[0] / (float)DD; __syncthreads();
    float v2 = 0.f;
    for (int d = threadIdx.x; d < DD; d += 256) { float t = y[d]-mu; v2 += t*t; }
    sh[threadIdx.x] = v2; __syncthreads();
    for (int o = 128; o > 0; o >>= 1) {
        if (threadIdx.x < o) sh[threadIdx.x] += sh[threadIdx.x+o];
        __syncthreads();
    }
    float inv = 1.0f / sqrtf(sh[0] / (float)DD + 1e-5f);
    for (int d = threadIdx.x; d < DD; d += 256)
        out[(size_t)r*DD + d] = (y[d] - mu) * inv * gamma[d] + beta[d];
}

// ---------------- host launchers ----------------
struct GemmArgs {
    const __half *A, *B;
    const float* bias;
    float* C;
    __half* C2;
    int M, N, K, lda, ldb, ldc, segoff;
    float oscale;
    int npA, npB, splitN;
    long long sAi, sAo, sBi, sBo, sCi, sCo, sbias;
    int innerN, batch;
};

template<int ACT, int OMODE, int BIG>
static void tg_launch(const GemmArgs& a) {
    dim3 grid(a.N/128, (a.M + 127)/128, a.batch);
    tgemm_k<ACT,OMODE,BIG><<<grid,256,TG_SMEM>>>(a.A, a.B, a.bias, a.C, a.C2,
        a.M, a.K, a.lda, a.ldb, a.ldc, a.segoff, a.oscale,
        a.npA, a.npB, a.splitN,
        a.sAi, a.sAo, a.sBi, a.sBo, a.sCi, a.sCo, a.sbias, a.innerN);
}

static void split2(const float* src, __half* dst, long long rows, int cols, float scale) {
    long long total4 = rows * cols / 4;
    split2v_k<<<(unsigned)((total4 + 255)/256), 256>>>(src, dst, total4, cols/4, cols, scale);
}

#define NPALL 3, 3, (1<<30)

extern "C" void kernel_launch(void* const* d_in, const int* in_sizes, int n_in,
                              void* d_out, int out_size) {
    const float* x         = (const float*)d_in[0];
    const float* Wp        = (const float*)d_in[1];
    const float* bp        = (const float*)d_in[2];
    const float* detW1     = (const float*)d_in[3];
    const float* detb1     = (const float*)d_in[4];
    const float* detW2     = (const float*)d_in[5];
    const float* detb2     = (const float*)d_in[6];
    const float* detW3     = (const float*)d_in[7];
    const float* detb3     = (const float*)d_in[8];
    const float* in_proj_w = (const float*)d_in[9];
    const float* in_proj_b = (const float*)d_in[10];
    const float* out_w     = (const float*)d_in[11];
    const float* out_b     = (const float*)d_in[12];
    const float* size_emb  = (const float*)d_in[13];
    const float* pos_enc   = (const float*)d_in[14];
    const float* procW1    = (const float*)d_in[15];
    const float* procb1    = (const float*)d_in[16];
    const float* procW2    = (const float*)d_in[17];
    const float* procb2    = (const float*)d_in[18];
    const float* ln_g      = (const float*)d_in[19];
    const float* ln_b      = (const float*)d_in[20];
    float* outp = (float*)d_out;

    cudaFuncSetAttribute(tgemm_k<0,0,0>, cudaFuncAttributeMaxDynamicSharedMemorySize, TG_SMEM);
    cudaFuncSetAttribute(tgemm_k<1,0,0>, cudaFuncAttributeMaxDynamicSharedMemorySize, TG_SMEM);
    cudaFuncSetAttribute(tgemm_k<1,1,0>, cudaFuncAttributeMaxDynamicSharedMemorySize, TG_SMEM);
    cudaFuncSetAttribute(tgemm_k<1,1,1>, cudaFuncAttributeMaxDynamicSharedMemorySize, TG_SMEM);

    void *p;
    cudaGetSymbolAddress(&p, g_xq);      float* xq      = (float*)p;
    cudaGetSymbolAddress(&p, g_bc);      float* bc      = (float*)p;
    cudaGetSymbolAddress(&p, g_h2);      float* h2      = (float*)p;
    cudaGetSymbolAddress(&p, g_attnout); float* attnout = (float*)p;
    cudaGetSymbolAddress(&p, g_y);       float* yb      = (float*)p;
    cudaGetSymbolAddress(&p, g_x2);      __half* x2     = (__half*)p;
    cudaGetSymbolAddress(&p, g_wc2);     __half* wc2    = (__half*)p;
    cudaGetSymbolAddress(&p, g_dW1_2);   __half* dW1_2  = (__half*)p;
    cudaGetSymbolAddress(&p, g_h1_2);    __half* h1_2   = (__half*)p;
    cudaGetSymbolAddress(&p, g_dW2_2);   __half* dW2_2  = (__half*)p;
    cudaGetSymbolAddress(&p, g_ctx2);    __half* ctx2   = (__half*)p;
    cudaGetSymbolAddress(&p, g_outw2);   __half* outw2  = (__half*)p;
    cudaGetSymbolAddress(&p, g_chunk2);  __half* chunk2 = (__half*)p;
    cudaGetSymbolAddress(&p, g_pw1_2);   __half* pw1_2  = (__half*)p;
    cudaGetSymbolAddress(&p, g_hproc2);  __half* hproc2 = (__half*)p;
    cudaGetSymbolAddress(&p, g_pw2_2);   __half* pw2_2  = (__half*)p;

    // ===== input splits (weights scaled by 64 to keep fp16 lo plane normal) =====
    split2(x, x2, NB*SS, DD, 1.0f);
    split2(Wp, wc2, DD, DD, WSCALE);                            // rows 0..1535 of combined W
    split2(in_proj_w, wc2 + (size_t)DD*2*DD, 3*DD, DD, WSCALE); // rows 1536..6143
    split2(detW1, dW1_2, 3*DD, 2*DD, WSCALE);
    split2(detW2, dW2_2, 3*(DD/2), DD, WSCALE);
    split2(out_w, outw2, DD, DD, WSCALE);
    split2(procW1, pw1_2, 2*DD, DD, WSCALE);
    split2(procW2, pw2_2, DD, 2*DD, WSCALE);
    biascat_k<<<(XQ + 255)/256, 256>>>(bp, in_proj_b);

    // ===== merged xling|qkv GEMM: 3 products for n<1536 (boundary), 2 for qkv =====
    { GemmArgs a = { x2, wc2, bc, xq, nullptr, NB*SS, XQ, DD, 2*DD, 2*DD, XQ, 0,
                     OSINV, 3, 2, DD, 0,0,0,0,0,0,0, 1, 1 };
      tg_launch<0,0,0>(a); }

    // ===== boundary path =====
    norm_k<<<NB*SS, 256>>>();
    cos_k<<<dim3(CS_TOT, NB), 256>>>();
    base_k<<<(NB*SM1 + 255)/256, 256>>>();
    // h1 = gelu(bi @ detW1[n]^T + b) -> 2-way split directly; A gathered from x2 (BIG=1)
    { GemmArgs a = { x2, dW1_2, detb1, nullptr, h1_2, ROWS_DET, DD, 2*DD,
                     2*DD, 2*2*DD, 2*DD, DD, OSINV, NPALL,
                     0, 0, (long long)DD*2*2*DD, 0,
                     (long long)ROWS_DET*2*DD, 0, DD, 3, 3 };
      tg_launch<1,1,1>(a); }
    // h2 = gelu(h1 @ detW2[n]^T + b) fp32
    { GemmArgs a = { h1_2, dW2_2, detb2, h2, nullptr, ROWS_DET, DD/2, DD,
                     2*DD, 2*DD, DD/2, 0, OSINV, NPALL,
                     (long long)ROWS_DET*2*DD, 0, (long long)(DD/2)*2*DD, 0,
                     (long long)ROWS_DET*(DD/2), 0, DD/2, 3, 3 };
      tg_launch<1,0,0>(a); }
    learned_final_k<<<ROWS_DET, 256>>>(detW3, detb3);
    seg_scan_k<<<NB, SS>>>();

    // ===== continuous path =====
    // fused segment attention (fp32) -> ctx2 (fp16 split)
    seg_attn_k<<<NB*SS*NH/8, 256>>>();
    // attn_out = ctx @ out_w^T + out_b
    { GemmArgs a = { ctx2, outw2, out_b, attnout, nullptr, NB*SS, DD, DD,
                     2*DD, 2*DD, DD, 0, OSINV, NPALL, 0,0,0,0,0,0,0, 1, 1 };
      tg_launch<0,0,0>(a); }
    chunk_k<<<dim3(MAXC, NB), 256>>>(size_emb, pos_enc);
    // hproc = gelu(chunk @ procW1^T + b) -> 2-way split directly
    { GemmArgs a = { chunk2, pw1_2, procb1, nullptr, hproc2, NB*MAXC, 2*DD, DD,
                     2*DD, 2*DD, 2*2*DD, 2*DD, OSINV, NPALL, 0,0,0,0,0,0,0, 1, 1 };
      tg_launch<1,1,0>(a); }
    // y = hproc @ procW2^T + b
    { GemmArgs a = { hproc2, pw2_2, procb2, yb, nullptr, NB*MAXC, DD, 2*DD,
                     2*2*DD, 2*2*DD, DD, 0, OSINV, NPALL, 0,0,0,0,0,0,0, 1, 1 };
      tg_launch<0,0,0>(a); }
    ln_k<<<NB*MAXC, 256>>>(ln_g, ln_b, outp);
}

// round 13
// speedup vs baseline: 1.1828x; 1.0681x over previous
#include <cuda_runtime.h>
#include <cuda_fp16.h>
#include <math.h>
#include <stdint.h>

// ---------------- problem constants ----------------
#define NB 4
#define SS 1024
#define DD 1536
#define NH 12
#define HDIM 128
#define MAXC 256
#define SM1 1023
#define ROWS_DET (NB*SM1)        // 4092
#define CS_TOT (1023+511+255)    // 1789
#define XQ 6144                  // combined xling|qkv row width
#define QOFF 1536                // qkv column offset in combined buffer

#define WSCALE 64.0f
#define OSINV  0.015625f         // 1/64

// ---------------- fp32 scratch ----------------
__device__ float g_xq[(size_t)NB*SS*XQ];       // [.,0:1536)=xling, [.,1536:6144)=qkv
__device__ float g_bc[XQ];                     // combined bias
__device__ float g_norm[NB*SS];
__device__ float g_cs[NB*CS_TOT];
__device__ float g_base[NB*SM1];
__device__ float g_h2[(size_t)3*ROWS_DET*(DD/2)];
__device__ float g_final[NB*SM1];
__device__ int   g_seg[NB*SS];
__device__ int   g_qlo[NB*SS];
__device__ int   g_qhi[NB*SS];
__device__ int   g_segstart[NB*MAXC];
__device__ int   g_segcount[NB*MAXC];
__device__ float g_attnout[(size_t)NB*SS*DD];
__device__ float g_y[(size_t)NB*MAXC*DD];

// ---------------- fp16 2-way split scratch [rows][2K] (hi|lo) ----------------
__device__ __half g_x2[(size_t)NB*SS*2*DD];
__device__ __half g_wc2[(size_t)XQ*2*DD];      // combined [Wp | in_proj_w] split
__device__ __half g_dW1_2[(size_t)3*DD*2*(2*DD)];
__device__ __half g_h1_2[(size_t)3*ROWS_DET*2*DD];
__device__ __half g_dW2_2[(size_t)3*(DD/2)*2*DD];
__device__ __half g_ctx2[(size_t)NB*SS*2*DD];
__device__ __half g_outw2[(size_t)DD*2*DD];
__device__ __half g_chunk2[(size_t)NB*MAXC*2*DD];
__device__ __half g_pw1_2[(size_t)2*DD*2*DD];
__device__ __half g_hproc2[(size_t)NB*MAXC*2*2*DD];
__device__ __half g_pw2_2[(size_t)DD*2*2*DD];

__device__ __forceinline__ float gelu_exact(float v) {
    return 0.5f * v * (1.0f + erff(v * 0.70710678118654752440f));
}
__device__ __forceinline__ uint32_t smem_u32(const void* p) {
    uint32_t a;
    asm("{ .reg .u64 t; cvta.to.shared.u64 t, %1; cvt.u32.u64 %0, t; }" : "=r"(a) : "l"(p));
    return a;
}

#define LDSM4(r0,r1,r2,r3,addr) \
    asm volatile("ldmatrix.sync.aligned.m8n8.x4.shared.b16 {%0,%1,%2,%3}, [%4];" \
        : "=r"(r0), "=r"(r1), "=r"(r2), "=r"(r3) : "r"(addr))

#define MMA16816(d, a, b0, b1) \
    asm volatile("mma.sync.aligned.m16n8k16.row.col.f32.f16.f16.f32 " \
        "{%0,%1,%2,%3},{%4,%5,%6,%7},{%8,%9},{%0,%1,%2,%3};" \
        : "+f"((d)[0]), "+f"((d)[1]), "+f"((d)[2]), "+f"((d)[3]) \
        : "r"((a)[0]), "r"((a)[1]), "r"((a)[2]), "r"((a)[3]), "r"(b0), "r"(b1))

#define CP_ASYNC16(dst, src, sz) \
    asm volatile("cp.async.ca.shared.global [%0], [%1], 16, %2;" :: "r"(dst), "l"(src), "r"(sz))
#define CP_COMMIT() asm volatile("cp.async.commit_group;" ::: "memory")
#define CP_WAIT1() asm volatile("cp.async.wait_group 1;" ::: "memory")
#define CP_WAIT0() asm volatile("cp.async.wait_group 0;" ::: "memory")

// ================= mma.sync fp16 split GEMM (2-stage, K64, 2 CTAs/SM) =================
// A[M][2K] (hi|lo), B[N][2K] (hi|lo).
// np = (n0 < splitN) ? npA : npB.
//   np=3: Ah.Bh + Ah.Bl + Al.Bh
//   np=2: Ah.Bh + Ah.Bl           (weights full precision, data fp16-truncated)
// BIG=1: A is g_x2; rows are bigrams (b,s); chunk selects x_s / x_{s+1}.
#define RSTRIDE 144
#define ATILE (128*RSTRIDE)        // 18432
#define BUFSZ (2*ATILE)            // 36864
#define TG_SMEM (2*BUFSZ)          // 73728

template<int ACT, int OMODE, int BIG>
__global__ void __launch_bounds__(256)
tgemm_k(const __half* __restrict__ A, const __half* __restrict__ B,
        const float* __restrict__ bias, float* __restrict__ C, __half* __restrict__ C2,
        int M, int K, int lda, int ldb, int ldc, int segoff, float oscale,
        int npA, int npB, int splitN,
        long long sAi, long long sAo, long long sBi, long long sBo,
        long long sCi, long long sCo, long long sbias, int innerN)
{
    const int segA_[3] = {0,0,1};
    const int segB_[3] = {0,1,0};
    extern __shared__ char smem[];
    uint32_t sb = smem_u32(smem);
    int tid = threadIdx.x;
    int z = blockIdx.z, zi = z % innerN, zo = z / innerN;
    if (!BIG) A += (size_t)(zi*sAi + zo*sAo);
    B += (size_t)(zi*sBi + zo*sBo);
    if (OMODE == 0) C  += (size_t)(zi*sCi + zo*sCo);
    else            C2 += (size_t)(zi*sCi + zo*sCo);
    int m0 = blockIdx.y * 128, n0 = blockIdx.x * 128;

    const int KPC = K >> 6;
    const int NP = (n0 < splitN) ? npA : npB;
    const int NC = NP * KPC;

    // per-thread A-load slots (row/col fixed across chunks)
    int arow_[4]; uint32_t asz_[4]; long long aoff_[4]; int ac_[4];
    #pragma unroll
    for (int i = 0; i < 4; i++) {
        int f = tid + (i << 8);
        int row = f >> 3, c = f & 7;
        int gr = m0 + row;
        int grc = gr < M ? gr : (M - 1);
        arow_[i] = row; ac_[i] = c;
        asz_[i] = gr < M ? 16u : 0u;
        if (BIG) {
            int b = grc / SM1, s = grc % SM1;
            aoff_[i] = (long long)(b*SS + s) * (2*DD);
        } else {
            aoff_[i] = (long long)grc * lda;
        }
    }

    auto issue = [&](int kc, int buf) {
        int p = kc / KPC;
        int k0 = (kc - p * KPC) << 6;
        uint32_t sA = sb + buf * BUFSZ;
        uint32_t sB = sA + ATILE;
        if (BIG) {
            int side = (k0 >= DD) ? 1 : 0;
            long long cofs = (long long)side*(2*DD) + segA_[p]*DD + (k0 - side*DD);
            #pragma unroll
            for (int i = 0; i < 4; i++) {
                const void* src = A + aoff_[i] + cofs + ac_[i] * 8;
                CP_ASYNC16(sA + arow_[i] * RSTRIDE + ac_[i] * 16, src, asz_[i]);
            }
        } else {
            const __half* Ap = A + (size_t)segA_[p] * K + k0;
            #pragma unroll
            for (int i = 0; i < 4; i++) {
                const void* src = Ap + aoff_[i] + ac_[i] * 8;
                CP_ASYNC16(sA + arow_[i] * RSTRIDE + ac_[i] * 16, src, asz_[i]);
            }
        }
        const __half* Bp = B + (size_t)segB_[p] * K + k0;
        #pragma unroll
        for (int i = 0; i < 4; i++) {
            int f = tid + (i << 8);
            int row = f >> 3, c = f & 7;
            const void* src = Bp + (size_t)(n0 + row) * ldb + c * 8;
            CP_ASYNC16(sB + row * RSTRIDE + c * 16, src, 16u);
        }
    };

    int lane = tid & 31, w = tid >> 5;
    int wm = w & 1, wn = w >> 1;
    uint32_t a_row = ((lane >> 3) & 1) * 8 + (lane & 7);
    uint32_t a_cs  = lane >> 4;
    uint32_t b_row = (lane >> 4) * 8 + (lane & 7);
    uint32_t b_cs  = (lane >> 3) & 1;

    float acc[4][4][4];
    #pragma unroll
    for (int i = 0; i < 4; i++)
        #pragma unroll
        for (int j = 0; j < 4; j++)
            #pragma unroll
            for (int r = 0; r < 4; r++) acc[i][j][r] = 0.f;

    issue(0, 0);
    CP_COMMIT();

    for (int kc = 0; kc < NC; kc++) {
        int cur = kc & 1;
        if (kc + 1 < NC) { issue(kc + 1, cur ^ 1); CP_COMMIT(); CP_WAIT1(); }
        else             { CP_WAIT0(); }
        __syncthreads();

        uint32_t sA = sb + cur * BUFSZ;
        uint32_t sB = sA + ATILE;
        #pragma unroll
        for (int ks = 0; ks < 4; ks++) {
            uint32_t av[4][4], bv[2][4];
            #pragma unroll
            for (int mt = 0; mt < 4; mt++) {
                uint32_t ad = sA + (wm*64 + mt*16 + a_row) * RSTRIDE + ((ks*2 + a_cs) << 4);
                LDSM4(av[mt][0], av[mt][1], av[mt][2], av[mt][3], ad);
            }
            #pragma unroll
            for (int bt = 0; bt < 2; bt++) {
                uint32_t bd = sB + (wn*32 + bt*16 + b_row) * RSTRIDE + ((ks*2 + b_cs) << 4);
                LDSM4(bv[bt][0], bv[bt][1], bv[bt][2], bv[bt][3], bd);
            }
            #pragma unroll
            for (int mt = 0; mt < 4; mt++)
                #pragma unroll
                for (int nt = 0; nt < 4; nt++) {
                    uint32_t b0 = bv[nt >> 1][(nt & 1) * 2];
                    uint32_t b1 = bv[nt >> 1][(nt & 1) * 2 + 1];
                    MMA16816(acc[mt][nt], av[mt], b0, b1);
                }
        }
        __syncthreads();
    }

    // ---- epilogue ----
    if (bias) bias += (size_t)z * (size_t)sbias;
    #pragma unroll
    for (int mt = 0; mt < 4; mt++) {
        int r0 = m0 + wm*64 + mt*16 + (lane >> 2);
        #pragma unroll
        for (int nt = 0; nt < 4; nt++) {
            int col = n0 + wn*32 + nt*8 + (lane & 3)*2;
            float bb0 = 0.f, bb1 = 0.f;
            if (bias) { bb0 = bias[col]; bb1 = bias[col+1]; }
            #pragma unroll
            for (int half_ = 0; half_ < 2; half_++) {
                int r = r0 + half_*8;
                if (r >= M) continue;
                float v0 = acc[mt][nt][half_*2]   * oscale + bb0;
                float v1 = acc[mt][nt][half_*2+1] * oscale + bb1;
                if (ACT == 1) { v0 = gelu_exact(v0); v1 = gelu_exact(v1); }
                if (OMODE == 0) {
                    *(float2*)(C + (size_t)r*ldc + col) = make_float2(v0, v1);
                } else {
                    __half* d = C2 + (size_t)r*ldc + col;
                    __half h0 = __float2half_rn(v0);
                    __half h1 = __float2half_rn(v1);
                    __half l0 = __float2half_rn(v0 - __half2float(h0));
                    __half l1 = __float2half_rn(v1 - __half2float(h1));
                    *(__half2*)(d)          = __halves2half2(h0, h1);
                    *(__half2*)(d + segoff) = __halves2half2(l0, l1);
                }
            }
        }
    }
}

// ================= vectorized split kernel (4 cols/thread, bit-identical math) =================
__global__ void split2v_k(const float* __restrict__ src, __half* __restrict__ dst,
                          long long total4, int C4, int C, float scale) {
    long long idx4 = (long long)blockIdx.x * 256 + threadIdx.x;
    if (idx4 >= total4) return;
    long long r = idx4 / C4;
    int c = (int)(idx4 - r * C4) * 4;
    float4 v = *(const float4*)(src + r * C + c);
    v.x *= scale; v.y *= scale; v.z *= scale; v.w *= scale;
    __half h0 = __float2half_rn(v.x), h1 = __float2half_rn(v.y);
    __half h2 = __float2half_rn(v.z), h3 = __float2half_rn(v.w);
    __half l0 = __float2half_rn(v.x - __half2float(h0));
    __half l1 = __float2half_rn(v.y - __half2float(h1));
    __half l2 = __float2half_rn(v.z - __half2float(h2));
    __half l3 = __float2half_rn(v.w - __half2float(h3));
    __half* d = dst + r * (2LL*C) + c;
    *(__half2*)(d)         = __halves2half2(h0, h1);
    *(__half2*)(d + 2)     = __halves2half2(h2, h3);
    *(__half2*)(d + C)     = __halves2half2(l0, l1);
    *(__half2*)(d + C + 2) = __halves2half2(l2, l3);
}

__global__ void biascat_k(const float* __restrict__ bp, const float* __restrict__ ipb) {
    int i = blockIdx.x * 256 + threadIdx.x;
    if (i < DD)      g_bc[i] = bp[i];
    else if (i < XQ) g_bc[i] = ipb[i - DD];
}

// ---------------- small kernels ----------------
__global__ void norm_k() {
    int r = blockIdx.x;
    const float* p = g_xq + (size_t)r * XQ;
    float ss = 0.f;
    for (int i = threadIdx.x; i < DD; i += 256) { float v = p[i]; ss += v*v; }
    __shared__ float sh[256];
    sh[threadIdx.x] = ss; __syncthreads();
    for (int o = 128; o > 0; o >>= 1) {
        if (threadIdx.x < o) sh[threadIdx.x] += sh[threadIdx.x + o];
        __syncthreads();
    }
    if (threadIdx.x == 0) g_norm[r] = fmaxf(sqrtf(sh[0]), 1e-8f);
}

__global__ void cos_k() {
    int b = blockIdx.y, t = blockIdx.x;
    int scale, i;
    if (t < 1023)      { scale = 1; i = t; }
    else if (t < 1534) { scale = 2; i = t - 1023; }
    else               { scale = 4; i = t - 1534; }
    int s0 = i * scale, s1 = s0 + scale;
    const float* a = g_xq + ((size_t)b*SS + s0) * XQ;
    const float* c = g_xq + ((size_t)b*SS + s1) * XQ;
    float d = 0.f;
    for (int j = threadIdx.x; j < DD; j += 256) d += a[j] * c[j];
    __shared__ float sh[256];
    sh[threadIdx.x] = d; __syncthreads();
    for (int o = 128; o > 0; o >>= 1) {
        if (threadIdx.x < o) sh[threadIdx.x] += sh[threadIdx.x + o];
        __syncthreads();
    }
    if (threadIdx.x == 0)
        g_cs[b*CS_TOT + t] = sh[0] / (g_norm[b*SS + s0] * g_norm[b*SS + s1]);
}

__global__ void base_k() {
    int idx = blockIdx.x * 256 + threadIdx.x;
    if (idx >= NB*SM1) return;
    int b = idx / SM1, j = idx % SM1;
    const int Ls[3]   = {1023, 511, 255};
    const int offs[3] = {0, 1023, 1534};
    float acc = 0.f;
    #pragma unroll
    for (int u = 0; u < 3; u++) {
        int L = Ls[u];
        float ratio = (float)((double)L / 1023.0);
        float src = ((float)j + 0.5f) * ratio - 0.5f;
        src = fminf(fmaxf(src, 0.0f), (float)(L - 1));
        int i0 = (int)floorf(src);
        int i1 = min(i0 + 1, L - 1);
        float w = src - (float)i0;
        const float* cs = g_cs + b*CS_TOT + offs[u];
        acc += cs[i0] * (1.0f - w) + cs[i1] * w;
    }
    g_base[idx] = 0.5f * (1.0f - acc / 3.0f);
}

__global__ void learned_final_k(const float* __restrict__ detW3,
                                const float* __restrict__ detb3) {
    int r = blockIdx.x;
    __shared__ float sh[256];
    __shared__ float sacc;
    if (threadIdx.x == 0) sacc = 0.f;
    for (int n = 0; n < 3; n++) {
        const float* h2p = g_h2 + ((size_t)n*ROWS_DET + r) * (DD/2);
        const float* w   = detW3 + n*(DD/2);
        float part = 0.f;
        for (int j = threadIdx.x; j < DD/2; j += 256) part += h2p[j] * w[j];
        __syncthreads();
        sh[threadIdx.x] = part; __syncthreads();
        for (int o = 128; o > 0; o >>= 1) {
            if (threadIdx.x < o) sh[threadIdx.x] += sh[threadIdx.x + o];
            __syncthreads();
        }
        if (threadIdx.x == 0) {
            float t = sh[0] + detb3[n];
            sacc += 1.0f / (1.0f + expf(-t));
        }
        __syncthreads();
    }
    if (threadIdx.x == 0)
        g_final[r] = 0.6f * g_base[r] + 0.4f * (sacc / 3.0f);
}

// parallel segmentation: integer scans (exact, order-independent)
__global__ void __launch_bounds__(SS)
seg_scan_k() {
    int b = blockIdx.x, t = threadIdx.x;
    __shared__ int sscan[SS];
    __shared__ int smax[SS];
    __shared__ int rmin[SS];
    float bv = (t == 0) ? 1.0f : g_final[b*SM1 + t - 1];
    int f = (t == 0) ? 1 : (bv > 0.5f ? 1 : 0);
    sscan[t] = f;
    smax[t]  = f ? t : -1;
    rmin[t]  = f ? t : SS;
    __syncthreads();
    for (int o = 1; o < SS; o <<= 1) {
        int vs = sscan[t];
        int vm = smax[t];
        int vr = rmin[t];
        int vs2 = (t >= o) ? sscan[t - o] : 0;
        int vm2 = (t >= o) ? smax[t - o]  : -1;
        int vr2 = (t + o < SS) ? rmin[t + o] : SS;
        __syncthreads();
        sscan[t] = vs + vs2;
        smax[t]  = max(vm, vm2);
        rmin[t]  = min(vr, vr2);
        __syncthreads();
    }
    int m = sscan[t] - 1;
    g_seg[b*SS + t] = m;
    g_qlo[b*SS + t] = smax[t];
    int hi = (t < SS - 1) ? rmin[t + 1] : SS;
    g_qhi[b*SS + t] = hi;
    if (t < MAXC) { g_segstart[b*MAXC + t] = 0; g_segcount[b*MAXC + t] = 0; }
    __syncthreads();
    if (f && m < MAXC) {
        g_segstart[b*MAXC + m] = t;
        g_segcount[b*MAXC + m] = hi - t;
    }
}

// fused segment attention: one warp per (b, s, h); fp32; writes fp16-split ctx
__global__ void __launch_bounds__(256)
seg_attn_k() {
    __shared__ float dots[8][SS];
    int w = threadIdx.x >> 5, lane = threadIdx.x & 31;
    int g = blockIdx.x * 8 + w;
    int h = g % NH;
    int s = (g / NH) & (SS - 1);
    int b = g / (NH * SS);
    int lo = g_qlo[b*SS + s], hi = g_qhi[b*SS + s];

    const float* qp = g_xq + ((size_t)(b*SS + s))*XQ + QOFF + h*HDIM + lane*4;
    float4 qv = *(const float4*)qp;
    const float scale = 0.088388347648318440550f;   // 1/sqrt(128)

    const float* kbase = g_xq + ((size_t)(b*SS))*XQ + QOFF + DD + h*HDIM + lane*4;
    float mx = -3.402823e38f;
    for (int k = lo; k < hi; k++) {
        float4 kv = *(const float4*)(kbase + (size_t)k*XQ);
        float d = qv.x*kv.x + qv.y*kv.y + qv.z*kv.z + qv.w*kv.w;
        #pragma unroll
        for (int o = 16; o > 0; o >>= 1) d += __shfl_xor_sync(0xffffffffu, d, o);
        d *= scale;
        if (lane == 0) dots[w][k - lo] = d;
        mx = fmaxf(mx, d);
    }
    __syncwarp();

    const float* vbase = g_xq + ((size_t)(b*SS))*XQ + QOFF + 2*DD + h*HDIM + lane*4;
    float4 acc = make_float4(0.f, 0.f, 0.f, 0.f);
    float sum = 0.f;
    for (int k = lo; k < hi; k++) {
        float e = expf(dots[w][k - lo] - mx);
        sum += e;
        float4 vv = *(const float4*)(vbase + (size_t)k*XQ);
        acc.x += e*vv.x; acc.y += e*vv.y; acc.z += e*vv.z; acc.w += e*vv.w;
    }
    float inv = 1.0f / sum;
    float c0 = acc.x*inv, c1 = acc.y*inv, c2 = acc.z*inv, c3 = acc.w*inv;

    __half* d = g_ctx2 + ((size_t)(b*SS + s))*(2*DD) + h*HDIM + lane*4;
    __half h0 = __float2half_rn(c0), h1 = __float2half_rn(c1);
    __half h2 = __float2half_rn(c2), h3 = __float2half_rn(c3);
    *(__half2*)(d)     = __halves2half2(h0, h1);
    *(__half2*)(d + 2) = __halves2half2(h2, h3);
    __half l0 = __float2half_rn(c0 - __half2float(h0));
    __half l1 = __float2half_rn(c1 - __half2float(h1));
    __half l2 = __float2half_rn(c2 - __half2float(h2));
    __half l3 = __float2half_rn(c3 - __half2float(h3));
    *(__half2*)(d + DD)     = __halves2half2(l0, l1);
    *(__half2*)(d + DD + 2) = __halves2half2(l2, l3);
}

// pooling + embeddings, writes 2-way fp16 split chunk directly
__global__ void chunk_k(const float* __restrict__ size_emb,
                        const float* __restrict__ pos_enc) {
    int m = blockIdx.x, b = blockIdx.y;
    int cnt = g_segcount[b*MAXC + m];
    int st  = g_segstart[b*MAXC + m];
    __half* drow = g_chunk2 + ((size_t)b*MAXC + m) * (2*DD);
    for (int d = threadIdx.x; d < DD; d += 256) {
        float v;
        if (cnt > 0) {
            float sum = 0.f;
            for (int s = st; s < st + cnt; s++)
                sum += g_attnout[((size_t)b*SS + s)*DD + d];
            int cl = min(cnt, 1023);
            v = sum / (float)cnt + size_emb[(size_t)cl*DD + d];
        } else v = 0.f;
        v += pos_enc[(size_t)m*DD + d];
        __half h = __float2half_rn(v);
        drow[d]      = h;
        drow[DD + d] = __float2half_rn(v - __half2float(h));
    }
}

__global__ void ln_k(const float* __restrict__ gamma,
                     const float* __restrict__ beta,
                     float* __restrict__ out) {
    int r = blockIdx.x;
    const float* y = g_y + (size_t)r*DD;
    __shared__ float sh[256];
    float s = 0.f;
    for (int d = threadIdx.x; d < DD; d += 256) s += y[d];
    sh[threadIdx.x] = s; __syncthreads();
    for (int o = 128; o > 0; o >>= 1) {
        if (threadIdx.x < o) sh[threadIdx.x] += sh[threadIdx.x+o];
        __syncthreads();
    }
    float mu = sh[0] / (float)DD; __syncthreads();
    float v2 = 0.f;
    for (int d = threadIdx.x; d < DD; d += 256) { float t = y[d]-mu; v2 += t*t; }
    sh[threadIdx.x] = v2; __syncthreads();
    for (int o = 128; o > 0; o >>= 1) {
        if (threadIdx.x < o) sh[threadIdx.x] += sh[threadIdx.x+o];
        __syncthreads();
    }
    float inv = 1.0f / sqrtf(sh[0] / (float)DD + 1e-5f);
    for (int d = threadIdx.x; d < DD; d += 256)
        out[(size_t)r*DD + d] = (y[d] - mu) * inv * gamma[d] + beta[d];
}

// ---------------- host launchers ----------------
struct GemmArgs {
    const __half *A, *B;
    const float* bias;
    float* C;
    __half* C2;
    int M, N, K, lda, ldb, ldc, segoff;
    float oscale;
    int npA, npB, splitN;
    long long sAi, sAo, sBi, sBo, sCi, sCo, sbias;
    int innerN, batch;
};

template<int ACT, int OMODE, int BIG>
static void tg_launch(const GemmArgs& a) {
    dim3 grid(a.N/128, (a.M + 127)/128, a.batch);
    tgemm_k<ACT,OMODE,BIG><<<grid,256,TG_SMEM>>>(a.A, a.B, a.bias, a.C, a.C2,
        a.M, a.K, a.lda, a.ldb, a.ldc, a.segoff, a.oscale,
        a.npA, a.npB, a.splitN,
        a.sAi, a.sAo, a.sBi, a.sBo, a.sCi, a.sCo, a.sbias, a.innerN);
}

static void split2(const float* src, __half* dst, long long rows, int cols, float scale) {
    long long total4 = rows * cols / 4;
    split2v_k<<<(unsigned)((total4 + 255)/256), 256>>>(src, dst, total4, cols/4, cols, scale);
}

#define NP3 3, 3, (1<<30)
#define NP2 2, 2, (1<<30)

extern "C" void kernel_launch(void* const* d_in, const int* in_sizes, int n_in,
                              void* d_out, int out_size) {
    const float* x         = (const float*)d_in[0];
    const float* Wp        = (const float*)d_in[1];
    const float* bp        = (const float*)d_in[2];
    const float* detW1     = (const float*)d_in[3];
    const float* detb1     = (const float*)d_in[4];
    const float* detW2     = (const float*)d_in[5];
    const float* detb2     = (const float*)d_in[6];
    const float* detW3     = (const float*)d_in[7];
    const float* detb3     = (const float*)d_in[8];
    const float* in_proj_w = (const float*)d_in[9];
    const float* in_proj_b = (const float*)d_in[10];
    const float* out_w     = (const float*)d_in[11];
    const float* out_b     = (const float*)d_in[12];
    const float* size_emb  = (const float*)d_in[13];
    const float* pos_enc   = (const float*)d_in[14];
    const float* procW1    = (const float*)d_in[15];
    const float* procb1    = (const float*)d_in[16];
    const float* procW2    = (const float*)d_in[17];
    const float* procb2    = (const float*)d_in[18];
    const float* ln_g      = (const float*)d_in[19];
    const float* ln_b      = (const float*)d_in[20];
    float* outp = (float*)d_out;

    cudaFuncSetAttribute(tgemm_k<0,0,0>, cudaFuncAttributeMaxDynamicSharedMemorySize, TG_SMEM);
    cudaFuncSetAttribute(tgemm_k<1,0,0>, cudaFuncAttributeMaxDynamicSharedMemorySize, TG_SMEM);
    cudaFuncSetAttribute(tgemm_k<1,1,0>, cudaFuncAttributeMaxDynamicSharedMemorySize, TG_SMEM);
    cudaFuncSetAttribute(tgemm_k<1,1,1>, cudaFuncAttributeMaxDynamicSharedMemorySize, TG_SMEM);

    void *p;
    cudaGetSymbolAddress(&p, g_xq);      float* xq      = (float*)p;
    cudaGetSymbolAddress(&p, g_bc);      float* bc      = (float*)p;
    cudaGetSymbolAddress(&p, g_h2);      float* h2      = (float*)p;
    cudaGetSymbolAddress(&p, g_attnout); float* attnout = (float*)p;
    cudaGetSymbolAddress(&p, g_y);       float* yb      = (float*)p;
    cudaGetSymbolAddress(&p, g_x2);      __half* x2     = (__half*)p;
    cudaGetSymbolAddress(&p, g_wc2);     __half* wc2    = (__half*)p;
    cudaGetSymbolAddress(&p, g_dW1_2);   __half* dW1_2  = (__half*)p;
    cudaGetSymbolAddress(&p, g_h1_2);    __half* h1_2   = (__half*)p;
    cudaGetSymbolAddress(&p, g_dW2_2);   __half* dW2_2  = (__half*)p;
    cudaGetSymbolAddress(&p, g_ctx2);    __half* ctx2   = (__half*)p;
    cudaGetSymbolAddress(&p, g_outw2);   __half* outw2  = (__half*)p;
    cudaGetSymbolAddress(&p, g_chunk2);  __half* chunk2 = (__half*)p;
    cudaGetSymbolAddress(&p, g_pw1_2);   __half* pw1_2  = (__half*)p;
    cudaGetSymbolAddress(&p, g_hproc2);  __half* hproc2 = (__half*)p;
    cudaGetSymbolAddress(&p, g_pw2_2);   __half* pw2_2  = (__half*)p;

    // ===== input splits (weights scaled by 64 to keep fp16 lo plane normal) =====
    split2(x, x2, NB*SS, DD, 1.0f);
    split2(Wp, wc2, DD, DD, WSCALE);                            // rows 0..1535 of combined W
    split2(in_proj_w, wc2 + (size_t)DD*2*DD, 3*DD, DD, WSCALE); // rows 1536..6143
    split2(detW1, dW1_2, 3*DD, 2*DD, WSCALE);
    split2(detW2, dW2_2, 3*(DD/2), DD, WSCALE);
    split2(out_w, outw2, DD, DD, WSCALE);
    split2(procW1, pw1_2, 2*DD, DD, WSCALE);
    split2(procW2, pw2_2, DD, 2*DD, WSCALE);
    biascat_k<<<(XQ + 255)/256, 256>>>(bp, in_proj_b);

    // ===== merged xling|qkv GEMM: 3 products for n<1536 (boundary), 2 for qkv =====
    { GemmArgs a = { x2, wc2, bc, xq, nullptr, NB*SS, XQ, DD, 2*DD, 2*DD, XQ, 0,
                     OSINV, 3, 2, DD, 0,0,0,0,0,0,0, 1, 1 };
      tg_launch<0,0,0>(a); }

    // ===== boundary path (np=3 everywhere -> segmentation bit-identical) =====
    norm_k<<<NB*SS, 256>>>();
    cos_k<<<dim3(CS_TOT, NB), 256>>>();
    base_k<<<(NB*SM1 + 255)/256, 256>>>();
    // h1 = gelu(bi @ detW1[n]^T + b) -> 2-way split directly; A gathered from x2 (BIG=1)
    { GemmArgs a = { x2, dW1_2, detb1, nullptr, h1_2, ROWS_DET, DD, 2*DD,
                     2*DD, 2*2*DD, 2*DD, DD, OSINV, NP3,
                     0, 0, (long long)DD*2*2*DD, 0,
                     (long long)ROWS_DET*2*DD, 0, DD, 3, 3 };
      tg_launch<1,1,1>(a); }
    // h2 = gelu(h1 @ detW2[n]^T + b) fp32
    { GemmArgs a = { h1_2, dW2_2, detb2, h2, nullptr, ROWS_DET, DD/2, DD,
                     2*DD, 2*DD, DD/2, 0, OSINV, NP3,
                     (long long)ROWS_DET*2*DD, 0, (long long)(DD/2)*2*DD, 0,
                     (long long)ROWS_DET*(DD/2), 0, DD/2, 3, 3 };
      tg_launch<1,0,0>(a); }
    learned_final_k<<<ROWS_DET, 256>>>(detW3, detb3);
    seg_scan_k<<<NB, SS>>>();

    // ===== continuous path (np=2: weights full precision, data fp16-truncated) =====
    // fused segment attention (fp32) -> ctx2 (fp16 split)
    seg_attn_k<<<NB*SS*NH/8, 256>>>();
    // attn_out = ctx @ out_w^T + out_b
    { GemmArgs a = { ctx2, outw2, out_b, attnout, nullptr, NB*SS, DD, DD,
                     2*DD, 2*DD, DD, 0, OSINV, NP2, 0,0,0,0,0,0,0, 1, 1 };
      tg_launch<0,0,0>(a); }
    chunk_k<<<dim3(MAXC, NB), 256>>>(size_emb, pos_enc);
    // hproc = gelu(chunk @ procW1^T + b) -> 2-way split directly
    { GemmArgs a = { chunk2, pw1_2, procb1, nullptr, hproc2, NB*MAXC, 2*DD, DD,
                     2*DD, 2*DD, 2*2*DD, 2*DD, OSINV, NP2, 0,0,0,0,0,0,0, 1, 1 };
      tg_launch<1,1,0>(a); }
    // y = hproc @ procW2^T + b
    { GemmArgs a = { hproc2, pw2_2, procb2, yb, nullptr, NB*MAXC, DD, 2*DD,
                     2*2*DD, 2*2*DD, DD, 0, OSINV, NP2, 0,0,0,0,0,0,0, 1, 1 };
      tg_launch<0,0,0>(a); }
    ln_k<<<NB*MAXC, 256>>>(ln_g, ln_b, outp);
}

// round 14
// speedup vs baseline: 1.1994x; 1.0140x over previous
#include <cuda_runtime.h>
#include <cuda_fp16.h>
#include <math.h>
#include <stdint.h>

// ---------------- problem constants ----------------
#define NB 4
#define SS 1024
#define DD 1536
#define NH 12
#define HDIM 128
#define MAXC 256
#define SM1 1023
#define ROWS_DET (NB*SM1)        // 4092
#define CS_TOT (1023+511+255)    // 1789
#define XQ 6144                  // combined xling|qkv row width
#define QOFF 1536                // qkv column offset in combined buffer

#define WSCALE 64.0f
#define OSINV  0.015625f         // 1/64

// ---------------- fp32 scratch ----------------
__device__ float g_xq[(size_t)NB*SS*XQ];       // [.,0:1536)=xling, [.,1536:6144)=qkv
__device__ float g_bc[XQ];                     // combined bias
__device__ float g_norm[NB*SS];
__device__ float g_cs[NB*CS_TOT];
__device__ float g_base[NB*SM1];
__device__ float g_h2[(size_t)3*ROWS_DET*(DD/2)];
__device__ float g_final[NB*SM1];
__device__ int   g_seg[NB*SS];
__device__ int   g_qlo[NB*SS];
__device__ int   g_qhi[NB*SS];
__device__ int   g_segstart[NB*MAXC];
__device__ int   g_segcount[NB*MAXC];
__device__ float g_attnout[(size_t)NB*SS*DD];
__device__ float g_y[(size_t)NB*MAXC*DD];

// ---------------- fp16 2-way split scratch [rows][2K] (hi|lo) ----------------
__device__ __half g_x2[(size_t)NB*SS*2*DD];
__device__ __half g_wc2[(size_t)XQ*2*DD];      // combined [Wp | in_proj_w] split
__device__ __half g_dW1_2[(size_t)3*DD*2*(2*DD)];
__device__ __half g_h1_2[(size_t)3*ROWS_DET*2*DD];
__device__ __half g_dW2_2[(size_t)3*(DD/2)*2*DD];
__device__ __half g_ctx2[(size_t)NB*SS*2*DD];
__device__ __half g_outw2[(size_t)DD*2*DD];
__device__ __half g_chunk2[(size_t)NB*MAXC*2*DD];
__device__ __half g_pw1_2[(size_t)2*DD*2*DD];
__device__ __half g_hproc2[(size_t)NB*MAXC*2*2*DD];
__device__ __half g_pw2_2[(size_t)DD*2*2*DD];

__device__ __forceinline__ float gelu_exact(float v) {
    return 0.5f * v * (1.0f + erff(v * 0.70710678118654752440f));
}
__device__ __forceinline__ uint32_t smem_u32(const void* p) {
    uint32_t a;
    asm("{ .reg .u64 t; cvta.to.shared.u64 t, %1; cvt.u32.u64 %0, t; }" : "=r"(a) : "l"(p));
    return a;
}
__device__ __forceinline__ float warp_sum(float v) {
    #pragma unroll
    for (int o = 16; o > 0; o >>= 1) v += __shfl_xor_sync(0xffffffffu, v, o);
    return v;
}

#define LDSM4(r0,r1,r2,r3,addr) \
    asm volatile("ldmatrix.sync.aligned.m8n8.x4.shared.b16 {%0,%1,%2,%3}, [%4];" \
        : "=r"(r0), "=r"(r1), "=r"(r2), "=r"(r3) : "r"(addr))

#define MMA16816(d, a, b0, b1) \
    asm volatile("mma.sync.aligned.m16n8k16.row.col.f32.f16.f16.f32 " \
        "{%0,%1,%2,%3},{%4,%5,%6,%7},{%8,%9},{%0,%1,%2,%3};" \
        : "+f"((d)[0]), "+f"((d)[1]), "+f"((d)[2]), "+f"((d)[3]) \
        : "r"((a)[0]), "r"((a)[1]), "r"((a)[2]), "r"((a)[3]), "r"(b0), "r"(b1))

#define CP_ASYNC16(dst, src, sz) \
    asm volatile("cp.async.ca.shared.global [%0], [%1], 16, %2;" :: "r"(dst), "l"(src), "r"(sz))
#define CP_COMMIT() asm volatile("cp.async.commit_group;" ::: "memory")
#define CP_WAIT1() asm volatile("cp.async.wait_group 1;" ::: "memory")
#define CP_WAIT0() asm volatile("cp.async.wait_group 0;" ::: "memory")

// ================= mma.sync fp16 split GEMM (2-stage, K64, 2 CTAs/SM) =================
// A[M][2K] (hi|lo), B[N][2K] (hi|lo).
// np = (n0 < splitN) ? npA : npB.
//   np=3: Ah.Bh + Ah.Bl + Al.Bh
//   np=2: Ah.Bh + Ah.Bl           (weights full precision, data fp16-truncated)
// BIG=1: A is g_x2; rows are bigrams (b,s); chunk selects x_s / x_{s+1}.
#define RSTRIDE 144
#define ATILE (128*RSTRIDE)        // 18432
#define BUFSZ (2*ATILE)            // 36864
#define TG_SMEM (2*BUFSZ)          // 73728

template<int ACT, int OMODE, int BIG>
__global__ void __launch_bounds__(256)
tgemm_k(const __half* __restrict__ A, const __half* __restrict__ B,
        const float* __restrict__ bias, float* __restrict__ C, __half* __restrict__ C2,
        int M, int K, int lda, int ldb, int ldc, int segoff, float oscale,
        int npA, int npB, int splitN,
        long long sAi, long long sAo, long long sBi, long long sBo,
        long long sCi, long long sCo, long long sbias, int innerN)
{
    const int segA_[3] = {0,0,1};
    const int segB_[3] = {0,1,0};
    extern __shared__ char smem[];
    uint32_t sb = smem_u32(smem);
    int tid = threadIdx.x;
    int z = blockIdx.z, zi = z % innerN, zo = z / innerN;
    if (!BIG) A += (size_t)(zi*sAi + zo*sAo);
    B += (size_t)(zi*sBi + zo*sBo);
    if (OMODE == 0) C  += (size_t)(zi*sCi + zo*sCo);
    else            C2 += (size_t)(zi*sCi + zo*sCo);
    int m0 = blockIdx.y * 128, n0 = blockIdx.x * 128;

    const int KPC = K >> 6;
    const int NP = (n0 < splitN) ? npA : npB;
    const int NC = NP * KPC;

    // per-thread A-load slots (row/col fixed across chunks)
    int arow_[4]; uint32_t asz_[4]; long long aoff_[4]; int ac_[4];
    #pragma unroll
    for (int i = 0; i < 4; i++) {
        int f = tid + (i << 8);
        int row = f >> 3, c = f & 7;
        int gr = m0 + row;
        int grc = gr < M ? gr : (M - 1);
        arow_[i] = row; ac_[i] = c;
        asz_[i] = gr < M ? 16u : 0u;
        if (BIG) {
            int b = grc / SM1, s = grc % SM1;
            aoff_[i] = (long long)(b*SS + s) * (2*DD);
        } else {
            aoff_[i] = (long long)grc * lda;
        }
    }

    auto issue = [&](int kc, int buf) {
        int p = kc / KPC;
        int k0 = (kc - p * KPC) << 6;
        uint32_t sA = sb + buf * BUFSZ;
        uint32_t sB = sA + ATILE;
        if (BIG) {
            int side = (k0 >= DD) ? 1 : 0;
            long long cofs = (long long)side*(2*DD) + segA_[p]*DD + (k0 - side*DD);
            #pragma unroll
            for (int i = 0; i < 4; i++) {
                const void* src = A + aoff_[i] + cofs + ac_[i] * 8;
                CP_ASYNC16(sA + arow_[i] * RSTRIDE + ac_[i] * 16, src, asz_[i]);
            }
        } else {
            const __half* Ap = A + (size_t)segA_[p] * K + k0;
            #pragma unroll
            for (int i = 0; i < 4; i++) {
                const void* src = Ap + aoff_[i] + ac_[i] * 8;
                CP_ASYNC16(sA + arow_[i] * RSTRIDE + ac_[i] * 16, src, asz_[i]);
            }
        }
        const __half* Bp = B + (size_t)segB_[p] * K + k0;
        #pragma unroll
        for (int i = 0; i < 4; i++) {
            int f = tid + (i << 8);
            int row = f >> 3, c = f & 7;
            const void* src = Bp + (size_t)(n0 + row) * ldb + c * 8;
            CP_ASYNC16(sB + row * RSTRIDE + c * 16, src, 16u);
        }
    };

    int lane = tid & 31, w = tid >> 5;
    int wm = w & 1, wn = w >> 1;
    uint32_t a_row = ((lane >> 3) & 1) * 8 + (lane & 7);
    uint32_t a_cs  = lane >> 4;
    uint32_t b_row = (lane >> 4) * 8 + (lane & 7);
    uint32_t b_cs  = (lane >> 3) & 1;

    float acc[4][4][4];
    #pragma unroll
    for (int i = 0; i < 4; i++)
        #pragma unroll
        for (int j = 0; j < 4; j++)
            #pragma unroll
            for (int r = 0; r < 4; r++) acc[i][j][r] = 0.f;

    issue(0, 0);
    CP_COMMIT();

    for (int kc = 0; kc < NC; kc++) {
        int cur = kc & 1;
        if (kc + 1 < NC) { issue(kc + 1, cur ^ 1); CP_COMMIT(); CP_WAIT1(); }
        else             { CP_WAIT0(); }
        __syncthreads();

        uint32_t sA = sb + cur * BUFSZ;
        uint32_t sB = sA + ATILE;
        #pragma unroll
        for (int ks = 0; ks < 4; ks++) {
            uint32_t av[4][4], bv[2][4];
            #pragma unroll
            for (int mt = 0; mt < 4; mt++) {
                uint32_t ad = sA + (wm*64 + mt*16 + a_row) * RSTRIDE + ((ks*2 + a_cs) << 4);
                LDSM4(av[mt][0], av[mt][1], av[mt][2], av[mt][3], ad);
            }
            #pragma unroll
            for (int bt = 0; bt < 2; bt++) {
                uint32_t bd = sB + (wn*32 + bt*16 + b_row) * RSTRIDE + ((ks*2 + b_cs) << 4);
                LDSM4(bv[bt][0], bv[bt][1], bv[bt][2], bv[bt][3], bd);
            }
            #pragma unroll
            for (int mt = 0; mt < 4; mt++)
                #pragma unroll
                for (int nt = 0; nt < 4; nt++) {
                    uint32_t b0 = bv[nt >> 1][(nt & 1) * 2];
                    uint32_t b1 = bv[nt >> 1][(nt & 1) * 2 + 1];
                    MMA16816(acc[mt][nt], av[mt], b0, b1);
                }
        }
        __syncthreads();
    }

    // ---- epilogue ----
    if (bias) bias += (size_t)z * (size_t)sbias;
    #pragma unroll
    for (int mt = 0; mt < 4; mt++) {
        int r0 = m0 + wm*64 + mt*16 + (lane >> 2);
        #pragma unroll
        for (int nt = 0; nt < 4; nt++) {
            int col = n0 + wn*32 + nt*8 + (lane & 3)*2;
            float bb0 = 0.f, bb1 = 0.f;
            if (bias) { bb0 = bias[col]; bb1 = bias[col+1]; }
            #pragma unroll
            for (int half_ = 0; half_ < 2; half_++) {
                int r = r0 + half_*8;
                if (r >= M) continue;
                float v0 = acc[mt][nt][half_*2]   * oscale + bb0;
                float v1 = acc[mt][nt][half_*2+1] * oscale + bb1;
                if (ACT == 1) { v0 = gelu_exact(v0); v1 = gelu_exact(v1); }
                if (OMODE == 0) {
                    *(float2*)(C + (size_t)r*ldc + col) = make_float2(v0, v1);
                } else {
                    __half* d = C2 + (size_t)r*ldc + col;
                    __half h0 = __float2half_rn(v0);
                    __half h1 = __float2half_rn(v1);
                    __half l0 = __float2half_rn(v0 - __half2float(h0));
                    __half l1 = __float2half_rn(v1 - __half2float(h1));
                    *(__half2*)(d)          = __halves2half2(h0, h1);
                    *(__half2*)(d + segoff) = __halves2half2(l0, l1);
                }
            }
        }
    }
}

// ================= vectorized split kernel (4 cols/thread) =================
__global__ void split2v_k(const float* __restrict__ src, __half* __restrict__ dst,
                          long long total4, int C4, int C, float scale) {
    long long idx4 = (long long)blockIdx.x * 256 + threadIdx.x;
    if (idx4 >= total4) return;
    long long r = idx4 / C4;
    int c = (int)(idx4 - r * C4) * 4;
    float4 v = *(const float4*)(src + r * C + c);
    v.x *= scale; v.y *= scale; v.z *= scale; v.w *= scale;
    __half h0 = __float2half_rn(v.x), h1 = __float2half_rn(v.y);
    __half h2 = __float2half_rn(v.z), h3 = __float2half_rn(v.w);
    __half l0 = __float2half_rn(v.x - __half2float(h0));
    __half l1 = __float2half_rn(v.y - __half2float(h1));
    __half l2 = __float2half_rn(v.z - __half2float(h2));
    __half l3 = __float2half_rn(v.w - __half2float(h3));
    __half* d = dst + r * (2LL*C) + c;
    *(__half2*)(d)         = __halves2half2(h0, h1);
    *(__half2*)(d + 2)     = __halves2half2(h2, h3);
    *(__half2*)(d + C)     = __halves2half2(l0, l1);
    *(__half2*)(d + C + 2) = __halves2half2(l2, l3);
}

__global__ void biascat_k(const float* __restrict__ bp, const float* __restrict__ ipb) {
    int i = blockIdx.x * 256 + threadIdx.x;
    if (i < DD)      g_bc[i] = bp[i];
    else if (i < XQ) g_bc[i] = ipb[i - DD];
}

// ---------------- warp-per-row reductions ----------------
// norms: one warp per row, float4 loads, shuffle reduce
__global__ void __launch_bounds__(256)
norm_k() {
    int w = threadIdx.x >> 5, lane = threadIdx.x & 31;
    int r = blockIdx.x * 8 + w;                     // 512 blocks * 8 = 4096 rows
    const float4* p = (const float4*)(g_xq + (size_t)r * XQ);
    float ss = 0.f;
    #pragma unroll
    for (int i = 0; i < 12; i++) {                  // 12*32*4 = 1536
        float4 v = p[lane + i*32];
        ss += v.x*v.x + v.y*v.y + v.z*v.z + v.w*v.w;
    }
    ss = warp_sum(ss);
    if (lane == 0) g_norm[r] = fmaxf(sqrtf(ss), 1e-8f);
}

// cosine sims: one warp per (b, t)
__global__ void __launch_bounds__(256)
cos_k() {
    int w = threadIdx.x >> 5, lane = threadIdx.x & 31;
    int t = blockIdx.x * 8 + w;
    int b = blockIdx.y;
    if (t >= CS_TOT) return;
    int scale, i;
    if (t < 1023)      { scale = 1; i = t; }
    else if (t < 1534) { scale = 2; i = t - 1023; }
    else               { scale = 4; i = t - 1534; }
    int s0 = i * scale, s1 = s0 + scale;
    const float4* a = (const float4*)(g_xq + ((size_t)b*SS + s0) * XQ);
    const float4* c = (const float4*)(g_xq + ((size_t)b*SS + s1) * XQ);
    float d = 0.f;
    #pragma unroll
    for (int j = 0; j < 12; j++) {
        float4 av = a[lane + j*32];
        float4 cv = c[lane + j*32];
        d += av.x*cv.x + av.y*cv.y + av.z*cv.z + av.w*cv.w;
    }
    d = warp_sum(d);
    if (lane == 0)
        g_cs[b*CS_TOT + t] = d / (g_norm[b*SS + s0] * g_norm[b*SS + s1]);
}

__global__ void base_k() {
    int idx = blockIdx.x * 256 + threadIdx.x;
    if (idx >= NB*SM1) return;
    int b = idx / SM1, j = idx % SM1;
    const int Ls[3]   = {1023, 511, 255};
    const int offs[3] = {0, 1023, 1534};
    float acc = 0.f;
    #pragma unroll
    for (int u = 0; u < 3; u++) {
        int L = Ls[u];
        float ratio = (float)((double)L / 1023.0);
        float src = ((float)j + 0.5f) * ratio - 0.5f;
        src = fminf(fmaxf(src, 0.0f), (float)(L - 1));
        int i0 = (int)floorf(src);
        int i1 = min(i0 + 1, L - 1);
        float w = src - (float)i0;
        const float* cs = g_cs + b*CS_TOT + offs[u];
        acc += cs[i0] * (1.0f - w) + cs[i1] * w;
    }
    g_base[idx] = 0.5f * (1.0f - acc / 3.0f);
}

// learned head + final boundary: one warp per row
__global__ void __launch_bounds__(256)
learned_final_k(const float* __restrict__ detW3,
                const float* __restrict__ detb3) {
    int w = threadIdx.x >> 5, lane = threadIdx.x & 31;
    int r = blockIdx.x * 8 + w;
    if (r >= ROWS_DET) return;
    float sacc = 0.f;
    #pragma unroll
    for (int n = 0; n < 3; n++) {
        const float4* h2p = (const float4*)(g_h2 + ((size_t)n*ROWS_DET + r) * (DD/2));
        const float4* wp  = (const float4*)(detW3 + n*(DD/2));
        float part = 0.f;
        #pragma unroll
        for (int j = 0; j < 6; j++) {               // 6*32*4 = 768
            float4 a = h2p[lane + j*32];
            float4 b = wp[lane + j*32];
            part += a.x*b.x + a.y*b.y + a.z*b.z + a.w*b.w;
        }
        part = warp_sum(part);
        float t = part + detb3[n];
        sacc += 1.0f / (1.0f + expf(-t));
    }
    if (lane == 0)
        g_final[r] = 0.6f * g_base[r] + 0.4f * (sacc / 3.0f);
}

// parallel segmentation: integer scans (exact, order-independent)
__global__ void __launch_bounds__(SS)
seg_scan_k() {
    int b = blockIdx.x, t = threadIdx.x;
    __shared__ int sscan[SS];
    __shared__ int smax[SS];
    __shared__ int rmin[SS];
    float bv = (t == 0) ? 1.0f : g_final[b*SM1 + t - 1];
    int f = (t == 0) ? 1 : (bv > 0.5f ? 1 : 0);
    sscan[t] = f;
    smax[t]  = f ? t : -1;
    rmin[t]  = f ? t : SS;
    __syncthreads();
    for (int o = 1; o < SS; o <<= 1) {
        int vs = sscan[t];
        int vm = smax[t];
        int vr = rmin[t];
        int vs2 = (t >= o) ? sscan[t - o] : 0;
        int vm2 = (t >= o) ? smax[t - o]  : -1;
        int vr2 = (t + o < SS) ? rmin[t + o] : SS;
        __syncthreads();
        sscan[t] = vs + vs2;
        smax[t]  = max(vm, vm2);
        rmin[t]  = min(vr, vr2);
        __syncthreads();
    }
    int m = sscan[t] - 1;
    g_seg[b*SS + t] = m;
    g_qlo[b*SS + t] = smax[t];
    int hi = (t < SS - 1) ? rmin[t + 1] : SS;
    g_qhi[b*SS + t] = hi;
    if (t < MAXC) { g_segstart[b*MAXC + t] = 0; g_segcount[b*MAXC + t] = 0; }
    __syncthreads();
    if (f && m < MAXC) {
        g_segstart[b*MAXC + m] = t;
        g_segcount[b*MAXC + m] = hi - t;
    }
}

// fused segment attention: one warp per (b, s, h); fp32; writes fp16-split ctx
__global__ void __launch_bounds__(256)
seg_attn_k() {
    __shared__ float dots[8][SS];
    int w = threadIdx.x >> 5, lane = threadIdx.x & 31;
    int g = blockIdx.x * 8 + w;
    int h = g % NH;
    int s = (g / NH) & (SS - 1);
    int b = g / (NH * SS);
    int lo = g_qlo[b*SS + s], hi = g_qhi[b*SS + s];

    const float* qp = g_xq + ((size_t)(b*SS + s))*XQ + QOFF + h*HDIM + lane*4;
    float4 qv = *(const float4*)qp;
    const float scale = 0.088388347648318440550f;   // 1/sqrt(128)

    const float* kbase = g_xq + ((size_t)(b*SS))*XQ + QOFF + DD + h*HDIM + lane*4;
    float mx = -3.402823e38f;
    for (int k = lo; k < hi; k++) {
        float4 kv = *(const float4*)(kbase + (size_t)k*XQ);
        float d = qv.x*kv.x + qv.y*kv.y + qv.z*kv.z + qv.w*kv.w;
        d = warp_sum(d);
        d *= scale;
        if (lane == 0) dots[w][k - lo] = d;
        mx = fmaxf(mx, d);
    }
    __syncwarp();

    const float* vbase = g_xq + ((size_t)(b*SS))*XQ + QOFF + 2*DD + h*HDIM + lane*4;
    float4 acc = make_float4(0.f, 0.f, 0.f, 0.f);
    float sum = 0.f;
    for (int k = lo; k < hi; k++) {
        float e = expf(dots[w][k - lo] - mx);
        sum += e;
        float4 vv = *(const float4*)(vbase + (size_t)k*XQ);
        acc.x += e*vv.x; acc.y += e*vv.y; acc.z += e*vv.z; acc.w += e*vv.w;
    }
    float inv = 1.0f / sum;
    float c0 = acc.x*inv, c1 = acc.y*inv, c2 = acc.z*inv, c3 = acc.w*inv;

    __half* d = g_ctx2 + ((size_t)(b*SS + s))*(2*DD) + h*HDIM + lane*4;
    __half h0 = __float2half_rn(c0), h1 = __float2half_rn(c1);
    __half h2 = __float2half_rn(c2), h3 = __float2half_rn(c3);
    *(__half2*)(d)     = __halves2half2(h0, h1);
    *(__half2*)(d + 2) = __halves2half2(h2, h3);
    __half l0 = __float2half_rn(c0 - __half2float(h0));
    __half l1 = __float2half_rn(c1 - __half2float(h1));
    __half l2 = __float2half_rn(c2 - __half2float(h2));
    __half l3 = __float2half_rn(c3 - __half2float(h3));
    *(__half2*)(d + DD)     = __halves2half2(l0, l1);
    *(__half2*)(d + DD + 2) = __halves2half2(l2, l3);
}

// pooling + embeddings, writes 2-way fp16 split chunk directly
__global__ void chunk_k(const float* __restrict__ size_emb,
                        const float* __restrict__ pos_enc) {
    int m = blockIdx.x, b = blockIdx.y;
    int cnt = g_segcount[b*MAXC + m];
    int st  = g_segstart[b*MAXC + m];
    __half* drow = g_chunk2 + ((size_t)b*MAXC + m) * (2*DD);
    for (int d = threadIdx.x; d < DD; d += 256) {
        float v;
        if (cnt > 0) {
            float sum = 0.f;
            for (int s = st; s < st + cnt; s++)
                sum += g_attnout[((size_t)b*SS + s)*DD + d];
            int cl = min(cnt, 1023);
            v = sum / (float)cnt + size_emb[(size_t)cl*DD + d];
        } else v = 0.f;
        v += pos_enc[(size_t)m*DD + d];
        __half h = __float2half_rn(v);
        drow[d]      = h;
        drow[DD + d] = __float2half_rn(v - __half2float(h));
    }
}

__global__ void ln_k(const float* __restrict__ gamma,
                     const float* __restrict__ beta,
                     float* __restrict__ out) {
    int r = blockIdx.x;
    const float* y = g_y + (size_t)r*DD;
    __shared__ float sh[256];
    float s = 0.f;
    for (int d = threadIdx.x; d < DD; d += 256) s += y[d];
    sh[threadIdx.x] = s; __syncthreads();
    for (int o = 128; o > 0; o >>= 1) {
        if (threadIdx.x < o) sh[threadIdx.x] += sh[threadIdx.x+o];
        __syncthreads();
    }
    float mu = sh[0] / (float)DD; __syncthreads();
    float v2 = 0.f;
    for (int d = threadIdx.x; d < DD; d += 256) { float t = y[d]-mu; v2 += t*t; }
    sh[threadIdx.x] = v2; __syncthreads();
    for (int o = 128; o > 0; o >>= 1) {
        if (threadIdx.x < o) sh[threadIdx.x] += sh[threadIdx.x+o];
        __syncthreads();
    }
    float inv = 1.0f / sqrtf(sh[0] / (float)DD + 1e-5f);
    for (int d = threadIdx.x; d < DD; d += 256)
        out[(size_t)r*DD + d] = (y[d] - mu) * inv * gamma[d] + beta[d];
}

// ---------------- host launchers ----------------
struct GemmArgs {
    const __half *A, *B;
    const float* bias;
    float* C;
    __half* C2;
    int M, N, K, lda, ldb, ldc, segoff;
    float oscale;
    int npA, npB, splitN;
    long long sAi, sAo, sBi, sBo, sCi, sCo, sbias;
    int innerN, batch;
};

template<int ACT, int OMODE, int BIG>
static void tg_launch(const GemmArgs& a) {
    dim3 grid(a.N/128, (a.M + 127)/128, a.batch);
    tgemm_k<ACT,OMODE,BIG><<<grid,256,TG_SMEM>>>(a.A, a.B, a.bias, a.C, a.C2,
        a.M, a.K, a.lda, a.ldb, a.ldc, a.segoff, a.oscale,
        a.npA, a.npB, a.splitN,
        a.sAi, a.sAo, a.sBi, a.sBo, a.sCi, a.sCo, a.sbias, a.innerN);
}

static void split2(const float* src, __half* dst, long long rows, int cols, float scale) {
    long long total4 = rows * cols / 4;
    split2v_k<<<(unsigned)((total4 + 255)/256), 256>>>(src, dst, total4, cols/4, cols, scale);
}

#define NP3 3, 3, (1<<30)
#define NP2 2, 2, (1<<30)

extern "C" void kernel_launch(void* const* d_in, const int* in_sizes, int n_in,
                              void* d_out, int out_size) {
    const float* x         = (const float*)d_in[0];
    const float* Wp        = (const float*)d_in[1];
    const float* bp        = (const float*)d_in[2];
    const float* detW1     = (const float*)d_in[3];
    const float* detb1     = (const float*)d_in[4];
    const float* detW2     = (const float*)d_in[5];
    const float* detb2     = (const float*)d_in[6];
    const float* detW3     = (const float*)d_in[7];
    const float* detb3     = (const float*)d_in[8];
    const float* in_proj_w = (const float*)d_in[9];
    const float* in_proj_b = (const float*)d_in[10];
    const float* out_w     = (const float*)d_in[11];
    const float* out_b     = (const float*)d_in[12];
    const float* size_emb  = (const float*)d_in[13];
    const float* pos_enc   = (const float*)d_in[14];
    const float* procW1    = (const float*)d_in[15];
    const float* procb1    = (const float*)d_in[16];
    const float* procW2    = (const float*)d_in[17];
    const float* procb2    = (const float*)d_in[18];
    const float* ln_g      = (const float*)d_in[19];
    const float* ln_b      = (const float*)d_in[20];
    float* outp = (float*)d_out;

    cudaFuncSetAttribute(tgemm_k<0,0,0>, cudaFuncAttributeMaxDynamicSharedMemorySize, TG_SMEM);
    cudaFuncSetAttribute(tgemm_k<1,0,0>, cudaFuncAttributeMaxDynamicSharedMemorySize, TG_SMEM);
    cudaFuncSetAttribute(tgemm_k<1,1,0>, cudaFuncAttributeMaxDynamicSharedMemorySize, TG_SMEM);
    cudaFuncSetAttribute(tgemm_k<1,1,1>, cudaFuncAttributeMaxDynamicSharedMemorySize, TG_SMEM);

    void *p;
    cudaGetSymbolAddress(&p, g_xq);      float* xq      = (float*)p;
    cudaGetSymbolAddress(&p, g_bc);      float* bc      = (float*)p;
    cudaGetSymbolAddress(&p, g_h2);      float* h2      = (float*)p;
    cudaGetSymbolAddress(&p, g_attnout); float* attnout = (float*)p;
    cudaGetSymbolAddress(&p, g_y);       float* yb      = (float*)p;
    cudaGetSymbolAddress(&p, g_x2);      __half* x2     = (__half*)p;
    cudaGetSymbolAddress(&p, g_wc2);     __half* wc2    = (__half*)p;
    cudaGetSymbolAddress(&p, g_dW1_2);   __half* dW1_2  = (__half*)p;
    cudaGetSymbolAddress(&p, g_h1_2);    __half* h1_2   = (__half*)p;
    cudaGetSymbolAddress(&p, g_dW2_2);   __half* dW2_2  = (__half*)p;
    cudaGetSymbolAddress(&p, g_ctx2);    __half* ctx2   = (__half*)p;
    cudaGetSymbolAddress(&p, g_outw2);   __half* outw2  = (__half*)p;
    cudaGetSymbolAddress(&p, g_chunk2);  __half* chunk2 = (__half*)p;
    cudaGetSymbolAddress(&p, g_pw1_2);   __half* pw1_2  = (__half*)p;
    cudaGetSymbolAddress(&p, g_hproc2);  __half* hproc2 = (__half*)p;
    cudaGetSymbolAddress(&p, g_pw2_2);   __half* pw2_2  = (__half*)p;

    // ===== input splits (weights scaled by 64 to keep fp16 lo plane normal) =====
    split2(x, x2, NB*SS, DD, 1.0f);
    split2(Wp, wc2, DD, DD, WSCALE);                            // rows 0..1535 of combined W
    split2(in_proj_w, wc2 + (size_t)DD*2*DD, 3*DD, DD, WSCALE); // rows 1536..6143
    split2(detW1, dW1_2, 3*DD, 2*DD, WSCALE);
    split2(detW2, dW2_2, 3*(DD/2), DD, WSCALE);
    split2(out_w, outw2, DD, DD, WSCALE);
    split2(procW1, pw1_2, 2*DD, DD, WSCALE);
    split2(procW2, pw2_2, DD, 2*DD, WSCALE);
    biascat_k<<<(XQ + 255)/256, 256>>>(bp, in_proj_b);

    // ===== merged xling|qkv GEMM: 3 products for n<1536 (boundary), 2 for qkv =====
    { GemmArgs a = { x2, wc2, bc, xq, nullptr, NB*SS, XQ, DD, 2*DD, 2*DD, XQ, 0,
                     OSINV, 3, 2, DD, 0,0,0,0,0,0,0, 1, 1 };
      tg_launch<0,0,0>(a); }

    // ===== boundary path (np=3 -> GEMMs bit-identical; warp reductions re-ordered) =====
    norm_k<<<NB*SS/8, 256>>>();
    cos_k<<<dim3((CS_TOT + 7)/8, NB), 256>>>();
    base_k<<<(NB*SM1 + 255)/256, 256>>>();
    // h1 = gelu(bi @ detW1[n]^T + b) -> 2-way split directly; A gathered from x2 (BIG=1)
    { GemmArgs a = { x2, dW1_2, detb1, nullptr, h1_2, ROWS_DET, DD, 2*DD,
                     2*DD, 2*2*DD, 2*DD, DD, OSINV, NP3,
                     0, 0, (long long)DD*2*2*DD, 0,
                     (long long)ROWS_DET*2*DD, 0, DD, 3, 3 };
      tg_launch<1,1,1>(a); }
    // h2 = gelu(h1 @ detW2[n]^T + b) fp32
    { GemmArgs a = { h1_2, dW2_2, detb2, h2, nullptr, ROWS_DET, DD/2, DD,
                     2*DD, 2*DD, DD/2, 0, OSINV, NP3,
                     (long long)ROWS_DET*2*DD, 0, (long long)(DD/2)*2*DD, 0,
                     (long long)ROWS_DET*(DD/2), 0, DD/2, 3, 3 };
      tg_launch<1,0,0>(a); }
    learned_final_k<<<(ROWS_DET + 7)/8, 256>>>(detW3, detb3);
    seg_scan_k<<<NB, SS>>>();

    // ===== continuous path (np=2) =====
    seg_attn_k<<<NB*SS*NH/8, 256>>>();
    // attn_out = ctx @ out_w^T + out_b
    { GemmArgs a = { ctx2, outw2, out_b, attnout, nullptr, NB*SS, DD, DD,
                     2*DD, 2*DD, DD, 0, OSINV, NP2, 0,0,0,0,0,0,0, 1, 1 };
      tg_launch<0,0,0>(a); }
    chunk_k<<<dim3(MAXC, NB), 256>>>(size_emb, pos_enc);
    // hproc = gelu(chunk @ procW1^T + b) -> 2-way split directly
    { GemmArgs a = { chunk2, pw1_2, procb1, nullptr, hproc2, NB*MAXC, 2*DD, DD,
                     2*DD, 2*DD, 2*2*DD, 2*DD, OSINV, NP2, 0,0,0,0,0,0,0, 1, 1 };
      tg_launch<1,1,0>(a); }
    // y = hproc @ procW2^T + b
    { GemmArgs a = { hproc2, pw2_2, procb2, yb, nullptr, NB*MAXC, DD, 2*DD,
                     2*2*DD, 2*2*DD, DD, 0, OSINV, NP2, 0,0,0,0,0,0,0, 1, 1 };
      tg_launch<0,0,0>(a); }
    ln_k<<<NB*MAXC, 256>>>(ln_g, ln_b, outp);
}

// round 15
// speedup vs baseline: 1.2041x; 1.0039x over previous
#include <cuda_runtime.h>
#include <cuda_fp16.h>
#include <math.h>
#include <stdint.h>

// ---------------- problem constants ----------------
#define NB 4
#define SS 1024
#define DD 1536
#define NH 12
#define HDIM 128
#define MAXC 256
#define SM1 1023
#define ROWS_DET (NB*SM1)        // 4092
#define CS_TOT (1023+511+255)    // 1789
#define XQ 6144                  // combined xling|qkv row width
#define QOFF 1536                // qkv column offset in combined buffer

#define WSCALE 64.0f
#define OSINV  0.015625f         // 1/64

// ---------------- fp32 scratch ----------------
__device__ float g_xq[(size_t)NB*SS*XQ];       // [.,0:1536)=xling, [.,1536:6144)=qkv
__device__ float g_bc[XQ];                     // combined bias
__device__ float g_norm[NB*SS];
__device__ float g_cs[NB*CS_TOT];
__device__ float g_base[NB*SM1];
__device__ float g_h2[(size_t)3*ROWS_DET*(DD/2)];
__device__ float g_final[NB*SM1];
__device__ int   g_seg[NB*SS];
__device__ int   g_qlo[NB*SS];
__device__ int   g_qhi[NB*SS];
__device__ int   g_segstart[NB*MAXC];
__device__ int   g_segcount[NB*MAXC];
__device__ float g_attnout[(size_t)NB*SS*DD];
__device__ float g_y[(size_t)NB*MAXC*DD];

// ---------------- fp16 2-way split scratch [rows][2K] (hi|lo) ----------------
__device__ __half g_x2[(size_t)NB*SS*2*DD];
__device__ __half g_wc2[(size_t)XQ*2*DD];      // combined [Wp | in_proj_w] split
__device__ __half g_dW1_2[(size_t)3*DD*2*(2*DD)];
__device__ __half g_h1_2[(size_t)3*ROWS_DET*2*DD];
__device__ __half g_dW2_2[(size_t)3*(DD/2)*2*DD];
__device__ __half g_ctx2[(size_t)NB*SS*2*DD];
__device__ __half g_outw2[(size_t)DD*2*DD];
__device__ __half g_chunk2[(size_t)NB*MAXC*2*DD];
__device__ __half g_pw1_2[(size_t)2*DD*2*DD];
__device__ __half g_hproc2[(size_t)NB*MAXC*2*2*DD];
__device__ __half g_pw2_2[(size_t)DD*2*2*DD];

__device__ __forceinline__ float gelu_exact(float v) {
    return 0.5f * v * (1.0f + erff(v * 0.70710678118654752440f));
}
__device__ __forceinline__ uint32_t smem_u32(const void* p) {
    uint32_t a;
    asm("{ .reg .u64 t; cvta.to.shared.u64 t, %1; cvt.u32.u64 %0, t; }" : "=r"(a) : "l"(p));
    return a;
}
__device__ __forceinline__ float warp_sum(float v) {
    #pragma unroll
    for (int o = 16; o > 0; o >>= 1) v += __shfl_xor_sync(0xffffffffu, v, o);
    return v;
}

#define LDSM4(r0,r1,r2,r3,addr) \
    asm volatile("ldmatrix.sync.aligned.m8n8.x4.shared.b16 {%0,%1,%2,%3}, [%4];" \
        : "=r"(r0), "=r"(r1), "=r"(r2), "=r"(r3) : "r"(addr))

#define MMA16816(d, a, b0, b1) \
    asm volatile("mma.sync.aligned.m16n8k16.row.col.f32.f16.f16.f32 " \
        "{%0,%1,%2,%3},{%4,%5,%6,%7},{%8,%9},{%0,%1,%2,%3};" \
        : "+f"((d)[0]), "+f"((d)[1]), "+f"((d)[2]), "+f"((d)[3]) \
        : "r"((a)[0]), "r"((a)[1]), "r"((a)[2]), "r"((a)[3]), "r"(b0), "r"(b1))

#define CP_ASYNC16(dst, src, sz) \
    asm volatile("cp.async.ca.shared.global [%0], [%1], 16, %2;" :: "r"(dst), "l"(src), "r"(sz))
#define CP_COMMIT() asm volatile("cp.async.commit_group;" ::: "memory")
#define CP_WAIT1() asm volatile("cp.async.wait_group 1;" ::: "memory")
#define CP_WAIT0() asm volatile("cp.async.wait_group 0;" ::: "memory")

// ================= mma.sync fp16 split GEMM (2-stage, K64, 2 CTAs/SM) =================
// A[M][2K] (hi|lo), B[N][2K] (hi|lo).
// np = (n0 < splitN) ? npA : npB.
//   np=3: Ah.Bh + Ah.Bl + Al.Bh
//   np=2: Ah.Bh + Ah.Bl           (weights full precision, data fp16-truncated)
// BIG=1: A is g_x2; rows are bigrams (b,s); chunk selects x_s / x_{s+1}.
#define RSTRIDE 144
#define ATILE (128*RSTRIDE)        // 18432
#define BUFSZ (2*ATILE)            // 36864
#define TG_SMEM (2*BUFSZ)          // 73728

template<int ACT, int OMODE, int BIG>
__global__ void __launch_bounds__(256)
tgemm_k(const __half* __restrict__ A, const __half* __restrict__ B,
        const float* __restrict__ bias, float* __restrict__ C, __half* __restrict__ C2,
        int M, int K, int lda, int ldb, int ldc, int segoff, float oscale,
        int npA, int npB, int splitN,
        long long sAi, long long sAo, long long sBi, long long sBo,
        long long sCi, long long sCo, long long sbias, int innerN)
{
    const int segA_[3] = {0,0,1};
    const int segB_[3] = {0,1,0};
    extern __shared__ char smem[];
    uint32_t sb = smem_u32(smem);
    int tid = threadIdx.x;
    int z = blockIdx.z, zi = z % innerN, zo = z / innerN;
    if (!BIG) A += (size_t)(zi*sAi + zo*sAo);
    B += (size_t)(zi*sBi + zo*sBo);
    if (OMODE == 0) C  += (size_t)(zi*sCi + zo*sCo);
    else            C2 += (size_t)(zi*sCi + zo*sCo);
    int m0 = blockIdx.y * 128, n0 = blockIdx.x * 128;

    const int KPC = K >> 6;
    const int NP = (n0 < splitN) ? npA : npB;
    const int NC = NP * KPC;

    // per-thread A-load slots (row/col fixed across chunks)
    int arow_[4]; uint32_t asz_[4]; long long aoff_[4]; int ac_[4];
    #pragma unroll
    for (int i = 0; i < 4; i++) {
        int f = tid + (i << 8);
        int row = f >> 3, c = f & 7;
        int gr = m0 + row;
        int grc = gr < M ? gr : (M - 1);
        arow_[i] = row; ac_[i] = c;
        asz_[i] = gr < M ? 16u : 0u;
        if (BIG) {
            int b = grc / SM1, s = grc % SM1;
            aoff_[i] = (long long)(b*SS + s) * (2*DD);
        } else {
            aoff_[i] = (long long)grc * lda;
        }
    }

    auto issue = [&](int kc, int buf) {
        int p = kc / KPC;
        int k0 = (kc - p * KPC) << 6;
        uint32_t sA = sb + buf * BUFSZ;
        uint32_t sB = sA + ATILE;
        if (BIG) {
            int side = (k0 >= DD) ? 1 : 0;
            long long cofs = (long long)side*(2*DD) + segA_[p]*DD + (k0 - side*DD);
            #pragma unroll
            for (int i = 0; i < 4; i++) {
                const void* src = A + aoff_[i] + cofs + ac_[i] * 8;
                CP_ASYNC16(sA + arow_[i] * RSTRIDE + ac_[i] * 16, src, asz_[i]);
            }
        } else {
            const __half* Ap = A + (size_t)segA_[p] * K + k0;
            #pragma unroll
            for (int i = 0; i < 4; i++) {
                const void* src = Ap + aoff_[i] + ac_[i] * 8;
                CP_ASYNC16(sA + arow_[i] * RSTRIDE + ac_[i] * 16, src, asz_[i]);
            }
        }
        const __half* Bp = B + (size_t)segB_[p] * K + k0;
        #pragma unroll
        for (int i = 0; i < 4; i++) {
            int f = tid + (i << 8);
            int row = f >> 3, c = f & 7;
            const void* src = Bp + (size_t)(n0 + row) * ldb + c * 8;
            CP_ASYNC16(sB + row * RSTRIDE + c * 16, src, 16u);
        }
    };

    int lane = tid & 31, w = tid >> 5;
    int wm = w & 1, wn = w >> 1;
    uint32_t a_row = ((lane >> 3) & 1) * 8 + (lane & 7);
    uint32_t a_cs  = lane >> 4;
    uint32_t b_row = (lane >> 4) * 8 + (lane & 7);
    uint32_t b_cs  = (lane >> 3) & 1;

    float acc[4][4][4];
    #pragma unroll
    for (int i = 0; i < 4; i++)
        #pragma unroll
        for (int j = 0; j < 4; j++)
            #pragma unroll
            for (int r = 0; r < 4; r++) acc[i][j][r] = 0.f;

    issue(0, 0);
    CP_COMMIT();

    for (int kc = 0; kc < NC; kc++) {
        int cur = kc & 1;
        if (kc + 1 < NC) { issue(kc + 1, cur ^ 1); CP_COMMIT(); CP_WAIT1(); }
        else             { CP_WAIT0(); }
        __syncthreads();

        uint32_t sA = sb + cur * BUFSZ;
        uint32_t sB = sA + ATILE;
        #pragma unroll
        for (int ks = 0; ks < 4; ks++) {
            uint32_t av[4][4], bv[2][4];
            #pragma unroll
            for (int mt = 0; mt < 4; mt++) {
                uint32_t ad = sA + (wm*64 + mt*16 + a_row) * RSTRIDE + ((ks*2 + a_cs) << 4);
                LDSM4(av[mt][0], av[mt][1], av[mt][2], av[mt][3], ad);
            }
            #pragma unroll
            for (int bt = 0; bt < 2; bt++) {
                uint32_t bd = sB + (wn*32 + bt*16 + b_row) * RSTRIDE + ((ks*2 + b_cs) << 4);
                LDSM4(bv[bt][0], bv[bt][1], bv[bt][2], bv[bt][3], bd);
            }
            #pragma unroll
            for (int mt = 0; mt < 4; mt++)
                #pragma unroll
                for (int nt = 0; nt < 4; nt++) {
                    uint32_t b0 = bv[nt >> 1][(nt & 1) * 2];
                    uint32_t b1 = bv[nt >> 1][(nt & 1) * 2 + 1];
                    MMA16816(acc[mt][nt], av[mt], b0, b1);
                }
        }
        __syncthreads();
    }

    // ---- epilogue ----
    if (bias) bias += (size_t)z * (size_t)sbias;
    #pragma unroll
    for (int mt = 0; mt < 4; mt++) {
        int r0 = m0 + wm*64 + mt*16 + (lane >> 2);
        #pragma unroll
        for (int nt = 0; nt < 4; nt++) {
            int col = n0 + wn*32 + nt*8 + (lane & 3)*2;
            float bb0 = 0.f, bb1 = 0.f;
            if (bias) { bb0 = bias[col]; bb1 = bias[col+1]; }
            #pragma unroll
            for (int half_ = 0; half_ < 2; half_++) {
                int r = r0 + half_*8;
                if (r >= M) continue;
                float v0 = acc[mt][nt][half_*2]   * oscale + bb0;
                float v1 = acc[mt][nt][half_*2+1] * oscale + bb1;
                if (ACT == 1) { v0 = gelu_exact(v0); v1 = gelu_exact(v1); }
                if (OMODE == 0) {
                    *(float2*)(C + (size_t)r*ldc + col) = make_float2(v0, v1);
                } else {
                    __half* d = C2 + (size_t)r*ldc + col;
                    __half h0 = __float2half_rn(v0);
                    __half h1 = __float2half_rn(v1);
                    __half l0 = __float2half_rn(v0 - __half2float(h0));
                    __half l1 = __float2half_rn(v1 - __half2float(h1));
                    *(__half2*)(d)          = __halves2half2(h0, h1);
                    *(__half2*)(d + segoff) = __halves2half2(l0, l1);
                }
            }
        }
    }
}

// ================= vectorized split kernel (4 cols/thread) =================
__global__ void split2v_k(const float* __restrict__ src, __half* __restrict__ dst,
                          long long total4, int C4, int C, float scale) {
    long long idx4 = (long long)blockIdx.x * 256 + threadIdx.x;
    if (idx4 >= total4) return;
    long long r = idx4 / C4;
    int c = (int)(idx4 - r * C4) * 4;
    float4 v = *(const float4*)(src + r * C + c);
    v.x *= scale; v.y *= scale; v.z *= scale; v.w *= scale;
    __half h0 = __float2half_rn(v.x), h1 = __float2half_rn(v.y);
    __half h2 = __float2half_rn(v.z), h3 = __float2half_rn(v.w);
    __half l0 = __float2half_rn(v.x - __half2float(h0));
    __half l1 = __float2half_rn(v.y - __half2float(h1));
    __half l2 = __float2half_rn(v.z - __half2float(h2));
    __half l3 = __float2half_rn(v.w - __half2float(h3));
    __half* d = dst + r * (2LL*C) + c;
    *(__half2*)(d)         = __halves2half2(h0, h1);
    *(__half2*)(d + 2)     = __halves2half2(h2, h3);
    *(__half2*)(d + C)     = __halves2half2(l0, l1);
    *(__half2*)(d + C + 2) = __halves2half2(l2, l3);
}

__global__ void biascat_k(const float* __restrict__ bp, const float* __restrict__ ipb) {
    int i = blockIdx.x * 256 + threadIdx.x;
    if (i < DD)      g_bc[i] = bp[i];
    else if (i < XQ) g_bc[i] = ipb[i - DD];
}

// ---------------- warp-per-row reductions ----------------
__global__ void __launch_bounds__(256)
norm_k() {
    int w = threadIdx.x >> 5, lane = threadIdx.x & 31;
    int r = blockIdx.x * 8 + w;
    const float4* p = (const float4*)(g_xq + (size_t)r * XQ);
    float ss = 0.f;
    #pragma unroll
    for (int i = 0; i < 12; i++) {
        float4 v = p[lane + i*32];
        ss += v.x*v.x + v.y*v.y + v.z*v.z + v.w*v.w;
    }
    ss = warp_sum(ss);
    if (lane == 0) g_norm[r] = fmaxf(sqrtf(ss), 1e-8f);
}

__global__ void __launch_bounds__(256)
cos_k() {
    int w = threadIdx.x >> 5, lane = threadIdx.x & 31;
    int t = blockIdx.x * 8 + w;
    int b = blockIdx.y;
    if (t >= CS_TOT) return;
    int scale, i;
    if (t < 1023)      { scale = 1; i = t; }
    else if (t < 1534) { scale = 2; i = t - 1023; }
    else               { scale = 4; i = t - 1534; }
    int s0 = i * scale, s1 = s0 + scale;
    const float4* a = (const float4*)(g_xq + ((size_t)b*SS + s0) * XQ);
    const float4* c = (const float4*)(g_xq + ((size_t)b*SS + s1) * XQ);
    float d = 0.f;
    #pragma unroll
    for (int j = 0; j < 12; j++) {
        float4 av = a[lane + j*32];
        float4 cv = c[lane + j*32];
        d += av.x*cv.x + av.y*cv.y + av.z*cv.z + av.w*cv.w;
    }
    d = warp_sum(d);
    if (lane == 0)
        g_cs[b*CS_TOT + t] = d / (g_norm[b*SS + s0] * g_norm[b*SS + s1]);
}

__global__ void base_k() {
    int idx = blockIdx.x * 256 + threadIdx.x;
    if (idx >= NB*SM1) return;
    int b = idx / SM1, j = idx % SM1;
    const int Ls[3]   = {1023, 511, 255};
    const int offs[3] = {0, 1023, 1534};
    float acc = 0.f;
    #pragma unroll
    for (int u = 0; u < 3; u++) {
        int L = Ls[u];
        float ratio = (float)((double)L / 1023.0);
        float src = ((float)j + 0.5f) * ratio - 0.5f;
        src = fminf(fmaxf(src, 0.0f), (float)(L - 1));
        int i0 = (int)floorf(src);
        int i1 = min(i0 + 1, L - 1);
        float w = src - (float)i0;
        const float* cs = g_cs + b*CS_TOT + offs[u];
        acc += cs[i0] * (1.0f - w) + cs[i1] * w;
    }
    g_base[idx] = 0.5f * (1.0f - acc / 3.0f);
}

__global__ void __launch_bounds__(256)
learned_final_k(const float* __restrict__ detW3,
                const float* __restrict__ detb3) {
    int w = threadIdx.x >> 5, lane = threadIdx.x & 31;
    int r = blockIdx.x * 8 + w;
    if (r >= ROWS_DET) return;
    float sacc = 0.f;
    #pragma unroll
    for (int n = 0; n < 3; n++) {
        const float4* h2p = (const float4*)(g_h2 + ((size_t)n*ROWS_DET + r) * (DD/2));
        const float4* wp  = (const float4*)(detW3 + n*(DD/2));
        float part = 0.f;
        #pragma unroll
        for (int j = 0; j < 6; j++) {
            float4 a = h2p[lane + j*32];
            float4 b = wp[lane + j*32];
            part += a.x*b.x + a.y*b.y + a.z*b.z + a.w*b.w;
        }
        part = warp_sum(part);
        float t = part + detb3[n];
        sacc += 1.0f / (1.0f + expf(-t));
    }
    if (lane == 0)
        g_final[r] = 0.6f * g_base[r] + 0.4f * (sacc / 3.0f);
}

// parallel segmentation: integer scans (exact, order-independent)
__global__ void __launch_bounds__(SS)
seg_scan_k() {
    int b = blockIdx.x, t = threadIdx.x;
    __shared__ int sscan[SS];
    __shared__ int smax[SS];
    __shared__ int rmin[SS];
    float bv = (t == 0) ? 1.0f : g_final[b*SM1 + t - 1];
    int f = (t == 0) ? 1 : (bv > 0.5f ? 1 : 0);
    sscan[t] = f;
    smax[t]  = f ? t : -1;
    rmin[t]  = f ? t : SS;
    __syncthreads();
    for (int o = 1; o < SS; o <<= 1) {
        int vs = sscan[t];
        int vm = smax[t];
        int vr = rmin[t];
        int vs2 = (t >= o) ? sscan[t - o] : 0;
        int vm2 = (t >= o) ? smax[t - o]  : -1;
        int vr2 = (t + o < SS) ? rmin[t + o] : SS;
        __syncthreads();
        sscan[t] = vs + vs2;
        smax[t]  = max(vm, vm2);
        rmin[t]  = min(vr, vr2);
        __syncthreads();
    }
    int m = sscan[t] - 1;
    g_seg[b*SS + t] = m;
    g_qlo[b*SS + t] = smax[t];
    int hi = (t < SS - 1) ? rmin[t + 1] : SS;
    g_qhi[b*SS + t] = hi;
    if (t < MAXC) { g_segstart[b*MAXC + t] = 0; g_segcount[b*MAXC + t] = 0; }
    __syncthreads();
    if (f && m < MAXC) {
        g_segstart[b*MAXC + m] = t;
        g_segcount[b*MAXC + m] = hi - t;
    }
}

// fused segment attention: one warp per (b, s, h); fp32; writes fp16-split ctx
__global__ void __launch_bounds__(256)
seg_attn_k() {
    __shared__ float dots[8][SS];
    int w = threadIdx.x >> 5, lane = threadIdx.x & 31;
    int g = blockIdx.x * 8 + w;
    int h = g % NH;
    int s = (g / NH) & (SS - 1);
    int b = g / (NH * SS);
    int lo = g_qlo[b*SS + s], hi = g_qhi[b*SS + s];

    const float* qp = g_xq + ((size_t)(b*SS + s))*XQ + QOFF + h*HDIM + lane*4;
    float4 qv = *(const float4*)qp;
    const float scale = 0.088388347648318440550f;   // 1/sqrt(128)

    const float* kbase = g_xq + ((size_t)(b*SS))*XQ + QOFF + DD + h*HDIM + lane*4;
    float mx = -3.402823e38f;
    for (int k = lo; k < hi; k++) {
        float4 kv = *(const float4*)(kbase + (size_t)k*XQ);
        float d = qv.x*kv.x + qv.y*kv.y + qv.z*kv.z + qv.w*kv.w;
        d = warp_sum(d);
        d *= scale;
        if (lane == 0) dots[w][k - lo] = d;
        mx = fmaxf(mx, d);
    }
    __syncwarp();

    const float* vbase = g_xq + ((size_t)(b*SS))*XQ + QOFF + 2*DD + h*HDIM + lane*4;
    float4 acc = make_float4(0.f, 0.f, 0.f, 0.f);
    float sum = 0.f;
    for (int k = lo; k < hi; k++) {
        float e = expf(dots[w][k - lo] - mx);
        sum += e;
        float4 vv = *(const float4*)(vbase + (size_t)k*XQ);
        acc.x += e*vv.x; acc.y += e*vv.y; acc.z += e*vv.z; acc.w += e*vv.w;
    }
    float inv = 1.0f / sum;
    float c0 = acc.x*inv, c1 = acc.y*inv, c2 = acc.z*inv, c3 = acc.w*inv;

    __half* d = g_ctx2 + ((size_t)(b*SS + s))*(2*DD) + h*HDIM + lane*4;
    __half h0 = __float2half_rn(c0), h1 = __float2half_rn(c1);
    __half h2 = __float2half_rn(c2), h3 = __float2half_rn(c3);
    *(__half2*)(d)     = __halves2half2(h0, h1);
    *(__half2*)(d + 2) = __halves2half2(h2, h3);
    __half l0 = __float2half_rn(c0 - __half2float(h0));
    __half l1 = __float2half_rn(c1 - __half2float(h1));
    __half l2 = __float2half_rn(c2 - __half2float(h2));
    __half l3 = __float2half_rn(c3 - __half2float(h3));
    *(__half2*)(d + DD)     = __halves2half2(l0, l1);
    *(__half2*)(d + DD + 2) = __halves2half2(l2, l3);
}

// pooling + embeddings, float4 path, writes 2-way fp16 split chunk (half2 stores)
__global__ void __launch_bounds__(384)
chunk_k(const float* __restrict__ size_emb,
        const float* __restrict__ pos_enc) {
    int m = blockIdx.x, b = blockIdx.y;
    int cnt = g_segcount[b*MAXC + m];
    int st  = g_segstart[b*MAXC + m];
    int d4 = threadIdx.x;                     // 384 threads * 4 = 1536
    int d = d4 * 4;
    float4 v;
    if (cnt > 0) {
        float4 sum = make_float4(0.f, 0.f, 0.f, 0.f);
        for (int s = st; s < st + cnt; s++) {
            float4 a = *(const float4*)(g_attnout + ((size_t)b*SS + s)*DD + d);
            sum.x += a.x; sum.y += a.y; sum.z += a.z; sum.w += a.w;
        }
        int cl = min(cnt, 1023);
        float4 se = *(const float4*)(size_emb + (size_t)cl*DD + d);
        float ic = 1.0f / (float)cnt;
        v.x = sum.x*ic + se.x; v.y = sum.y*ic + se.y;
        v.z = sum.z*ic + se.z; v.w = sum.w*ic + se.w;
    } else v = make_float4(0.f, 0.f, 0.f, 0.f);
    float4 pe = *(const float4*)(pos_enc + (size_t)m*DD + d);
    v.x += pe.x; v.y += pe.y; v.z += pe.z; v.w += pe.w;
    __half h0 = __float2half_rn(v.x), h1 = __float2half_rn(v.y);
    __half h2 = __float2half_rn(v.z), h3 = __float2half_rn(v.w);
    __half l0 = __float2half_rn(v.x - __half2float(h0));
    __half l1 = __float2half_rn(v.y - __half2float(h1));
    __half l2 = __float2half_rn(v.z - __half2float(h2));
    __half l3 = __float2half_rn(v.w - __half2float(h3));
    __half* drow = g_chunk2 + ((size_t)b*MAXC + m) * (2*DD) + d;
    *(__half2*)(drow)          = __halves2half2(h0, h1);
    *(__half2*)(drow + 2)      = __halves2half2(h2, h3);
    *(__half2*)(drow + DD)     = __halves2half2(l0, l1);
    *(__half2*)(drow + DD + 2) = __halves2half2(l2, l3);
}

// final layernorm: one warp per row, float4
__global__ void __launch_bounds__(256)
ln_k(const float* __restrict__ gamma,
     const float* __restrict__ beta,
     float* __restrict__ out) {
    int w = threadIdx.x >> 5, lane = threadIdx.x & 31;
    int r = blockIdx.x * 8 + w;
    const float4* y = (const float4*)(g_y + (size_t)r*DD);
    float4 vv[12];
    float s = 0.f;
    #pragma unroll
    for (int j = 0; j < 12; j++) {
        vv[j] = y[lane + j*32];
        s += vv[j].x + vv[j].y + vv[j].z + vv[j].w;
    }
    s = warp_sum(s);
    float mu = s / (float)DD;
    float v2 = 0.f;
    #pragma unroll
    for (int j = 0; j < 12; j++) {
        float a = vv[j].x - mu, b = vv[j].y - mu, c = vv[j].z - mu, e = vv[j].w - mu;
        v2 += a*a + b*b + c*c + e*e;
    }
    v2 = warp_sum(v2);
    float inv = 1.0f / sqrtf(v2 / (float)DD + 1e-5f);
    const float4* gp = (const float4*)gamma;
    const float4* bp = (const float4*)beta;
    float4* op = (float4*)(out + (size_t)r*DD);
    #pragma unroll
    for (int j = 0; j < 12; j++) {
        float4 g4 = gp[lane + j*32];
        float4 b4 = bp[lane + j*32];
        float4 o4;
        o4.x = (vv[j].x - mu) * inv * g4.x + b4.x;
        o4.y = (vv[j].y - mu) * inv * g4.y + b4.y;
        o4.z = (vv[j].z - mu) * inv * g4.z + b4.z;
        o4.w = (vv[j].w - mu) * inv * g4.w + b4.w;
        op[lane + j*32] = o4;
    }
}

// ---------------- host launchers ----------------
struct GemmArgs {
    const __half *A, *B;
    const float* bias;
    float* C;
    __half* C2;
    int M, N, K, lda, ldb, ldc, segoff;
    float oscale;
    int npA, npB, splitN;
    long long sAi, sAo, sBi, sBo, sCi, sCo, sbias;
    int innerN, batch;
};

template<int ACT, int OMODE, int BIG>
static void tg_launch(const GemmArgs& a) {
    dim3 grid(a.N/128, (a.M + 127)/128, a.batch);
    tgemm_k<ACT,OMODE,BIG><<<grid,256,TG_SMEM>>>(a.A, a.B, a.bias, a.C, a.C2,
        a.M, a.K, a.lda, a.ldb, a.ldc, a.segoff, a.oscale,
        a.npA, a.npB, a.splitN,
        a.sAi, a.sAo, a.sBi, a.sBo, a.sCi, a.sCo, a.sbias, a.innerN);
}

static void split2(const float* src, __half* dst, long long rows, int cols, float scale) {
    long long total4 = rows * cols / 4;
    split2v_k<<<(unsigned)((total4 + 255)/256), 256>>>(src, dst, total4, cols/4, cols, scale);
}

#define NP3 3, 3, (1<<30)
#define NP2 2, 2, (1<<30)

extern "C" void kernel_launch(void* const* d_in, const int* in_sizes, int n_in,
                              void* d_out, int out_size) {
    const float* x         = (const float*)d_in[0];
    const float* Wp        = (const float*)d_in[1];
    const float* bp        = (const float*)d_in[2];
    const float* detW1     = (const float*)d_in[3];
    const float* detb1     = (const float*)d_in[4];
    const float* detW2     = (const float*)d_in[5];
    const float* detb2     = (const float*)d_in[6];
    const float* detW3     = (const float*)d_in[7];
    const float* detb3     = (const float*)d_in[8];
    const float* in_proj_w = (const float*)d_in[9];
    const float* in_proj_b = (const float*)d_in[10];
    const float* out_w     = (const float*)d_in[11];
    const float* out_b     = (const float*)d_in[12];
    const float* size_emb  = (const float*)d_in[13];
    const float* pos_enc   = (const float*)d_in[14];
    const float* procW1    = (const float*)d_in[15];
    const float* procb1    = (const float*)d_in[16];
    const float* procW2    = (const float*)d_in[17];
    const float* procb2    = (const float*)d_in[18];
    const float* ln_g      = (const float*)d_in[19];
    const float* ln_b      = (const float*)d_in[20];
    float* outp = (float*)d_out;

    cudaFuncSetAttribute(tgemm_k<0,0,0>, cudaFuncAttributeMaxDynamicSharedMemorySize, TG_SMEM);
    cudaFuncSetAttribute(tgemm_k<1,0,0>, cudaFuncAttributeMaxDynamicSharedMemorySize, TG_SMEM);
    cudaFuncSetAttribute(tgemm_k<1,1,0>, cudaFuncAttributeMaxDynamicSharedMemorySize, TG_SMEM);
    cudaFuncSetAttribute(tgemm_k<1,1,1>, cudaFuncAttributeMaxDynamicSharedMemorySize, TG_SMEM);

    void *p;
    cudaGetSymbolAddress(&p, g_xq);      float* xq      = (float*)p;
    cudaGetSymbolAddress(&p, g_bc);      float* bc      = (float*)p;
    cudaGetSymbolAddress(&p, g_h2);      float* h2      = (float*)p;
    cudaGetSymbolAddress(&p, g_attnout); float* attnout = (float*)p;
    cudaGetSymbolAddress(&p, g_y);       float* yb      = (float*)p;
    cudaGetSymbolAddress(&p, g_x2);      __half* x2     = (__half*)p;
    cudaGetSymbolAddress(&p, g_wc2);     __half* wc2    = (__half*)p;
    cudaGetSymbolAddress(&p, g_dW1_2);   __half* dW1_2  = (__half*)p;
    cudaGetSymbolAddress(&p, g_h1_2);    __half* h1_2   = (__half*)p;
    cudaGetSymbolAddress(&p, g_dW2_2);   __half* dW2_2  = (__half*)p;
    cudaGetSymbolAddress(&p, g_ctx2);    __half* ctx2   = (__half*)p;
    cudaGetSymbolAddress(&p, g_outw2);   __half* outw2  = (__half*)p;
    cudaGetSymbolAddress(&p, g_chunk2);  __half* chunk2 = (__half*)p;
    cudaGetSymbolAddress(&p, g_pw1_2);   __half* pw1_2  = (__half*)p;
    cudaGetSymbolAddress(&p, g_hproc2);  __half* hproc2 = (__half*)p;
    cudaGetSymbolAddress(&p, g_pw2_2);   __half* pw2_2  = (__half*)p;

    // ===== input splits (weights scaled by 64 to keep fp16 lo plane normal) =====
    split2(x, x2, NB*SS, DD, 1.0f);
    split2(Wp, wc2, DD, DD, WSCALE);                            // rows 0..1535 of combined W
    split2(in_proj_w, wc2 + (size_t)DD*2*DD, 3*DD, DD, WSCALE); // rows 1536..6143
    split2(detW1, dW1_2, 3*DD, 2*DD, WSCALE);
    split2(detW2, dW2_2, 3*(DD/2), DD, WSCALE);
    split2(out_w, outw2, DD, DD, WSCALE);
    split2(procW1, pw1_2, 2*DD, DD, WSCALE);
    split2(procW2, pw2_2, DD, 2*DD, WSCALE);
    biascat_k<<<(XQ + 255)/256, 256>>>(bp, in_proj_b);

    // ===== merged xling|qkv GEMM: 3 products for n<1536 (boundary), 2 for qkv =====
    { GemmArgs a = { x2, wc2, bc, xq, nullptr, NB*SS, XQ, DD, 2*DD, 2*DD, XQ, 0,
                     OSINV, 3, 2, DD, 0,0,0,0,0,0,0, 1, 1 };
      tg_launch<0,0,0>(a); }

    // ===== boundary path (np=3 -> GEMMs bit-identical) =====
    norm_k<<<NB*SS/8, 256>>>();
    cos_k<<<dim3((CS_TOT + 7)/8, NB), 256>>>();
    base_k<<<(NB*SM1 + 255)/256, 256>>>();
    // h1 = gelu(bi @ detW1[n]^T + b) -> 2-way split directly; A gathered from x2 (BIG=1)
    { GemmArgs a = { x2, dW1_2, detb1, nullptr, h1_2, ROWS_DET, DD, 2*DD,
                     2*DD, 2*2*DD, 2*DD, DD, OSINV, NP3,
                     0, 0, (long long)DD*2*2*DD, 0,
                     (long long)ROWS_DET*2*DD, 0, DD, 3, 3 };
      tg_launch<1,1,1>(a); }
    // h2 = gelu(h1 @ detW2[n]^T + b) fp32
    { GemmArgs a = { h1_2, dW2_2, detb2, h2, nullptr, ROWS_DET, DD/2, DD,
                     2*DD, 2*DD, DD/2, 0, OSINV, NP3,
                     (long long)ROWS_DET*2*DD, 0, (long long)(DD/2)*2*DD, 0,
                     (long long)ROWS_DET*(DD/2), 0, DD/2, 3, 3 };
      tg_launch<1,0,0>(a); }
    learned_final_k<<<(ROWS_DET + 7)/8, 256>>>(detW3, detb3);
    seg_scan_k<<<NB, SS>>>();

    // ===== continuous path (np=2) =====
    seg_attn_k<<<NB*SS*NH/8, 256>>>();
    // attn_out = ctx @ out_w^T + out_b
    { GemmArgs a = { ctx2, outw2, out_b, attnout, nullptr, NB*SS, DD, DD,
                     2*DD, 2*DD, DD, 0, OSINV, NP2, 0,0,0,0,0,0,0, 1, 1 };
      tg_launch<0,0,0>(a); }
    chunk_k<<<dim3(MAXC, NB), 384>>>(size_emb, pos_enc);
    // hproc = gelu(chunk @ procW1^T + b) -> 2-way split directly
    { GemmArgs a = { chunk2, pw1_2, procb1, nullptr, hproc2, NB*MAXC, 2*DD, DD,
                     2*DD, 2*DD, 2*2*DD, 2*DD, OSINV, NP2, 0,0,0,0,0,0,0, 1, 1 };
      tg_launch<1,1,0>(a); }
    // y = hproc @ procW2^T + b
    { GemmArgs a = { hproc2, pw2_2, procb2, yb, nullptr, NB*MAXC, DD, 2*DD,
                     2*2*DD, 2*2*DD, DD, 0, OSINV, NP2, 0,0,0,0,0,0,0, 1, 1 };
      tg_launch<0,0,0>(a); }
    ln_k<<<NB*MAXC/8, 256>>>(ln_g, ln_b, outp);
}

// round 16
// speedup vs baseline: 1.2134x; 1.0077x over previous
#include <cuda_runtime.h>
#include <cuda_fp16.h>
#include <math.h>
#include <stdint.h>

// ---------------- problem constants ----------------
#define NB 4
#define SS 1024
#define DD 1536
#define NH 12
#define HDIM 128
#define MAXC 256
#define SM1 1023
#define ROWS_DET (NB*SM1)        // 4092
#define CS_TOT (1023+511+255)    // 1789
#define XQ 6144                  // combined xling|qkv row width
#define QOFF 1536                // qkv column offset in combined buffer

#define WSCALE 64.0f
#define OSINV  0.015625f         // 1/64

// ---------------- fp32 scratch ----------------
__device__ float g_xq[(size_t)NB*SS*XQ];       // [.,0:1536)=xling, [.,1536:6144)=qkv
__device__ float g_bc[XQ];                     // combined bias
__device__ float g_norm[NB*SS];
__device__ float g_cs[NB*CS_TOT];
__device__ float g_base[NB*SM1];
__device__ float g_h2[(size_t)3*ROWS_DET*(DD/2)];
__device__ float g_final[NB*SM1];
__device__ int   g_seg[NB*SS];
__device__ int   g_qlo[NB*SS];
__device__ int   g_qhi[NB*SS];
__device__ int   g_segstart[NB*MAXC];
__device__ int   g_segcount[NB*MAXC];
__device__ float g_attnout[(size_t)NB*SS*DD];
__device__ float g_y[(size_t)NB*MAXC*DD];

// ---------------- fp16 2-way split scratch [rows][2K] (hi|lo) ----------------
__device__ __half g_x2[(size_t)NB*SS*2*DD];
__device__ __half g_wc2[(size_t)XQ*2*DD];      // combined [Wp | in_proj_w] split
__device__ __half g_dW1_2[(size_t)3*DD*2*(2*DD)];
__device__ __half g_h1_2[(size_t)3*ROWS_DET*2*DD];
__device__ __half g_dW2_2[(size_t)3*(DD/2)*2*DD];
__device__ __half g_ctx2[(size_t)NB*SS*2*DD];
__device__ __half g_outw2[(size_t)DD*2*DD];
__device__ __half g_chunk2[(size_t)NB*MAXC*2*DD];
__device__ __half g_pw1_2[(size_t)2*DD*2*DD];
__device__ __half g_hproc2[(size_t)NB*MAXC*2*2*DD];
__device__ __half g_pw2_2[(size_t)DD*2*2*DD];

__device__ __forceinline__ float gelu_exact(float v) {
    return 0.5f * v * (1.0f + erff(v * 0.70710678118654752440f));
}
__device__ __forceinline__ uint32_t smem_u32(const void* p) {
    uint32_t a;
    asm("{ .reg .u64 t; cvta.to.shared.u64 t, %1; cvt.u32.u64 %0, t; }" : "=r"(a) : "l"(p));
    return a;
}
__device__ __forceinline__ float warp_sum(float v) {
    #pragma unroll
    for (int o = 16; o > 0; o >>= 1) v += __shfl_xor_sync(0xffffffffu, v, o);
    return v;
}

#define LDSM4(r0,r1,r2,r3,addr) \
    asm volatile("ldmatrix.sync.aligned.m8n8.x4.shared.b16 {%0,%1,%2,%3}, [%4];" \
        : "=r"(r0), "=r"(r1), "=r"(r2), "=r"(r3) : "r"(addr))

#define MMA16816(d, a, b0, b1) \
    asm volatile("mma.sync.aligned.m16n8k16.row.col.f32.f16.f16.f32 " \
        "{%0,%1,%2,%3},{%4,%5,%6,%7},{%8,%9},{%0,%1,%2,%3};" \
        : "+f"((d)[0]), "+f"((d)[1]), "+f"((d)[2]), "+f"((d)[3]) \
        : "r"((a)[0]), "r"((a)[1]), "r"((a)[2]), "r"((a)[3]), "r"(b0), "r"(b1))

#define CP_ASYNC16(dst, src, sz) \
    asm volatile("cp.async.ca.shared.global [%0], [%1], 16, %2;" :: "r"(dst), "l"(src), "r"(sz))
#define CP_COMMIT() asm volatile("cp.async.commit_group;" ::: "memory")
#define CP_WAIT1() asm volatile("cp.async.wait_group 1;" ::: "memory")
#define CP_WAIT0() asm volatile("cp.async.wait_group 0;" ::: "memory")

// ================= mma.sync fp16 split GEMM (2-stage, K64, 2 CTAs/SM) =================
// A[M][2K] (hi|lo), B[N][2K] (hi|lo).
// np = (n0 < splitN) ? npA : npB.
//   np=3: Ah.Bh + Ah.Bl + Al.Bh
//   np=2: Ah.Bh + Ah.Bl           (weights full precision, data fp16-truncated)
// BIG=1: A is g_x2; rows are bigrams (b,s); chunk selects x_s / x_{s+1}.
#define RSTRIDE 144
#define ATILE (128*RSTRIDE)        // 18432
#define BUFSZ (2*ATILE)            // 36864
#define TG_SMEM (2*BUFSZ)          // 73728

template<int ACT, int OMODE, int BIG>
__global__ void __launch_bounds__(256)
tgemm_k(const __half* __restrict__ A, const __half* __restrict__ B,
        const float* __restrict__ bias, float* __restrict__ C, __half* __restrict__ C2,
        int M, int K, int lda, int ldb, int ldc, int segoff, float oscale,
        int npA, int npB, int splitN,
        long long sAi, long long sAo, long long sBi, long long sBo,
        long long sCi, long long sCo, long long sbias, int innerN)
{
    const int segA_[3] = {0,0,1};
    const int segB_[3] = {0,1,0};
    extern __shared__ char smem[];
    uint32_t sb = smem_u32(smem);
    int tid = threadIdx.x;
    int z = blockIdx.z, zi = z % innerN, zo = z / innerN;
    if (!BIG) A += (size_t)(zi*sAi + zo*sAo);
    B += (size_t)(zi*sBi + zo*sBo);
    if (OMODE == 0) C  += (size_t)(zi*sCi + zo*sCo);
    else            C2 += (size_t)(zi*sCi + zo*sCo);
    int m0 = blockIdx.y * 128, n0 = blockIdx.x * 128;

    const int KPC = K >> 6;
    const int NP = (n0 < splitN) ? npA : npB;
    const int NC = NP * KPC;

    // per-thread A-load slots (row/col fixed across chunks)
    int arow_[4]; uint32_t asz_[4]; long long aoff_[4]; int ac_[4];
    #pragma unroll
    for (int i = 0; i < 4; i++) {
        int f = tid + (i << 8);
        int row = f >> 3, c = f & 7;
        int gr = m0 + row;
        int grc = gr < M ? gr : (M - 1);
        arow_[i] = row; ac_[i] = c;
        asz_[i] = gr < M ? 16u : 0u;
        if (BIG) {
            int b = grc / SM1, s = grc % SM1;
            aoff_[i] = (long long)(b*SS + s) * (2*DD);
        } else {
            aoff_[i] = (long long)grc * lda;
        }
    }

    auto issue = [&](int kc, int buf) {
        int p = kc / KPC;
        int k0 = (kc - p * KPC) << 6;
        uint32_t sA = sb + buf * BUFSZ;
        uint32_t sB = sA + ATILE;
        if (BIG) {
            int side = (k0 >= DD) ? 1 : 0;
            long long cofs = (long long)side*(2*DD) + segA_[p]*DD + (k0 - side*DD);
            #pragma unroll
            for (int i = 0; i < 4; i++) {
                const void* src = A + aoff_[i] + cofs + ac_[i] * 8;
                CP_ASYNC16(sA + arow_[i] * RSTRIDE + ac_[i] * 16, src, asz_[i]);
            }
        } else {
            const __half* Ap = A + (size_t)segA_[p] * K + k0;
            #pragma unroll
            for (int i = 0; i < 4; i++) {
                const void* src = Ap + aoff_[i] + ac_[i] * 8;
                CP_ASYNC16(sA + arow_[i] * RSTRIDE + ac_[i] * 16, src, asz_[i]);
            }
        }
        const __half* Bp = B + (size_t)segB_[p] * K + k0;
        #pragma unroll
        for (int i = 0; i < 4; i++) {
            int f = tid + (i << 8);
            int row = f >> 3, c = f & 7;
            const void* src = Bp + (size_t)(n0 + row) * ldb + c * 8;
            CP_ASYNC16(sB + row * RSTRIDE + c * 16, src, 16u);
        }
    };

    int lane = tid & 31, w = tid >> 5;
    int wm = w & 1, wn = w >> 1;
    uint32_t a_row = ((lane >> 3) & 1) * 8 + (lane & 7);
    uint32_t a_cs  = lane >> 4;
    uint32_t b_row = (lane >> 4) * 8 + (lane & 7);
    uint32_t b_cs  = (lane >> 3) & 1;

    float acc[4][4][4];
    #pragma unroll
    for (int i = 0; i < 4; i++)
        #pragma unroll
        for (int j = 0; j < 4; j++)
            #pragma unroll
            for (int r = 0; r < 4; r++) acc[i][j][r] = 0.f;

    issue(0, 0);
    CP_COMMIT();

    for (int kc = 0; kc < NC; kc++) {
        int cur = kc & 1;
        if (kc + 1 < NC) { issue(kc + 1, cur ^ 1); CP_COMMIT(); CP_WAIT1(); }
        else             { CP_WAIT0(); }
        __syncthreads();

        uint32_t sA = sb + cur * BUFSZ;
        uint32_t sB = sA + ATILE;
        #pragma unroll
        for (int ks = 0; ks < 4; ks++) {
            uint32_t av[4][4], bv[2][4];
            #pragma unroll
            for (int mt = 0; mt < 4; mt++) {
                uint32_t ad = sA + (wm*64 + mt*16 + a_row) * RSTRIDE + ((ks*2 + a_cs) << 4);
                LDSM4(av[mt][0], av[mt][1], av[mt][2], av[mt][3], ad);
            }
            #pragma unroll
            for (int bt = 0; bt < 2; bt++) {
                uint32_t bd = sB + (wn*32 + bt*16 + b_row) * RSTRIDE + ((ks*2 + b_cs) << 4);
                LDSM4(bv[bt][0], bv[bt][1], bv[bt][2], bv[bt][3], bd);
            }
            #pragma unroll
            for (int mt = 0; mt < 4; mt++)
                #pragma unroll
                for (int nt = 0; nt < 4; nt++) {
                    uint32_t b0 = bv[nt >> 1][(nt & 1) * 2];
                    uint32_t b1 = bv[nt >> 1][(nt & 1) * 2 + 1];
                    MMA16816(acc[mt][nt], av[mt], b0, b1);
                }
        }
        __syncthreads();
    }

    // ---- epilogue ----
    if (bias) bias += (size_t)z * (size_t)sbias;
    #pragma unroll
    for (int mt = 0; mt < 4; mt++) {
        int r0 = m0 + wm*64 + mt*16 + (lane >> 2);
        #pragma unroll
        for (int nt = 0; nt < 4; nt++) {
            int col = n0 + wn*32 + nt*8 + (lane & 3)*2;
            float bb0 = 0.f, bb1 = 0.f;
            if (bias) { bb0 = bias[col]; bb1 = bias[col+1]; }
            #pragma unroll
            for (int half_ = 0; half_ < 2; half_++) {
                int r = r0 + half_*8;
                if (r >= M) continue;
                float v0 = acc[mt][nt][half_*2]   * oscale + bb0;
                float v1 = acc[mt][nt][half_*2+1] * oscale + bb1;
                if (ACT == 1) { v0 = gelu_exact(v0); v1 = gelu_exact(v1); }
                if (OMODE == 0) {
                    *(float2*)(C + (size_t)r*ldc + col) = make_float2(v0, v1);
                } else {
                    __half* d = C2 + (size_t)r*ldc + col;
                    __half h0 = __float2half_rn(v0);
                    __half h1 = __float2half_rn(v1);
                    __half l0 = __float2half_rn(v0 - __half2float(h0));
                    __half l1 = __float2half_rn(v1 - __half2float(h1));
                    *(__half2*)(d)          = __halves2half2(h0, h1);
                    *(__half2*)(d + segoff) = __halves2half2(l0, l1);
                }
            }
        }
    }
}

// ============ fused split: all 9 input splits + biascat in ONE launch ============
// Per-element math identical to round-15 split2v_k -> bit-identical outputs.
__device__ __forceinline__ void split4_do(const float* __restrict__ src,
                                          __half* __restrict__ dst,
                                          long long l4, int C4, int C, float scale) {
    long long r = l4 / C4;
    int c = (int)(l4 - r * C4) * 4;
    float4 v = *(const float4*)(src + r * C + c);
    v.x *= scale; v.y *= scale; v.z *= scale; v.w *= scale;
    __half h0 = __float2half_rn(v.x), h1 = __float2half_rn(v.y);
    __half h2 = __float2half_rn(v.z), h3 = __float2half_rn(v.w);
    __half l0 = __float2half_rn(v.x - __half2float(h0));
    __half l1 = __float2half_rn(v.y - __half2float(h1));
    __half l2 = __float2half_rn(v.z - __half2float(h2));
    __half l3 = __float2half_rn(v.w - __half2float(h3));
    __half* d = dst + r * (2LL*C) + c;
    *(__half2*)(d)         = __halves2half2(h0, h1);
    *(__half2*)(d + 2)     = __halves2half2(h2, h3);
    *(__half2*)(d + C)     = __halves2half2(l0, l1);
    *(__half2*)(d + C + 2) = __halves2half2(l2, l3);
}

// segment boundaries in float4 units (compile-time)
#define SP_X   1572864LL                      // x: 4096*1536/4
#define SP_WP  (SP_X  + 589824LL)             // Wp: 1536*1536/4
#define SP_IPW (SP_WP + 1769472LL)            // in_proj: 4608*1536/4
#define SP_DW1 (SP_IPW + 3538944LL)           // detW1: 4608*3072/4
#define SP_DW2 (SP_DW1 + 884736LL)            // detW2: 2304*1536/4
#define SP_OW  (SP_DW2 + 589824LL)            // out_w: 1536*1536/4
#define SP_PW1 (SP_OW  + 1179648LL)           // procW1: 3072*1536/4
#define SP_PW2 (SP_PW1 + 1179648LL)           // procW2: 1536*3072/4
#define SP_BC  (SP_PW2 + (XQ/4))              // biascat tail: 1536 idx4
#define SP_BLOCKS ((unsigned)((SP_BC + 255) / 256))

__global__ void __launch_bounds__(256)
fused_split_k(const float* __restrict__ x,   const float* __restrict__ Wp,
              const float* __restrict__ ipw, const float* __restrict__ dW1,
              const float* __restrict__ dW2, const float* __restrict__ outw,
              const float* __restrict__ pw1, const float* __restrict__ pw2,
              const float* __restrict__ bp,  const float* __restrict__ ipb)
{
    long long i = (long long)blockIdx.x * 256 + threadIdx.x;
    if (i < SP_X) {
        split4_do(x, g_x2, i, DD/4, DD, 1.0f);
    } else if (i < SP_WP) {
        split4_do(Wp, g_wc2, i - SP_X, DD/4, DD, WSCALE);
    } else if (i < SP_IPW) {
        split4_do(ipw, g_wc2 + (size_t)DD*2*DD, i - SP_WP, DD/4, DD, WSCALE);
    } else if (i < SP_DW1) {
        split4_do(dW1, g_dW1_2, i - SP_IPW, (2*DD)/4, 2*DD, WSCALE);
    } else if (i < SP_DW2) {
        split4_do(dW2, g_dW2_2, i - SP_DW1, DD/4, DD, WSCALE);
    } else if (i < SP_OW) {
        split4_do(outw, g_outw2, i - SP_DW2, DD/4, DD, WSCALE);
    } else if (i < SP_PW1) {
        split4_do(pw1, g_pw1_2, i - SP_OW, DD/4, DD, WSCALE);
    } else if (i < SP_PW2) {
        split4_do(pw2, g_pw2_2, i - SP_PW1, (2*DD)/4, 2*DD, WSCALE);
    } else if (i < SP_BC) {
        int j = (int)(i - SP_PW2) * 4;
        #pragma unroll
        for (int u = 0; u < 4; u++) {
            int idx = j + u;
            g_bc[idx] = (idx < DD) ? bp[idx] : ipb[idx - DD];
        }
    }
}

// ---------------- warp-per-row reductions ----------------
__global__ void __launch_bounds__(256)
norm_k() {
    int w = threadIdx.x >> 5, lane = threadIdx.x & 31;
    int r = blockIdx.x * 8 + w;
    const float4* p = (const float4*)(g_xq + (size_t)r * XQ);
    float ss = 0.f;
    #pragma unroll
    for (int i = 0; i < 12; i++) {
        float4 v = p[lane + i*32];
        ss += v.x*v.x + v.y*v.y + v.z*v.z + v.w*v.w;
    }
    ss = warp_sum(ss);
    if (lane == 0) g_norm[r] = fmaxf(sqrtf(ss), 1e-8f);
}

__global__ void __launch_bounds__(256)
cos_k() {
    int w = threadIdx.x >> 5, lane = threadIdx.x & 31;
    int t = blockIdx.x * 8 + w;
    int b = blockIdx.y;
    if (t >= CS_TOT) return;
    int scale, i;
    if (t < 1023)      { scale = 1; i = t; }
    else if (t < 1534) { scale = 2; i = t - 1023; }
    else               { scale = 4; i = t - 1534; }
    int s0 = i * scale, s1 = s0 + scale;
    const float4* a = (const float4*)(g_xq + ((size_t)b*SS + s0) * XQ);
    const float4* c = (const float4*)(g_xq + ((size_t)b*SS + s1) * XQ);
    float d = 0.f;
    #pragma unroll
    for (int j = 0; j < 12; j++) {
        float4 av = a[lane + j*32];
        float4 cv = c[lane + j*32];
        d += av.x*cv.x + av.y*cv.y + av.z*cv.z + av.w*cv.w;
    }
    d = warp_sum(d);
    if (lane == 0)
        g_cs[b*CS_TOT + t] = d / (g_norm[b*SS + s0] * g_norm[b*SS + s1]);
}

__global__ void base_k() {
    int idx = blockIdx.x * 256 + threadIdx.x;
    if (idx >= NB*SM1) return;
    int b = idx / SM1, j = idx % SM1;
    const int Ls[3]   = {1023, 511, 255};
    const int offs[3] = {0, 1023, 1534};
    float acc = 0.f;
    #pragma unroll
    for (int u = 0; u < 3; u++) {
        int L = Ls[u];
        float ratio = (float)((double)L / 1023.0);
        float src = ((float)j + 0.5f) * ratio - 0.5f;
        src = fminf(fmaxf(src, 0.0f), (float)(L - 1));
        int i0 = (int)floorf(src);
        int i1 = min(i0 + 1, L - 1);
        float w = src - (float)i0;
        const float* cs = g_cs + b*CS_TOT + offs[u];
        acc += cs[i0] * (1.0f - w) + cs[i1] * w;
    }
    g_base[idx] = 0.5f * (1.0f - acc / 3.0f);
}

__global__ void __launch_bounds__(256)
learned_final_k(const float* __restrict__ detW3,
                const float* __restrict__ detb3) {
    int w = threadIdx.x >> 5, lane = threadIdx.x & 31;
    int r = blockIdx.x * 8 + w;
    if (r >= ROWS_DET) return;
    float sacc = 0.f;
    #pragma unroll
    for (int n = 0; n < 3; n++) {
        const float4* h2p = (const float4*)(g_h2 + ((size_t)n*ROWS_DET + r) * (DD/2));
        const float4* wp  = (const float4*)(detW3 + n*(DD/2));
        float part = 0.f;
        #pragma unroll
        for (int j = 0; j < 6; j++) {
            float4 a = h2p[lane + j*32];
            float4 b = wp[lane + j*32];
            part += a.x*b.x + a.y*b.y + a.z*b.z + a.w*b.w;
        }
        part = warp_sum(part);
        float t = part + detb3[n];
        sacc += 1.0f / (1.0f + expf(-t));
    }
    if (lane == 0)
        g_final[r] = 0.6f * g_base[r] + 0.4f * (sacc / 3.0f);
}

// parallel segmentation: integer scans (exact, order-independent)
__global__ void __launch_bounds__(SS)
seg_scan_k() {
    int b = blockIdx.x, t = threadIdx.x;
    __shared__ int sscan[SS];
    __shared__ int smax[SS];
    __shared__ int rmin[SS];
    float bv = (t == 0) ? 1.0f : g_final[b*SM1 + t - 1];
    int f = (t == 0) ? 1 : (bv > 0.5f ? 1 : 0);
    sscan[t] = f;
    smax[t]  = f ? t : -1;
    rmin[t]  = f ? t : SS;
    __syncthreads();
    for (int o = 1; o < SS; o <<= 1) {
        int vs = sscan[t];
        int vm = smax[t];
        int vr = rmin[t];
        int vs2 = (t >= o) ? sscan[t - o] : 0;
        int vm2 = (t >= o) ? smax[t - o]  : -1;
        int vr2 = (t + o < SS) ? rmin[t + o] : SS;
        __syncthreads();
        sscan[t] = vs + vs2;
        smax[t]  = max(vm, vm2);
        rmin[t]  = min(vr, vr2);
        __syncthreads();
    }
    int m = sscan[t] - 1;
    g_seg[b*SS + t] = m;
    g_qlo[b*SS + t] = smax[t];
    int hi = (t < SS - 1) ? rmin[t + 1] : SS;
    g_qhi[b*SS + t] = hi;
    if (t < MAXC) { g_segstart[b*MAXC + t] = 0; g_segcount[b*MAXC + t] = 0; }
    __syncthreads();
    if (f && m < MAXC) {
        g_segstart[b*MAXC + m] = t;
        g_segcount[b*MAXC + m] = hi - t;
    }
}

// fused segment attention: one warp per (b, s, h); fp32; writes fp16-split ctx
__global__ void __launch_bounds__(256)
seg_attn_k() {
    __shared__ float dots[8][SS];
    int w = threadIdx.x >> 5, lane = threadIdx.x & 31;
    int g = blockIdx.x * 8 + w;
    int h = g % NH;
    int s = (g / NH) & (SS - 1);
    int b = g / (NH * SS);
    int lo = g_qlo[b*SS + s], hi = g_qhi[b*SS + s];

    const float* qp = g_xq + ((size_t)(b*SS + s))*XQ + QOFF + h*HDIM + lane*4;
    float4 qv = *(const float4*)qp;
    const float scale = 0.088388347648318440550f;   // 1/sqrt(128)

    const float* kbase = g_xq + ((size_t)(b*SS))*XQ + QOFF + DD + h*HDIM + lane*4;
    float mx = -3.402823e38f;
    for (int k = lo; k < hi; k++) {
        float4 kv = *(const float4*)(kbase + (size_t)k*XQ);
        float d = qv.x*kv.x + qv.y*kv.y + qv.z*kv.z + qv.w*kv.w;
        d = warp_sum(d);
        d *= scale;
        if (lane == 0) dots[w][k - lo] = d;
        mx = fmaxf(mx, d);
    }
    __syncwarp();

    const float* vbase = g_xq + ((size_t)(b*SS))*XQ + QOFF + 2*DD + h*HDIM + lane*4;
    float4 acc = make_float4(0.f, 0.f, 0.f, 0.f);
    float sum = 0.f;
    for (int k = lo; k < hi; k++) {
        float e = expf(dots[w][k - lo] - mx);
        sum += e;
        float4 vv = *(const float4*)(vbase + (size_t)k*XQ);
        acc.x += e*vv.x; acc.y += e*vv.y; acc.z += e*vv.z; acc.w += e*vv.w;
    }
    float inv = 1.0f / sum;
    float c0 = acc.x*inv, c1 = acc.y*inv, c2 = acc.z*inv, c3 = acc.w*inv;

    __half* d = g_ctx2 + ((size_t)(b*SS + s))*(2*DD) + h*HDIM + lane*4;
    __half h0 = __float2half_rn(c0), h1 = __float2half_rn(c1);
    __half h2 = __float2half_rn(c2), h3 = __float2half_rn(c3);
    *(__half2*)(d)     = __halves2half2(h0, h1);
    *(__half2*)(d + 2) = __halves2half2(h2, h3);
    __half l0 = __float2half_rn(c0 - __half2float(h0));
    __half l1 = __float2half_rn(c1 - __half2float(h1));
    __half l2 = __float2half_rn(c2 - __half2float(h2));
    __half l3 = __float2half_rn(c3 - __half2float(h3));
    *(__half2*)(d + DD)     = __halves2half2(l0, l1);
    *(__half2*)(d + DD + 2) = __halves2half2(l2, l3);
}

// pooling + embeddings, float4 path, writes 2-way fp16 split chunk (half2 stores)
__global__ void __launch_bounds__(384)
chunk_k(const float* __restrict__ size_emb,
        const float* __restrict__ pos_enc) {
    int m = blockIdx.x, b = blockIdx.y;
    int cnt = g_segcount[b*MAXC + m];
    int st  = g_segstart[b*MAXC + m];
    int d = threadIdx.x * 4;
    float4 v;
    if (cnt > 0) {
        float4 sum = make_float4(0.f, 0.f, 0.f, 0.f);
        for (int s = st; s < st + cnt; s++) {
            float4 a = *(const float4*)(g_attnout + ((size_t)b*SS + s)*DD + d);
            sum.x += a.x; sum.y += a.y; sum.z += a.z; sum.w += a.w;
        }
        int cl = min(cnt, 1023);
        float4 se = *(const float4*)(size_emb + (size_t)cl*DD + d);
        float ic = 1.0f / (float)cnt;
        v.x = sum.x*ic + se.x; v.y = sum.y*ic + se.y;
        v.z = sum.z*ic + se.z; v.w = sum.w*ic + se.w;
    } else v = make_float4(0.f, 0.f, 0.f, 0.f);
    float4 pe = *(const float4*)(pos_enc + (size_t)m*DD + d);
    v.x += pe.x; v.y += pe.y; v.z += pe.z; v.w += pe.w;
    __half h0 = __float2half_rn(v.x), h1 = __float2half_rn(v.y);
    __half h2 = __float2half_rn(v.z), h3 = __float2half_rn(v.w);
    __half l0 = __float2half_rn(v.x - __half2float(h0));
    __half l1 = __float2half_rn(v.y - __half2float(h1));
    __half l2 = __float2half_rn(v.z - __half2float(h2));
    __half l3 = __float2half_rn(v.w - __half2float(h3));
    __half* drow = g_chunk2 + ((size_t)b*MAXC + m) * (2*DD) + d;
    *(__half2*)(drow)          = __halves2half2(h0, h1);
    *(__half2*)(drow + 2)      = __halves2half2(h2, h3);
    *(__half2*)(drow + DD)     = __halves2half2(l0, l1);
    *(__half2*)(drow + DD + 2) = __halves2half2(l2, l3);
}

// final layernorm: one warp per row, float4
__global__ void __launch_bounds__(256)
ln_k(const float* __restrict__ gamma,
     const float* __restrict__ beta,
     float* __restrict__ out) {
    int w = threadIdx.x >> 5, lane = threadIdx.x & 31;
    int r = blockIdx.x * 8 + w;
    const float4* y = (const float4*)(g_y + (size_t)r*DD);
    float4 vv[12];
    float s = 0.f;
    #pragma unroll
    for (int j = 0; j < 12; j++) {
        vv[j] = y[lane + j*32];
        s += vv[j].x + vv[j].y + vv[j].z + vv[j].w;
    }
    s = warp_sum(s);
    float mu = s / (float)DD;
    float v2 = 0.f;
    #pragma unroll
    for (int j = 0; j < 12; j++) {
        float a = vv[j].x - mu, b = vv[j].y - mu, c = vv[j].z - mu, e = vv[j].w - mu;
        v2 += a*a + b*b + c*c + e*e;
    }
    v2 = warp_sum(v2);
    float inv = 1.0f / sqrtf(v2 / (float)DD + 1e-5f);
    const float4* gp = (const float4*)gamma;
    const float4* bp = (const float4*)beta;
    float4* op = (float4*)(out + (size_t)r*DD);
    #pragma unroll
    for (int j = 0; j < 12; j++) {
        float4 g4 = gp[lane + j*32];
        float4 b4 = bp[lane + j*32];
        float4 o4;
        o4.x = (vv[j].x - mu) * inv * g4.x + b4.x;
        o4.y = (vv[j].y - mu) * inv * g4.y + b4.y;
        o4.z = (vv[j].z - mu) * inv * g4.z + b4.z;
        o4.w = (vv[j].w - mu) * inv * g4.w + b4.w;
        op[lane + j*32] = o4;
    }
}

// ---------------- host launchers ----------------
struct GemmArgs {
    const __half *A, *B;
    const float* bias;
    float* C;
    __half* C2;
    int M, N, K, lda, ldb, ldc, segoff;
    float oscale;
    int npA, npB, splitN;
    long long sAi, sAo, sBi, sBo, sCi, sCo, sbias;
    int innerN, batch;
};

template<int ACT, int OMODE, int BIG>
static void tg_launch(const GemmArgs& a) {
    dim3 grid(a.N/128, (a.M + 127)/128, a.batch);
    tgemm_k<ACT,OMODE,BIG><<<grid,256,TG_SMEM>>>(a.A, a.B, a.bias, a.C, a.C2,
        a.M, a.K, a.lda, a.ldb, a.ldc, a.segoff, a.oscale,
        a.npA, a.npB, a.splitN,
        a.sAi, a.sAo, a.sBi, a.sBo, a.sCi, a.sCo, a.sbias, a.innerN);
}

#define NP3 3, 3, (1<<30)
#define NP2 2, 2, (1<<30)

extern "C" void kernel_launch(void* const* d_in, const int* in_sizes, int n_in,
                              void* d_out, int out_size) {
    const float* x         = (const float*)d_in[0];
    const float* Wp        = (const float*)d_in[1];
    const float* bp        = (const float*)d_in[2];
    const float* detW1     = (const float*)d_in[3];
    const float* detb1     = (const float*)d_in[4];
    const float* detW2     = (const float*)d_in[5];
    const float* detb2     = (const float*)d_in[6];
    const float* detW3     = (const float*)d_in[7];
    const float* detb3     = (const float*)d_in[8];
    const float* in_proj_w = (const float*)d_in[9];
    const float* in_proj_b = (const float*)d_in[10];
    const float* out_w     = (const float*)d_in[11];
    const float* out_b     = (const float*)d_in[12];
    const float* size_emb  = (const float*)d_in[13];
    const float* pos_enc   = (const float*)d_in[14];
    const float* procW1    = (const float*)d_in[15];
    const float* procb1    = (const float*)d_in[16];
    const float* procW2    = (const float*)d_in[17];
    const float* procb2    = (const float*)d_in[18];
    const float* ln_g      = (const float*)d_in[19];
    const float* ln_b      = (const float*)d_in[20];
    float* outp = (float*)d_out;

    cudaFuncSetAttribute(tgemm_k<0,0,0>, cudaFuncAttributeMaxDynamicSharedMemorySize, TG_SMEM);
    cudaFuncSetAttribute(tgemm_k<1,0,0>, cudaFuncAttributeMaxDynamicSharedMemorySize, TG_SMEM);
    cudaFuncSetAttribute(tgemm_k<1,1,0>, cudaFuncAttributeMaxDynamicSharedMemorySize, TG_SMEM);
    cudaFuncSetAttribute(tgemm_k<1,1,1>, cudaFuncAttributeMaxDynamicSharedMemorySize, TG_SMEM);

    void *p;
    cudaGetSymbolAddress(&p, g_xq);      float* xq      = (float*)p;
    cudaGetSymbolAddress(&p, g_bc);      float* bc      = (float*)p;
    cudaGetSymbolAddress(&p, g_h2);      float* h2      = (float*)p;
    cudaGetSymbolAddress(&p, g_attnout); float* attnout = (float*)p;
    cudaGetSymbolAddress(&p, g_y);       float* yb      = (float*)p;
    cudaGetSymbolAddress(&p, g_x2);      __half* x2     = (__half*)p;
    cudaGetSymbolAddress(&p, g_wc2);     __half* wc2    = (__half*)p;
    cudaGetSymbolAddress(&p, g_dW1_2);   __half* dW1_2  = (__half*)p;
    cudaGetSymbolAddress(&p, g_h1_2);    __half* h1_2   = (__half*)p;
    cudaGetSymbolAddress(&p, g_dW2_2);   __half* dW2_2  = (__half*)p;
    cudaGetSymbolAddress(&p, g_ctx2);    __half* ctx2   = (__half*)p;
    cudaGetSymbolAddress(&p, g_outw2);   __half* outw2  = (__half*)p;
    cudaGetSymbolAddress(&p, g_chunk2);  __half* chunk2 = (__half*)p;
    cudaGetSymbolAddress(&p, g_pw1_2);   __half* pw1_2  = (__half*)p;
    cudaGetSymbolAddress(&p, g_hproc2);  __half* hproc2 = (__half*)p;
    cudaGetSymbolAddress(&p, g_pw2_2);   __half* pw2_2  = (__half*)p;

    // ===== ONE fused split launch (bit-identical planes) =====
    fused_split_k<<<SP_BLOCKS, 256>>>(x, Wp, in_proj_w, detW1, detW2,
                                      out_w, procW1, procW2, bp, in_proj_b);

    // ===== merged xling|qkv GEMM: 3 products for n<1536 (boundary), 2 for qkv =====
    { GemmArgs a = { x2, wc2, bc, xq, nullptr, NB*SS, XQ, DD, 2*DD, 2*DD, XQ, 0,
                     OSINV, 3, 2, DD, 0,0,0,0,0,0,0, 1, 1 };
      tg_launch<0,0,0>(a); }

    // ===== boundary path (np=3 -> GEMMs bit-identical) =====
    norm_k<<<NB*SS/8, 256>>>();
    cos_k<<<dim3((CS_TOT + 7)/8, NB), 256>>>();
    base_k<<<(NB*SM1 + 255)/256, 256>>>();
    // h1 = gelu(bi @ detW1[n]^T + b) -> 2-way split directly; A gathered from x2 (BIG=1)
    { GemmArgs a = { x2, dW1_2, detb1, nullptr, h1_2, ROWS_DET, DD, 2*DD,
                     2*DD, 2*2*DD, 2*DD, DD, OSINV, NP3,
                     0, 0, (long long)DD*2*2*DD, 0,
                     (long long)ROWS_DET*2*DD, 0, DD, 3, 3 };
      tg_launch<1,1,1>(a); }
    // h2 = gelu(h1 @ detW2[n]^T + b) fp32
    { GemmArgs a = { h1_2, dW2_2, detb2, h2, nullptr, ROWS_DET, DD/2, DD,
                     2*DD, 2*DD, DD/2, 0, OSINV, NP3,
                     (long long)ROWS_DET*2*DD, 0, (long long)(DD/2)*2*DD, 0,
                     (long long)ROWS_DET*(DD/2), 0, DD/2, 3, 3 };
      tg_launch<1,0,0>(a); }
    learned_final_k<<<(ROWS_DET + 7)/8, 256>>>(detW3, detb3);
    seg_scan_k<<<NB, SS>>>();

    // ===== continuous path (np=2) =====
    seg_attn_k<<<NB*SS*NH/8, 256>>>();
    // attn_out = ctx @ out_w^T + out_b
    { GemmArgs a = { ctx2, outw2, out_b, attnout, nullptr, NB*SS, DD, DD,
                     2*DD, 2*DD, DD, 0, OSINV, NP2, 0,0,0,0,0,0,0, 1, 1 };
      tg_launch<0,0,0>(a); }
    chunk_k<<<dim3(MAXC, NB), 384>>>(size_emb, pos_enc);
    // hproc = gelu(chunk @ procW1^T + b) -> 2-way split directly
    { GemmArgs a = { chunk2, pw1_2, procb1, nullptr, hproc2, NB*MAXC, 2*DD, DD,
                     2*DD, 2*DD, 2*2*DD, 2*DD, OSINV, NP2, 0,0,0,0,0,0,0, 1, 1 };
      tg_launch<1,1,0>(a); }
    // y = hproc @ procW2^T + b
    { GemmArgs a = { hproc2, pw2_2, procb2, yb, nullptr, NB*MAXC, DD, 2*DD,
                     2*2*DD, 2*2*DD, DD, 0, OSINV, NP2, 0,0,0,0,0,0,0, 1, 1 };
      tg_launch<0,0,0>(a); }
    ln_k<<<NB*MAXC/8, 256>>>(ln_g, ln_b, outp);
}

// round 17
// speedup vs baseline: 1.2236x; 1.0084x over previous
#include <cuda_runtime.h>
#include <cuda_fp16.h>
#include <math.h>
#include <stdint.h>

// ---------------- problem constants ----------------
#define NB 4
#define SS 1024
#define DD 1536
#define NH 12
#define HDIM 128
#define MAXC 256
#define SM1 1023
#define ROWS_DET (NB*SM1)        // 4092
#define CS_TOT (1023+511+255)    // 1789
#define XQ 6144                  // combined xling|qkv row width
#define QOFF 1536                // qkv column offset in combined buffer

#define WSCALE 64.0f
#define OSINV  0.015625f         // 1/64

// ---------------- fp32 scratch ----------------
__device__ float g_xq[(size_t)NB*SS*XQ];       // [.,0:1536)=xling, [.,1536:6144)=qkv
__device__ float g_bc[XQ];                     // combined bias
__device__ float g_cs[NB*CS_TOT];
__device__ float g_h2[(size_t)3*ROWS_DET*(DD/2)];
__device__ float g_final[NB*SM1];
__device__ int   g_seg[NB*SS];
__device__ int   g_qlo[NB*SS];
__device__ int   g_qhi[NB*SS];
__device__ int   g_segstart[NB*MAXC];
__device__ int   g_segcount[NB*MAXC];
__device__ float g_attnout[(size_t)NB*SS*DD];
__device__ float g_y[(size_t)NB*MAXC*DD];

// ---------------- fp16 2-way split scratch [rows][2K] (hi|lo) ----------------
__device__ __half g_x2[(size_t)NB*SS*2*DD];
__device__ __half g_wc2[(size_t)XQ*2*DD];      // combined [Wp | in_proj_w] split
__device__ __half g_dW1_2[(size_t)3*DD*2*(2*DD)];
__device__ __half g_h1_2[(size_t)3*ROWS_DET*2*DD];
__device__ __half g_dW2_2[(size_t)3*(DD/2)*2*DD];
__device__ __half g_ctx2[(size_t)NB*SS*2*DD];
__device__ __half g_outw2[(size_t)DD*2*DD];
__device__ __half g_chunk2[(size_t)NB*MAXC*2*DD];
__device__ __half g_pw1_2[(size_t)2*DD*2*DD];
__device__ __half g_hproc2[(size_t)NB*MAXC*2*2*DD];
__device__ __half g_pw2_2[(size_t)DD*2*2*DD];

__device__ __forceinline__ float gelu_exact(float v) {
    return 0.5f * v * (1.0f + erff(v * 0.70710678118654752440f));
}
__device__ __forceinline__ uint32_t smem_u32(const void* p) {
    uint32_t a;
    asm("{ .reg .u64 t; cvta.to.shared.u64 t, %1; cvt.u32.u64 %0, t; }" : "=r"(a) : "l"(p));
    return a;
}
__device__ __forceinline__ float warp_sum(float v) {
    #pragma unroll
    for (int o = 16; o > 0; o >>= 1) v += __shfl_xor_sync(0xffffffffu, v, o);
    return v;
}

#define LDSM4(r0,r1,r2,r3,addr) \
    asm volatile("ldmatrix.sync.aligned.m8n8.x4.shared.b16 {%0,%1,%2,%3}, [%4];" \
        : "=r"(r0), "=r"(r1), "=r"(r2), "=r"(r3) : "r"(addr))

#define MMA16816(d, a, b0, b1) \
    asm volatile("mma.sync.aligned.m16n8k16.row.col.f32.f16.f16.f32 " \
        "{%0,%1,%2,%3},{%4,%5,%6,%7},{%8,%9},{%0,%1,%2,%3};" \
        : "+f"((d)[0]), "+f"((d)[1]), "+f"((d)[2]), "+f"((d)[3]) \
        : "r"((a)[0]), "r"((a)[1]), "r"((a)[2]), "r"((a)[3]), "r"(b0), "r"(b1))

#define CP_ASYNC16(dst, src, sz) \
    asm volatile("cp.async.ca.shared.global [%0], [%1], 16, %2;" :: "r"(dst), "l"(src), "r"(sz))
#define CP_COMMIT() asm volatile("cp.async.commit_group;" ::: "memory")
#define CP_WAIT1() asm volatile("cp.async.wait_group 1;" ::: "memory")
#define CP_WAIT0() asm volatile("cp.async.wait_group 0;" ::: "memory")

// ================= mma.sync fp16 split GEMM (2-stage, K64, 2 CTAs/SM) =================
// A[M][2K] (hi|lo), B[N][2K] (hi|lo).
// np = (n0 < splitN) ? npA : npB.
//   np=3: Ah.Bh + Ah.Bl + Al.Bh
//   np=2: Ah.Bh + Ah.Bl           (weights full precision, data fp16-truncated)
// BIG=1: A is g_x2; rows are bigrams (b,s); chunk selects x_s / x_{s+1}.
#define RSTRIDE 144
#define ATILE (128*RSTRIDE)        // 18432
#define BUFSZ (2*ATILE)            // 36864
#define TG_SMEM (2*BUFSZ)          // 73728

template<int ACT, int OMODE, int BIG>
__global__ void __launch_bounds__(256)
tgemm_k(const __half* __restrict__ A, const __half* __restrict__ B,
        const float* __restrict__ bias, float* __restrict__ C, __half* __restrict__ C2,
        int M, int K, int lda, int ldb, int ldc, int segoff, float oscale,
        int npA, int npB, int splitN,
        long long sAi, long long sAo, long long sBi, long long sBo,
        long long sCi, long long sCo, long long sbias, int innerN)
{
    const int segA_[3] = {0,0,1};
    const int segB_[3] = {0,1,0};
    extern __shared__ char smem[];
    uint32_t sb = smem_u32(smem);
    int tid = threadIdx.x;
    int z = blockIdx.z, zi = z % innerN, zo = z / innerN;
    if (!BIG) A += (size_t)(zi*sAi + zo*sAo);
    B += (size_t)(zi*sBi + zo*sBo);
    if (OMODE == 0) C  += (size_t)(zi*sCi + zo*sCo);
    else            C2 += (size_t)(zi*sCi + zo*sCo);
    int m0 = blockIdx.y * 128, n0 = blockIdx.x * 128;

    const int KPC = K >> 6;
    const int NP = (n0 < splitN) ? npA : npB;
    const int NC = NP * KPC;

    int arow_[4]; uint32_t asz_[4]; long long aoff_[4]; int ac_[4];
    #pragma unroll
    for (int i = 0; i < 4; i++) {
        int f = tid + (i << 8);
        int row = f >> 3, c = f & 7;
        int gr = m0 + row;
        int grc = gr < M ? gr : (M - 1);
        arow_[i] = row; ac_[i] = c;
        asz_[i] = gr < M ? 16u : 0u;
        if (BIG) {
            int b = grc / SM1, s = grc % SM1;
            aoff_[i] = (long long)(b*SS + s) * (2*DD);
        } else {
            aoff_[i] = (long long)grc * lda;
        }
    }

    auto issue = [&](int kc, int buf) {
        int p = kc / KPC;
        int k0 = (kc - p * KPC) << 6;
        uint32_t sA = sb + buf * BUFSZ;
        uint32_t sB = sA + ATILE;
        if (BIG) {
            int side = (k0 >= DD) ? 1 : 0;
            long long cofs = (long long)side*(2*DD) + segA_[p]*DD + (k0 - side*DD);
            #pragma unroll
            for (int i = 0; i < 4; i++) {
                const void* src = A + aoff_[i] + cofs + ac_[i] * 8;
                CP_ASYNC16(sA + arow_[i] * RSTRIDE + ac_[i] * 16, src, asz_[i]);
            }
        } else {
            const __half* Ap = A + (size_t)segA_[p] * K + k0;
            #pragma unroll
            for (int i = 0; i < 4; i++) {
                const void* src = Ap + aoff_[i] + ac_[i] * 8;
                CP_ASYNC16(sA + arow_[i] * RSTRIDE + ac_[i] * 16, src, asz_[i]);
            }
        }
        const __half* Bp = B + (size_t)segB_[p] * K + k0;
        #pragma unroll
        for (int i = 0; i < 4; i++) {
            int f = tid + (i << 8);
            int row = f >> 3, c = f & 7;
            const void* src = Bp + (size_t)(n0 + row) * ldb + c * 8;
            CP_ASYNC16(sB + row * RSTRIDE + c * 16, src, 16u);
        }
    };

    int lane = tid & 31, w = tid >> 5;
    int wm = w & 1, wn = w >> 1;
    uint32_t a_row = ((lane >> 3) & 1) * 8 + (lane & 7);
    uint32_t a_cs  = lane >> 4;
    uint32_t b_row = (lane >> 4) * 8 + (lane & 7);
    uint32_t b_cs  = (lane >> 3) & 1;

    float acc[4][4][4];
    #pragma unroll
    for (int i = 0; i < 4; i++)
        #pragma unroll
        for (int j = 0; j < 4; j++)
            #pragma unroll
            for (int r = 0; r < 4; r++) acc[i][j][r] = 0.f;

    issue(0, 0);
    CP_COMMIT();

    for (int kc = 0; kc < NC; kc++) {
        int cur = kc & 1;
        if (kc + 1 < NC) { issue(kc + 1, cur ^ 1); CP_COMMIT(); CP_WAIT1(); }
        else             { CP_WAIT0(); }
        __syncthreads();

        uint32_t sA = sb + cur * BUFSZ;
        uint32_t sB = sA + ATILE;
        #pragma unroll
        for (int ks = 0; ks < 4; ks++) {
            uint32_t av[4][4], bv[2][4];
            #pragma unroll
            for (int mt = 0; mt < 4; mt++) {
                uint32_t ad = sA + (wm*64 + mt*16 + a_row) * RSTRIDE + ((ks*2 + a_cs) << 4);
                LDSM4(av[mt][0], av[mt][1], av[mt][2], av[mt][3], ad);
            }
            #pragma unroll
            for (int bt = 0; bt < 2; bt++) {
                uint32_t bd = sB + (wn*32 + bt*16 + b_row) * RSTRIDE + ((ks*2 + b_cs) << 4);
                LDSM4(bv[bt][0], bv[bt][1], bv[bt][2], bv[bt][3], bd);
            }
            #pragma unroll
            for (int mt = 0; mt < 4; mt++)
                #pragma unroll
                for (int nt = 0; nt < 4; nt++) {
                    uint32_t b0 = bv[nt >> 1][(nt & 1) * 2];
                    uint32_t b1 = bv[nt >> 1][(nt & 1) * 2 + 1];
                    MMA16816(acc[mt][nt], av[mt], b0, b1);
                }
        }
        __syncthreads();
    }

    // ---- epilogue ----
    if (bias) bias += (size_t)z * (size_t)sbias;
    #pragma unroll
    for (int mt = 0; mt < 4; mt++) {
        int r0 = m0 + wm*64 + mt*16 + (lane >> 2);
        #pragma unroll
        for (int nt = 0; nt < 4; nt++) {
            int col = n0 + wn*32 + nt*8 + (lane & 3)*2;
            float bb0 = 0.f, bb1 = 0.f;
            if (bias) { bb0 = bias[col]; bb1 = bias[col+1]; }
            #pragma unroll
            for (int half_ = 0; half_ < 2; half_++) {
                int r = r0 + half_*8;
                if (r >= M) continue;
                float v0 = acc[mt][nt][half_*2]   * oscale + bb0;
                float v1 = acc[mt][nt][half_*2+1] * oscale + bb1;
                if (ACT == 1) { v0 = gelu_exact(v0); v1 = gelu_exact(v1); }
                if (OMODE == 0) {
                    *(float2*)(C + (size_t)r*ldc + col) = make_float2(v0, v1);
                } else {
                    __half* d = C2 + (size_t)r*ldc + col;
                    __half h0 = __float2half_rn(v0);
                    __half h1 = __float2half_rn(v1);
                    __half l0 = __float2half_rn(v0 - __half2float(h0));
                    __half l1 = __float2half_rn(v1 - __half2float(h1));
                    *(__half2*)(d)          = __halves2half2(h0, h1);
                    *(__half2*)(d + segoff) = __halves2half2(l0, l1);
                }
            }
        }
    }
}

// ============ fused split: all 9 input splits + biascat in ONE launch ============
__device__ __forceinline__ void split4_do(const float* __restrict__ src,
                                          __half* __restrict__ dst,
                                          long long l4, int C4, int C, float scale) {
    long long r = l4 / C4;
    int c = (int)(l4 - r * C4) * 4;
    float4 v = *(const float4*)(src + r * C + c);
    v.x *= scale; v.y *= scale; v.z *= scale; v.w *= scale;
    __half h0 = __float2half_rn(v.x), h1 = __float2half_rn(v.y);
    __half h2 = __float2half_rn(v.z), h3 = __float2half_rn(v.w);
    __half l0 = __float2half_rn(v.x - __half2float(h0));
    __half l1 = __float2half_rn(v.y - __half2float(h1));
    __half l2 = __float2half_rn(v.z - __half2float(h2));
    __half l3 = __float2half_rn(v.w - __half2float(h3));
    __half* d = dst + r * (2LL*C) + c;
    *(__half2*)(d)         = __halves2half2(h0, h1);
    *(__half2*)(d + 2)     = __halves2half2(h2, h3);
    *(__half2*)(d + C)     = __halves2half2(l0, l1);
    *(__half2*)(d + C + 2) = __halves2half2(l2, l3);
}

#define SP_X   1572864LL
#define SP_WP  (SP_X  + 589824LL)
#define SP_IPW (SP_WP + 1769472LL)
#define SP_DW1 (SP_IPW + 3538944LL)
#define SP_DW2 (SP_DW1 + 884736LL)
#define SP_OW  (SP_DW2 + 589824LL)
#define SP_PW1 (SP_OW  + 1179648LL)
#define SP_PW2 (SP_PW1 + 1179648LL)
#define SP_BC  (SP_PW2 + (XQ/4))
#define SP_BLOCKS ((unsigned)((SP_BC + 255) / 256))

__global__ void __launch_bounds__(256)
fused_split_k(const float* __restrict__ x,   const float* __restrict__ Wp,
              const float* __restrict__ ipw, const float* __restrict__ dW1,
              const float* __restrict__ dW2, const float* __restrict__ outw,
              const float* __restrict__ pw1, const float* __restrict__ pw2,
              const float* __restrict__ bp,  const float* __restrict__ ipb)
{
    long long i = (long long)blockIdx.x * 256 + threadIdx.x;
    if (i < SP_X) {
        split4_do(x, g_x2, i, DD/4, DD, 1.0f);
    } else if (i < SP_WP) {
        split4_do(Wp, g_wc2, i - SP_X, DD/4, DD, WSCALE);
    } else if (i < SP_IPW) {
        split4_do(ipw, g_wc2 + (size_t)DD*2*DD, i - SP_WP, DD/4, DD, WSCALE);
    } else if (i < SP_DW1) {
        split4_do(dW1, g_dW1_2, i - SP_IPW, (2*DD)/4, 2*DD, WSCALE);
    } else if (i < SP_DW2) {
        split4_do(dW2, g_dW2_2, i - SP_DW1, DD/4, DD, WSCALE);
    } else if (i < SP_OW) {
        split4_do(outw, g_outw2, i - SP_DW2, DD/4, DD, WSCALE);
    } else if (i < SP_PW1) {
        split4_do(pw1, g_pw1_2, i - SP_OW, DD/4, DD, WSCALE);
    } else if (i < SP_PW2) {
        split4_do(pw2, g_pw2_2, i - SP_PW1, (2*DD)/4, 2*DD, WSCALE);
    } else if (i < SP_BC) {
        int j = (int)(i - SP_PW2) * 4;
        #pragma unroll
        for (int u = 0; u < 4; u++) {
            int idx = j + u;
            g_bc[idx] = (idx < DD) ? bp[idx] : ipb[idx - DD];
        }
    }
}

// ---------------- fused norms+cosine: one warp per (b, t), norms inline ----------------
// Norm accumulation uses the same float4 traversal + warp_sum as the old norm_k
// -> bit-identical norm values; cs output unchanged to the last ulp.
__global__ void __launch_bounds__(256)
cos_k() {
    int w = threadIdx.x >> 5, lane = threadIdx.x & 31;
    int t = blockIdx.x * 8 + w;
    int b = blockIdx.y;
    if (t >= CS_TOT) return;
    int scale, i;
    if (t < 1023)      { scale = 1; i = t; }
    else if (t < 1534) { scale = 2; i = t - 1023; }
    else               { scale = 4; i = t - 1534; }
    int s0 = i * scale, s1 = s0 + scale;
    const float4* a = (const float4*)(g_xq + ((size_t)b*SS + s0) * XQ);
    const float4* c = (const float4*)(g_xq + ((size_t)b*SS + s1) * XQ);
    float d = 0.f, na = 0.f, nc = 0.f;
    #pragma unroll
    for (int j = 0; j < 12; j++) {
        float4 av = a[lane + j*32];
        float4 cv = c[lane + j*32];
        d  += av.x*cv.x + av.y*cv.y + av.z*cv.z + av.w*cv.w;
        na += av.x*av.x + av.y*av.y + av.z*av.z + av.w*av.w;
        nc += cv.x*cv.x + cv.y*cv.y + cv.z*cv.z + cv.w*cv.w;
    }
    d  = warp_sum(d);
    na = warp_sum(na);
    nc = warp_sum(nc);
    if (lane == 0) {
        float n0 = fmaxf(sqrtf(na), 1e-8f);
        float n1 = fmaxf(sqrtf(nc), 1e-8f);
        g_cs[b*CS_TOT + t] = d / (n0 * n1);
    }
}

// learned head + base interp + final boundary: one warp per row
__global__ void __launch_bounds__(256)
learned_final_k(const float* __restrict__ detW3,
                const float* __restrict__ detb3) {
    int w = threadIdx.x >> 5, lane = threadIdx.x & 31;
    int r = blockIdx.x * 8 + w;
    if (r >= ROWS_DET) return;
    float sacc = 0.f;
    #pragma unroll
    for (int n = 0; n < 3; n++) {
        const float4* h2p = (const float4*)(g_h2 + ((size_t)n*ROWS_DET + r) * (DD/2));
        const float4* wp  = (const float4*)(detW3 + n*(DD/2));
        float part = 0.f;
        #pragma unroll
        for (int j = 0; j < 6; j++) {
            float4 a = h2p[lane + j*32];
            float4 b = wp[lane + j*32];
            part += a.x*b.x + a.y*b.y + a.z*b.z + a.w*b.w;
        }
        part = warp_sum(part);
        float t = part + detb3[n];
        sacc += 1.0f / (1.0f + expf(-t));
    }
    if (lane == 0) {
        // inline base interpolation (identical arithmetic to old base_k)
        int b = r / SM1, j = r % SM1;
        const int Ls[3]   = {1023, 511, 255};
        const int offs[3] = {0, 1023, 1534};
        float acc = 0.f;
        #pragma unroll
        for (int u = 0; u < 3; u++) {
            int L = Ls[u];
            float ratio = (float)((double)L / 1023.0);
            float src = ((float)j + 0.5f) * ratio - 0.5f;
            src = fminf(fmaxf(src, 0.0f), (float)(L - 1));
            int i0 = (int)floorf(src);
            int i1 = min(i0 + 1, L - 1);
            float wq = src - (float)i0;
            const float* cs = g_cs + b*CS_TOT + offs[u];
            acc += cs[i0] * (1.0f - wq) + cs[i1] * wq;
        }
        float base = 0.5f * (1.0f - acc / 3.0f);
        g_final[r] = 0.6f * base + 0.4f * (sacc / 3.0f);
    }
}

// parallel segmentation: integer scans (exact, order-independent)
__global__ void __launch_bounds__(SS)
seg_scan_k() {
    int b = blockIdx.x, t = threadIdx.x;
    __shared__ int sscan[SS];
    __shared__ int smax[SS];
    __shared__ int rmin[SS];
    float bv = (t == 0) ? 1.0f : g_final[b*SM1 + t - 1];
    int f = (t == 0) ? 1 : (bv > 0.5f ? 1 : 0);
    sscan[t] = f;
    smax[t]  = f ? t : -1;
    rmin[t]  = f ? t : SS;
    __syncthreads();
    for (int o = 1; o < SS; o <<= 1) {
        int vs = sscan[t];
        int vm = smax[t];
        int vr = rmin[t];
        int vs2 = (t >= o) ? sscan[t - o] : 0;
        int vm2 = (t >= o) ? smax[t - o]  : -1;
        int vr2 = (t + o < SS) ? rmin[t + o] : SS;
        __syncthreads();
        sscan[t] = vs + vs2;
        smax[t]  = max(vm, vm2);
        rmin[t]  = min(vr, vr2);
        __syncthreads();
    }
    int m = sscan[t] - 1;
    g_seg[b*SS + t] = m;
    g_qlo[b*SS + t] = smax[t];
    int hi = (t < SS - 1) ? rmin[t + 1] : SS;
    g_qhi[b*SS + t] = hi;
    if (t < MAXC) { g_segstart[b*MAXC + t] = 0; g_segcount[b*MAXC + t] = 0; }
    __syncthreads();
    if (f && m < MAXC) {
        g_segstart[b*MAXC + m] = t;
        g_segcount[b*MAXC + m] = hi - t;
    }
}

// fused segment attention: one warp per (b, s, h); fp32; writes fp16-split ctx
__global__ void __launch_bounds__(256)
seg_attn_k() {
    __shared__ float dots[8][SS];
    int w = threadIdx.x >> 5, lane = threadIdx.x & 31;
    int g = blockIdx.x * 8 + w;
    int h = g % NH;
    int s = (g / NH) & (SS - 1);
    int b = g / (NH * SS);
    int lo = g_qlo[b*SS + s], hi = g_qhi[b*SS + s];

    const float* qp = g_xq + ((size_t)(b*SS + s))*XQ + QOFF + h*HDIM + lane*4;
    float4 qv = *(const float4*)qp;
    const float scale = 0.088388347648318440550f;   // 1/sqrt(128)

    const float* kbase = g_xq + ((size_t)(b*SS))*XQ + QOFF + DD + h*HDIM + lane*4;
    float mx = -3.402823e38f;
    for (int k = lo; k < hi; k++) {
        float4 kv = *(const float4*)(kbase + (size_t)k*XQ);
        float d = qv.x*kv.x + qv.y*kv.y + qv.z*kv.z + qv.w*kv.w;
        d = warp_sum(d);
        d *= scale;
        if (lane == 0) dots[w][k - lo] = d;
        mx = fmaxf(mx, d);
    }
    __syncwarp();

    const float* vbase = g_xq + ((size_t)(b*SS))*XQ + QOFF + 2*DD + h*HDIM + lane*4;
    float4 acc = make_float4(0.f, 0.f, 0.f, 0.f);
    float sum = 0.f;
    for (int k = lo; k < hi; k++) {
        float e = expf(dots[w][k - lo] - mx);
        sum += e;
        float4 vv = *(const float4*)(vbase + (size_t)k*XQ);
        acc.x += e*vv.x; acc.y += e*vv.y; acc.z += e*vv.z; acc.w += e*vv.w;
    }
    float inv = 1.0f / sum;
    float c0 = acc.x*inv, c1 = acc.y*inv, c2 = acc.z*inv, c3 = acc.w*inv;

    __half* d = g_ctx2 + ((size_t)(b*SS + s))*(2*DD) + h*HDIM + lane*4;
    __half h0 = __float2half_rn(c0), h1 = __float2half_rn(c1);
    __half h2 = __float2half_rn(c2), h3 = __float2half_rn(c3);
    *(__half2*)(d)     = __halves2half2(h0, h1);
    *(__half2*)(d + 2) = __halves2half2(h2, h3);
    __half l0 = __float2half_rn(c0 - __half2float(h0));
    __half l1 = __float2half_rn(c1 - __half2float(h1));
    __half l2 = __float2half_rn(c2 - __half2float(h2));
    __half l3 = __float2half_rn(c3 - __half2float(h3));
    *(__half2*)(d + DD)     = __halves2half2(l0, l1);
    *(__half2*)(d + DD + 2) = __halves2half2(l2, l3);
}

// pooling + embeddings, float4 path, writes 2-way fp16 split chunk (half2 stores)
__global__ void __launch_bounds__(384)
chunk_k(const float* __restrict__ size_emb,
        const float* __restrict__ pos_enc) {
    int m = blockIdx.x, b = blockIdx.y;
    int cnt = g_segcount[b*MAXC + m];
    int st  = g_segstart[b*MAXC + m];
    int d = threadIdx.x * 4;
    float4 v;
    if (cnt > 0) {
        float4 sum = make_float4(0.f, 0.f, 0.f, 0.f);
        for (int s = st; s < st + cnt; s++) {
            float4 a = *(const float4*)(g_attnout + ((size_t)b*SS + s)*DD + d);
            sum.x += a.x; sum.y += a.y; sum.z += a.z; sum.w += a.w;
        }
        int cl = min(cnt, 1023);
        float4 se = *(const float4*)(size_emb + (size_t)cl*DD + d);
        float ic = 1.0f / (float)cnt;
        v.x = sum.x*ic + se.x; v.y = sum.y*ic + se.y;
        v.z = sum.z*ic + se.z; v.w = sum.w*ic + se.w;
    } else v = make_float4(0.f, 0.f, 0.f, 0.f);
    float4 pe = *(const float4*)(pos_enc + (size_t)m*DD + d);
    v.x += pe.x; v.y += pe.y; v.z += pe.z; v.w += pe.w;
    __half h0 = __float2half_rn(v.x), h1 = __float2half_rn(v.y);
    __half h2 = __float2half_rn(v.z), h3 = __float2half_rn(v.w);
    __half l0 = __float2half_rn(v.x - __half2float(h0));
    __half l1 = __float2half_rn(v.y - __half2float(h1));
    __half l2 = __float2half_rn(v.z - __half2float(h2));
    __half l3 = __float2half_rn(v.w - __half2float(h3));
    __half* drow = g_chunk2 + ((size_t)b*MAXC + m) * (2*DD) + d;
    *(__half2*)(drow)          = __halves2half2(h0, h1);
    *(__half2*)(drow + 2)      = __halves2half2(h2, h3);
    *(__half2*)(drow + DD)     = __halves2half2(l0, l1);
    *(__half2*)(drow + DD + 2) = __halves2half2(l2, l3);
}

// final layernorm: one warp per row, float4
__global__ void __launch_bounds__(256)
ln_k(const float* __restrict__ gamma,
     const float* __restrict__ beta,
     float* __restrict__ out) {
    int w = threadIdx.x >> 5, lane = threadIdx.x & 31;
    int r = blockIdx.x * 8 + w;
    const float4* y = (const float4*)(g_y + (size_t)r*DD);
    float4 vv[12];
    float s = 0.f;
    #pragma unroll
    for (int j = 0; j < 12; j++) {
        vv[j] = y[lane + j*32];
        s += vv[j].x + vv[j].y + vv[j].z + vv[j].w;
    }
    s = warp_sum(s);
    float mu = s / (float)DD;
    float v2 = 0.f;
    #pragma unroll
    for (int j = 0; j < 12; j++) {
        float a = vv[j].x - mu, b = vv[j].y - mu, c = vv[j].z - mu, e = vv[j].w - mu;
        v2 += a*a + b*b + c*c + e*e;
    }
    v2 = warp_sum(v2);
    float inv = 1.0f / sqrtf(v2 / (float)DD + 1e-5f);
    const float4* gp = (const float4*)gamma;
    const float4* bp = (const float4*)beta;
    float4* op = (float4*)(out + (size_t)r*DD);
    #pragma unroll
    for (int j = 0; j < 12; j++) {
        float4 g4 = gp[lane + j*32];
        float4 b4 = bp[lane + j*32];
        float4 o4;
        o4.x = (vv[j].x - mu) * inv * g4.x + b4.x;
        o4.y = (vv[j].y - mu) * inv * g4.y + b4.y;
        o4.z = (vv[j].z - mu) * inv * g4.z + b4.z;
        o4.w = (vv[j].w - mu) * inv * g4.w + b4.w;
        op[lane + j*32] = o4;
    }
}

// ---------------- host launchers ----------------
struct GemmArgs {
    const __half *A, *B;
    const float* bias;
    float* C;
    __half* C2;
    int M, N, K, lda, ldb, ldc, segoff;
    float oscale;
    int npA, npB, splitN;
    long long sAi, sAo, sBi, sBo, sCi, sCo, sbias;
    int innerN, batch;
};

template<int ACT, int OMODE, int BIG>
static void tg_launch(const GemmArgs& a) {
    dim3 grid(a.N/128, (a.M + 127)/128, a.batch);
    tgemm_k<ACT,OMODE,BIG><<<grid,256,TG_SMEM>>>(a.A, a.B, a.bias, a.C, a.C2,
        a.M, a.K, a.lda, a.ldb, a.ldc, a.segoff, a.oscale,
        a.npA, a.npB, a.splitN,
        a.sAi, a.sAo, a.sBi, a.sBo, a.sCi, a.sCo, a.sbias, a.innerN);
}

#define NP3 3, 3, (1<<30)
#define NP2 2, 2, (1<<30)

extern "C" void kernel_launch(void* const* d_in, const int* in_sizes, int n_in,
                              void* d_out, int out_size) {
    const float* x         = (const float*)d_in[0];
    const float* Wp        = (const float*)d_in[1];
    const float* bp        = (const float*)d_in[2];
    const float* detW1     = (const float*)d_in[3];
    const float* detb1     = (const float*)d_in[4];
    const float* detW2     = (const float*)d_in[5];
    const float* detb2     = (const float*)d_in[6];
    const float* detW3     = (const float*)d_in[7];
    const float* detb3     = (const float*)d_in[8];
    const float* in_proj_w = (const float*)d_in[9];
    const float* in_proj_b = (const float*)d_in[10];
    const float* out_w     = (const float*)d_in[11];
    const float* out_b     = (const float*)d_in[12];
    const float* size_emb  = (const float*)d_in[13];
    const float* pos_enc   = (const float*)d_in[14];
    const float* procW1    = (const float*)d_in[15];
    const float* procb1    = (const float*)d_in[16];
    const float* procW2    = (const float*)d_in[17];
    const float* procb2    = (const float*)d_in[18];
    const float* ln_g      = (const float*)d_in[19];
    const float* ln_b      = (const float*)d_in[20];
    float* outp = (float*)d_out;

    cudaFuncSetAttribute(tgemm_k<0,0,0>, cudaFuncAttributeMaxDynamicSharedMemorySize, TG_SMEM);
    cudaFuncSetAttribute(tgemm_k<1,0,0>, cudaFuncAttributeMaxDynamicSharedMemorySize, TG_SMEM);
    cudaFuncSetAttribute(tgemm_k<1,1,0>, cudaFuncAttributeMaxDynamicSharedMemorySize, TG_SMEM);
    cudaFuncSetAttribute(tgemm_k<1,1,1>, cudaFuncAttributeMaxDynamicSharedMemorySize, TG_SMEM);

    void *p;
    cudaGetSymbolAddress(&p, g_xq);      float* xq      = (float*)p;
    cudaGetSymbolAddress(&p, g_bc);      float* bc      = (float*)p;
    cudaGetSymbolAddress(&p, g_h2);      float* h2      = (float*)p;
    cudaGetSymbolAddress(&p, g_attnout); float* attnout = (float*)p;
    cudaGetSymbolAddress(&p, g_y);       float* yb      = (float*)p;
    cudaGetSymbolAddress(&p, g_x2);      __half* x2     = (__half*)p;
    cudaGetSymbolAddress(&p, g_wc2);     __half* wc2    = (__half*)p;
    cudaGetSymbolAddress(&p, g_dW1_2);   __half* dW1_2  = (__half*)p;
    cudaGetSymbolAddress(&p, g_h1_2);    __half* h1_2   = (__half*)p;
    cudaGetSymbolAddress(&p, g_dW2_2);   __half* dW2_2  = (__half*)p;
    cudaGetSymbolAddress(&p, g_ctx2);    __half* ctx2   = (__half*)p;
    cudaGetSymbolAddress(&p, g_outw2);   __half* outw2  = (__half*)p;
    cudaGetSymbolAddress(&p, g_chunk2);  __half* chunk2 = (__half*)p;
    cudaGetSymbolAddress(&p, g_pw1_2);   __half* pw1_2  = (__half*)p;
    cudaGetSymbolAddress(&p, g_hproc2);  __half* hproc2 = (__half*)p;
    cudaGetSymbolAddress(&p, g_pw2_2);   __half* pw2_2  = (__half*)p;

    // ===== ONE fused split launch (bit-identical planes) =====
    fused_split_k<<<SP_BLOCKS, 256>>>(x, Wp, in_proj_w, detW1, detW2,
                                      out_w, procW1, procW2, bp, in_proj_b);

    // ===== merged xling|qkv GEMM: 3 products for n<1536 (boundary), 2 for qkv =====
    { GemmArgs a = { x2, wc2, bc, xq, nullptr, NB*SS, XQ, DD, 2*DD, 2*DD, XQ, 0,
                     OSINV, 3, 2, DD, 0,0,0,0,0,0,0, 1, 1 };
      tg_launch<0,0,0>(a); }

    // ===== boundary path (np=3 -> GEMMs bit-identical; norms fused into cos) =====
    cos_k<<<dim3((CS_TOT + 7)/8, NB), 256>>>();
    // h1 = gelu(bi @ detW1[n]^T + b) -> 2-way split directly; A gathered from x2 (BIG=1)
    { GemmArgs a = { x2, dW1_2, detb1, nullptr, h1_2, ROWS_DET, DD, 2*DD,
                     2*DD, 2*2*DD, 2*DD, DD, OSINV, NP3,
                     0, 0, (long long)DD*2*2*DD, 0,
                     (long long)ROWS_DET*2*DD, 0, DD, 3, 3 };
      tg_launch<1,1,1>(a); }
    // h2 = gelu(h1 @ detW2[n]^T + b) fp32
    { GemmArgs a = { h1_2, dW2_2, detb2, h2, nullptr, ROWS_DET, DD/2, DD,
                     2*DD, 2*DD, DD/2, 0, OSINV, NP3,
                     (long long)ROWS_DET*2*DD, 0, (long long)(DD/2)*2*DD, 0,
                     (long long)ROWS_DET*(DD/2), 0, DD/2, 3, 3 };
      tg_launch<1,0,0>(a); }
    learned_final_k<<<(ROWS_DET + 7)/8, 256>>>(detW3, detb3);
    seg_scan_k<<<NB, SS>>>();

    // ===== continuous path (np=2) =====
    seg_attn_k<<<NB*SS*NH/8, 256>>>();
    // attn_out = ctx @ out_w^T + out_b
    { GemmArgs a = { ctx2, outw2, out_b, attnout, nullptr, NB*SS, DD, DD,
                     2*DD, 2*DD, DD, 0, OSINV, NP2, 0,0,0,0,0,0,0, 1, 1 };
      tg_launch<0,0,0>(a); }
    chunk_k<<<dim3(MAXC, NB), 384>>>(size_emb, pos_enc);
    // hproc = gelu(chunk @ procW1^T + b) -> 2-way split directly
    { GemmArgs a = { chunk2, pw1_2, procb1, nullptr, hproc2, NB*MAXC, 2*DD, DD,
                     2*DD, 2*DD, 2*2*DD, 2*DD, OSINV, NP2, 0,0,0,0,0,0,0, 1, 1 };
      tg_launch<1,1,0>(a); }
    // y = hproc @ procW2^T + b
    { GemmArgs a = { hproc2, pw2_2, procb2, yb, nullptr, NB*MAXC, DD, 2*DD,
                     2*2*DD, 2*2*DD, DD, 0, OSINV, NP2, 0,0,0,0,0,0,0, 1, 1 };
      tg_launch<0,0,0>(a); }
    ln_k<<<NB*MAXC/8, 256>>>(ln_g, ln_b, outp);
}